// round 1
// baseline (speedup 1.0000x reference)
#include <cuda_runtime.h>

#define BATCH   32
#define CHUNK   480000
#define NFFT    400
#define HOP     160
#define NMELS   128
#define NFREQ   201
#define NFRAMES 3000
#define PADW    200
#define FP      208            // padded freq dim for transposed tables
#define TF      64             // frames per block
#define SLAB    ((TF - 1) * HOP + NFFT)   // 10480 floats
#define SLAB_SK (SLAB + ((SLAB >> 8) << 1) + 8)

// ---------------- device scratch (static, no runtime allocation) ----------------
__device__ float    g_power[(size_t)BATCH * NFREQ * NFRAMES];   // 77 MB
__device__ float    g_cosT[(NFFT / 2) * FP * 2];                // [(n>>1)][f][2]
__device__ float    g_sinT[(NFFT / 2) * FP * 2];
__device__ unsigned g_max[BATCH];
__device__ int      g_lo[NMELS];
__device__ int      g_hi[NMELS];

// ordered-uint encoding so atomicMax works on floats (incl. negatives)
__device__ __forceinline__ unsigned f2ord(float f) {
    unsigned u = __float_as_uint(f);
    return (u & 0x80000000u) ? ~u : (u | 0x80000000u);
}
__device__ __forceinline__ float ord2f(unsigned u) {
    return __uint_as_float((u & 0x80000000u) ? (u & 0x7fffffffu) : ~u);
}

// ---------------- prep: transpose DFT tables, mel ranges, init maxes ------------
__global__ void prep_kernel(const float* __restrict__ cosk,
                            const float* __restrict__ sink,
                            const float* __restrict__ fb) {
    int idx = blockIdx.x * blockDim.x + threadIdx.x;
    int stride = gridDim.x * blockDim.x;
    const int total = NFFT * FP;
    for (int i = idx; i < total; i += stride) {
        int n = i / FP;
        int f = i - n * FP;
        float cv = (f < NFREQ) ? cosk[f * NFFT + n] : 0.0f;
        float sv = (f < NFREQ) ? sink[f * NFFT + n] : 0.0f;
        int o = ((n >> 1) * FP + f) * 2 + (n & 1);
        g_cosT[o] = cv;
        g_sinT[o] = sv;
    }
    if (idx < NMELS) {
        int lo = NFREQ, hi = 0;
        for (int f = 0; f < NFREQ; ++f) {
            if (fb[idx * NFREQ + f] != 0.0f) {
                if (f < lo) lo = f;
                hi = f + 1;
            }
        }
        if (lo >= hi) { lo = 0; hi = 0; }
        g_lo[idx] = lo;
        g_hi[idx] = hi;
    }
    if (idx < BATCH) g_max[idx] = f2ord(-3.0e38f);
}

// ---------------- STFT power ----------------------------------------------------
// Block: 128 threads = 16 freq-slots x 8 frame-groups. Thread tile: NA freqs x 8 frames.
template <int NA>
__device__ __forceinline__ void stft_round(const float* __restrict__ slab,
                                           int fbase_v, int lt0, int b, int t0,
                                           bool valid_t) {
    float ar[NA][8], ai[NA][8];
#pragma unroll
    for (int a = 0; a < NA; ++a)
#pragma unroll
        for (int j = 0; j < 8; ++j) { ar[a][j] = 0.0f; ai[a][j] = 0.0f; }

    const float2* cp = reinterpret_cast<const float2*>(g_cosT) + fbase_v;
    const float2* sp = reinterpret_cast<const float2*>(g_sinT) + fbase_v;

#pragma unroll 2
    for (int n2 = 0; n2 < NFFT / 2; ++n2) {
        float2 c[NA], s[NA];
#pragma unroll
        for (int a = 0; a < NA; ++a) {
            c[a] = cp[16 * a];
            s[a] = sp[16 * a];
        }
        cp += FP;
        sp += FP;
#pragma unroll
        for (int j = 0; j < 8; ++j) {
            int i = (lt0 + j) * HOP + 2 * n2;
            float2 xv = *reinterpret_cast<const float2*>(&slab[i + ((i >> 8) << 1)]);
#pragma unroll
            for (int a = 0; a < NA; ++a) {
                ar[a][j] = fmaf(c[a].x, xv.x, ar[a][j]);
                ar[a][j] = fmaf(c[a].y, xv.y, ar[a][j]);
                ai[a][j] = fmaf(s[a].x, xv.x, ai[a][j]);
                ai[a][j] = fmaf(s[a].y, xv.y, ai[a][j]);
            }
        }
    }

    if (valid_t) {
#pragma unroll
        for (int a = 0; a < NA; ++a) {
            int f = fbase_v + 16 * a;
            if (f < NFREQ) {
                float p[8];
#pragma unroll
                for (int j = 0; j < 8; ++j)
                    p[j] = ar[a][j] * ar[a][j] + ai[a][j] * ai[a][j];
                float* dst = g_power + ((size_t)b * NFREQ + f) * NFRAMES + t0;
                *reinterpret_cast<float4*>(dst)     = make_float4(p[0], p[1], p[2], p[3]);
                *reinterpret_cast<float4*>(dst + 4) = make_float4(p[4], p[5], p[6], p[7]);
            }
        }
    }
}

__global__ void __launch_bounds__(128) stft_kernel(const float* __restrict__ audio) {
    __shared__ __align__(16) float slab[SLAB_SK];
    const int b = blockIdx.y;
    const int tile0 = blockIdx.x * TF;
    const long base = (long)tile0 * HOP;      // padded coordinates
    const float* aud = audio + (size_t)b * CHUNK;

    for (int i = threadIdx.x; i < SLAB; i += 128) {
        long src = base + i - PADW;
        if (src < 0) src = -src;                          // reflect (no edge repeat)
        if (src >= CHUNK) src = 2L * CHUNK - 2 - src;
        slab[i + ((i >> 8) << 1)] = aud[src];
    }
    __syncthreads();

    const int fslot = threadIdx.x & 15;
    const int tg = threadIdx.x >> 4;          // 0..7
    const int lt0 = tg * 8;
    const int t0 = tile0 + lt0;
    const bool valid_t = (t0 < NFRAMES);

    // rounds: freqs [0,64), [64,128), [128,192) with NA=4; [192,208) with NA=1
    stft_round<4>(slab, 0 + fslot, lt0, b, t0, valid_t);
    stft_round<4>(slab, 64 + fslot, lt0, b, t0, valid_t);
    stft_round<4>(slab, 128 + fslot, lt0, b, t0, valid_t);
    stft_round<1>(slab, 192 + fslot, lt0, b, t0, valid_t);
}

// ---------------- mel + log10 + per-batch max -----------------------------------
__global__ void __launch_bounds__(256) mel_kernel(const float* __restrict__ fb,
                                                  float* __restrict__ out) {
    const int b = blockIdx.y;
    const int t = blockIdx.x * blockDim.x + threadIdx.x;
    float localmax = -3.0e38f;
    if (t < NFRAMES) {
        const float* pw = g_power + (size_t)b * NFREQ * NFRAMES + t;
        float* op = out + (size_t)b * NMELS * NFRAMES + t;
        for (int m = 0; m < NMELS; ++m) {
            const int lo = g_lo[m];
            const int hi = g_hi[m];
            float acc = 0.0f;
            for (int f = lo; f < hi; ++f)
                acc = fmaf(fb[m * NFREQ + f], pw[(size_t)f * NFRAMES], acc);
            float lm = log10f(fmaxf(acc, 1e-10f));
            op[(size_t)m * NFRAMES] = lm;
            localmax = fmaxf(localmax, lm);
        }
    }
#pragma unroll
    for (int o = 16; o; o >>= 1)
        localmax = fmaxf(localmax, __shfl_xor_sync(0xffffffffu, localmax, o));
    if ((threadIdx.x & 31) == 0) atomicMax(&g_max[b], f2ord(localmax));
}

// ---------------- finalize: floor at max-8, normalize ---------------------------
__global__ void __launch_bounds__(256) fin_kernel(float* __restrict__ out) {
    const int b = blockIdx.y;
    const float floorv = ord2f(g_max[b]) - 8.0f;
    const size_t idx = (size_t)blockIdx.x * blockDim.x + threadIdx.x;  // float4 units
    const size_t per = (size_t)NMELS * NFRAMES / 4;                    // 96000
    if (idx < per) {
        float4* p = reinterpret_cast<float4*>(out + (size_t)b * NMELS * NFRAMES) + idx;
        float4 v = *p;
        v.x = (fmaxf(v.x, floorv) + 4.0f) * 0.25f;
        v.y = (fmaxf(v.y, floorv) + 4.0f) * 0.25f;
        v.z = (fmaxf(v.z, floorv) + 4.0f) * 0.25f;
        v.w = (fmaxf(v.w, floorv) + 4.0f) * 0.25f;
        *p = v;
    }
}

// ---------------- launch --------------------------------------------------------
extern "C" void kernel_launch(void* const* d_in, const int* in_sizes, int n_in,
                              void* d_out, int out_size) {
    const float* audio = (const float*)d_in[0];
    const float* cosk  = (const float*)d_in[1];
    const float* sink  = (const float*)d_in[2];
    const float* fb    = (const float*)d_in[3];
    float* out = (float*)d_out;

    prep_kernel<<<128, 256>>>(cosk, sink, fb);

    dim3 gs((NFRAMES + TF - 1) / TF, BATCH);      // (47, 32)
    stft_kernel<<<gs, 128>>>(audio);

    dim3 gm((NFRAMES + 255) / 256, BATCH);        // (12, 32)
    mel_kernel<<<gm, 256>>>(fb, out);

    dim3 gf((NMELS * NFRAMES / 4 + 255) / 256, BATCH);  // (375, 32)
    fin_kernel<<<gf, 256>>>(out);
}

// round 2
// speedup vs baseline: 1.2295x; 1.2295x over previous
#include <cuda_runtime.h>

#define BATCH   32
#define CHUNK   480000
#define NFFT    400
#define HOP     160
#define NMELS   128
#define NFREQ   201
#define NFRAMES 3000
#define PADW    200
#define FP      208            // padded freq dim for packed table
#define TF      64             // frames per block
#define SLAB    ((TF - 1) * HOP + NFFT)   // 10480 floats
#define SLAB_SK (SLAB + ((SLAB >> 8) << 1) + 8)

// ---------------- device scratch (static, no runtime allocation) ----------------
__device__ float    g_power[(size_t)BATCH * NFREQ * NFRAMES];   // 77 MB
// packed table: [n2][f] -> float4 (cos[2n2][f], sin[2n2][f], cos[2n2+1][f], sin[2n2+1][f])
__device__ float4   g_tab[(NFFT / 2) * FP];
__device__ unsigned g_max[BATCH];
__device__ int      g_lo[NMELS];
__device__ int      g_hi[NMELS];

// packed f32x2 helpers (sm_100a FFMA2 — only reachable via PTX)
#define FMA2(d, a, b) \
    asm("fma.rn.f32x2 %0, %1, %2, %0;" : "+l"(d) : "l"(a), "l"(b))
#define PACK_DUP(d, f) \
    asm("mov.b64 %0, {%1, %1};" : "=l"(d) : "f"(f))
#define UNPACK2(lo, hi, d) \
    asm("mov.b64 {%0, %1}, %2;" : "=f"(lo), "=f"(hi) : "l"(d))

// ordered-uint encoding so atomicMax works on floats (incl. negatives)
__device__ __forceinline__ unsigned f2ord(float f) {
    unsigned u = __float_as_uint(f);
    return (u & 0x80000000u) ? ~u : (u | 0x80000000u);
}
__device__ __forceinline__ float ord2f(unsigned u) {
    return __uint_as_float((u & 0x80000000u) ? (u & 0x7fffffffu) : ~u);
}

// ---------------- prep: pack DFT tables, mel ranges, init maxes -----------------
__global__ void prep_kernel(const float* __restrict__ cosk,
                            const float* __restrict__ sink,
                            const float* __restrict__ fb) {
    int idx = blockIdx.x * blockDim.x + threadIdx.x;
    int stride = gridDim.x * blockDim.x;
    const int total = (NFFT / 2) * FP;
    for (int i = idx; i < total; i += stride) {
        int n2 = i / FP;
        int f = i - n2 * FP;
        float4 v = make_float4(0.f, 0.f, 0.f, 0.f);
        if (f < NFREQ) {
            v.x = cosk[f * NFFT + 2 * n2];
            v.y = sink[f * NFFT + 2 * n2];
            v.z = cosk[f * NFFT + 2 * n2 + 1];
            v.w = sink[f * NFFT + 2 * n2 + 1];
        }
        g_tab[i] = v;
    }
    if (idx < NMELS) {
        int lo = NFREQ, hi = 0;
        for (int f = 0; f < NFREQ; ++f) {
            if (fb[idx * NFREQ + f] != 0.0f) {
                if (f < lo) lo = f;
                hi = f + 1;
            }
        }
        if (lo >= hi) { lo = 0; hi = 0; }
        g_lo[idx] = lo;
        g_hi[idx] = hi;
    }
    if (idx < BATCH) g_max[idx] = f2ord(-3.0e38f);
}

// ---------------- STFT power ----------------------------------------------------
// Block: 128 threads = 16 freq-slots x 8 frame-groups. Thread tile: NA freqs x 8 frames.
// Accumulators are packed (real, imag) f32x2 pairs -> one FFMA2 per sample per (f,t).
template <int NA>
__device__ __forceinline__ void stft_round(const float* __restrict__ slab,
                                           int fbase_v, int lt0, int b, int t0,
                                           bool valid_t) {
    unsigned long long acc[NA][8];
#pragma unroll
    for (int a = 0; a < NA; ++a)
#pragma unroll
        for (int j = 0; j < 8; ++j) acc[a][j] = 0ull;   // bits of (0.0f, 0.0f)

    const float4* tp = g_tab + fbase_v;

#pragma unroll 2
    for (int n2 = 0; n2 < NFFT / 2; ++n2) {
        union { float4 v; unsigned long long u[2]; } cs[NA];
#pragma unroll
        for (int a = 0; a < NA; ++a) cs[a].v = tp[16 * a];
        tp += FP;
#pragma unroll
        for (int j = 0; j < 8; ++j) {
            int i = (lt0 + j) * HOP + 2 * n2;
            float2 xv = *reinterpret_cast<const float2*>(&slab[i + ((i >> 8) << 1)]);
            unsigned long long x0, x1;
            PACK_DUP(x0, xv.x);
            PACK_DUP(x1, xv.y);
#pragma unroll
            for (int a = 0; a < NA; ++a) {
                FMA2(acc[a][j], cs[a].u[0], x0);
                FMA2(acc[a][j], cs[a].u[1], x1);
            }
        }
    }

    if (valid_t) {
#pragma unroll
        for (int a = 0; a < NA; ++a) {
            int f = fbase_v + 16 * a;
            if (f < NFREQ) {
                float p[8];
#pragma unroll
                for (int j = 0; j < 8; ++j) {
                    float re, im;
                    UNPACK2(re, im, acc[a][j]);
                    p[j] = re * re + im * im;
                }
                float* dst = g_power + ((size_t)b * NFREQ + f) * NFRAMES + t0;
                *reinterpret_cast<float4*>(dst)     = make_float4(p[0], p[1], p[2], p[3]);
                *reinterpret_cast<float4*>(dst + 4) = make_float4(p[4], p[5], p[6], p[7]);
            }
        }
    }
}

__global__ void __launch_bounds__(128, 4) stft_kernel(const float* __restrict__ audio) {
    __shared__ __align__(16) float slab[SLAB_SK];
    const int b = blockIdx.y;
    const int tile0 = blockIdx.x * TF;
    const long base = (long)tile0 * HOP;      // padded coordinates
    const float* aud = audio + (size_t)b * CHUNK;

    for (int i = threadIdx.x; i < SLAB; i += 128) {
        long src = base + i - PADW;
        if (src < 0) src = -src;                          // reflect (no edge repeat)
        if (src >= CHUNK) src = 2L * CHUNK - 2 - src;
        slab[i + ((i >> 8) << 1)] = aud[src];
    }
    __syncthreads();

    const int fslot = threadIdx.x & 15;
    const int tg = threadIdx.x >> 4;          // 0..7
    const int lt0 = tg * 8;
    const int t0 = tile0 + lt0;
    const bool valid_t = (t0 < NFRAMES);

    // rounds: freqs [0,64), [64,128), [128,192) with NA=4; [192,208) with NA=1
    stft_round<4>(slab, 0 + fslot, lt0, b, t0, valid_t);
    stft_round<4>(slab, 64 + fslot, lt0, b, t0, valid_t);
    stft_round<4>(slab, 128 + fslot, lt0, b, t0, valid_t);
    stft_round<1>(slab, 192 + fslot, lt0, b, t0, valid_t);
}

// ---------------- mel + log10 + per-batch max -----------------------------------
__global__ void __launch_bounds__(256) mel_kernel(const float* __restrict__ fb,
                                                  float* __restrict__ out) {
    const int b = blockIdx.y;
    const int t = blockIdx.x * blockDim.x + threadIdx.x;
    float localmax = -3.0e38f;
    if (t < NFRAMES) {
        const float* pw = g_power + (size_t)b * NFREQ * NFRAMES + t;
        float* op = out + (size_t)b * NMELS * NFRAMES + t;
        for (int m = 0; m < NMELS; ++m) {
            const int lo = g_lo[m];
            const int hi = g_hi[m];
            float acc = 0.0f;
            for (int f = lo; f < hi; ++f)
                acc = fmaf(fb[m * NFREQ + f], pw[(size_t)f * NFRAMES], acc);
            float lm = log10f(fmaxf(acc, 1e-10f));
            op[(size_t)m * NFRAMES] = lm;
            localmax = fmaxf(localmax, lm);
        }
    }
#pragma unroll
    for (int o = 16; o; o >>= 1)
        localmax = fmaxf(localmax, __shfl_xor_sync(0xffffffffu, localmax, o));
    if ((threadIdx.x & 31) == 0) atomicMax(&g_max[b], f2ord(localmax));
}

// ---------------- finalize: floor at max-8, normalize ---------------------------
__global__ void __launch_bounds__(256) fin_kernel(float* __restrict__ out) {
    const int b = blockIdx.y;
    const float floorv = ord2f(g_max[b]) - 8.0f;
    const size_t idx = (size_t)blockIdx.x * blockDim.x + threadIdx.x;  // float4 units
    const size_t per = (size_t)NMELS * NFRAMES / 4;                    // 96000
    if (idx < per) {
        float4* p = reinterpret_cast<float4*>(out + (size_t)b * NMELS * NFRAMES) + idx;
        float4 v = *p;
        v.x = (fmaxf(v.x, floorv) + 4.0f) * 0.25f;
        v.y = (fmaxf(v.y, floorv) + 4.0f) * 0.25f;
        v.z = (fmaxf(v.z, floorv) + 4.0f) * 0.25f;
        v.w = (fmaxf(v.w, floorv) + 4.0f) * 0.25f;
        *p = v;
    }
}

// ---------------- launch --------------------------------------------------------
extern "C" void kernel_launch(void* const* d_in, const int* in_sizes, int n_in,
                              void* d_out, int out_size) {
    const float* audio = (const float*)d_in[0];
    const float* cosk  = (const float*)d_in[1];
    const float* sink  = (const float*)d_in[2];
    const float* fb    = (const float*)d_in[3];
    float* out = (float*)d_out;

    prep_kernel<<<128, 256>>>(cosk, sink, fb);

    dim3 gs((NFRAMES + TF - 1) / TF, BATCH);      // (47, 32)
    stft_kernel<<<gs, 128>>>(audio);

    dim3 gm((NFRAMES + 255) / 256, BATCH);        // (12, 32)
    mel_kernel<<<gm, 256>>>(fb, out);

    dim3 gf((NMELS * NFRAMES / 4 + 255) / 256, BATCH);  // (375, 32)
    fin_kernel<<<gf, 256>>>(out);
}

// round 4
// speedup vs baseline: 1.8146x; 1.4759x over previous
#include <cuda_runtime.h>
#include <cuda_bf16.h>
#include <cstdint>

#define BATCH   32
#define CHUNK   480000
#define NFFT    400
#define HOP     160
#define NMELS   128
#define NFREQ   201
#define NFRAMES 3000
#define NFRTOT  (BATCH * NFRAMES)   // 96000
#define MROWS   402                 // 201 freqs x (cos,sin)
#define MPAD    512                 // 4 tiles of 128
#define KPAD    448                 // 14 chunks of 32
#define KC      32
#define NCHUNK  (KPAD / KC)         // 14
#define NT      128                 // frames per block
#define NNT     (NFRTOT / NT)       // 750
#define ASTRIDE 80                  // smem row stride in bytes (32 bf16 + pad)

// ---------------- device scratch ------------------------------------------------
__device__ float g_power[(size_t)NFREQ * NFRTOT];                 // [f][global frame], 77 MB
__device__ __align__(16) __nv_bfloat16 g_ah[MPAD * KPAD];         // A hi  [512][448]
__device__ __align__(16) __nv_bfloat16 g_al[MPAD * KPAD];         // A lo
__device__ unsigned g_max[BATCH];
__device__ int      g_lo[NMELS];
__device__ int      g_hi[NMELS];

// ---------------- helpers -------------------------------------------------------
__device__ __forceinline__ uint32_t smem_u32(const void* p) {
    uint32_t a;
    asm("{ .reg .u64 t; cvta.to.shared.u64 t, %1; cvt.u32.u64 %0, t; }" : "=r"(a) : "l"(p));
    return a;
}
__device__ __forceinline__ void ldsm_x4(uint32_t& r0, uint32_t& r1, uint32_t& r2, uint32_t& r3,
                                        uint32_t addr) {
    asm volatile("ldmatrix.sync.aligned.m8n8.x4.shared.b16 {%0,%1,%2,%3}, [%4];"
                 : "=r"(r0), "=r"(r1), "=r"(r2), "=r"(r3) : "r"(addr));
}
__device__ __forceinline__ void mma16816(float* d, const uint32_t* a, uint32_t b0, uint32_t b1) {
    asm volatile("mma.sync.aligned.m16n8k16.row.col.f32.bf16.bf16.f32 "
                 "{%0,%1,%2,%3}, {%4,%5,%6,%7}, {%8,%9}, {%0,%1,%2,%3};"
                 : "+f"(d[0]), "+f"(d[1]), "+f"(d[2]), "+f"(d[3])
                 : "r"(a[0]), "r"(a[1]), "r"(a[2]), "r"(a[3]), "r"(b0), "r"(b1));
}
__device__ __forceinline__ unsigned f2ord(float f) {
    unsigned u = __float_as_uint(f);
    return (u & 0x80000000u) ? ~u : (u | 0x80000000u);
}
__device__ __forceinline__ float ord2f(unsigned u) {
    return __uint_as_float((u & 0x80000000u) ? (u & 0x7fffffffu) : ~u);
}
__device__ __forceinline__ void split_bf16(float v, unsigned short& h, unsigned short& l) {
    __nv_bfloat16 hb = __float2bfloat16_rn(v);
    __nv_bfloat16 lb = __float2bfloat16_rn(v - __bfloat162float(hb));
    h = __bfloat16_as_ushort(hb);
    l = __bfloat16_as_ushort(lb);
}

// ---------------- prep: A hi/lo tables, mel ranges, maxes -----------------------
__global__ void prep_kernel(const float* __restrict__ cosk,
                            const float* __restrict__ sink,
                            const float* __restrict__ fb) {
    int idx = blockIdx.x * blockDim.x + threadIdx.x;
    const int total = MPAD * KPAD;
    for (int e = idx; e < total; e += gridDim.x * blockDim.x) {
        int R = e / KPAD;
        int K = e - R * KPAD;
        float v = 0.0f;
        if (R < MROWS && K < NFFT) {
            int f = R >> 1;
            v = (R & 1) ? sink[f * NFFT + K] : cosk[f * NFFT + K];
        }
        unsigned short h, l;
        split_bf16(v, h, l);
        g_ah[e] = __ushort_as_bfloat16(h);
        g_al[e] = __ushort_as_bfloat16(l);
    }
    if (idx < NMELS) {
        int lo = NFREQ, hi = 0;
        for (int f = 0; f < NFREQ; ++f) {
            if (fb[idx * NFREQ + f] != 0.0f) { if (f < lo) lo = f; hi = f + 1; }
        }
        if (lo >= hi) { lo = 0; hi = 0; }
        g_lo[idx] = lo;
        g_hi[idx] = hi;
    }
    if (idx < BATCH) g_max[idx] = f2ord(-3.0e38f);
}

// ---------------- STFT power via mma.sync bf16 hi/lo ----------------------------
// grid (750, 4): x = frame tile (128 frames), y = M tile (128 rows).
// 256 threads = 8 warps, warp grid 2m x 4n, warp tile 64M x 32N.
__global__ void __launch_bounds__(256, 2) stft_mma_kernel(const float* __restrict__ audio) {
    __shared__ __align__(128) char sAh[128 * ASTRIDE];
    __shared__ __align__(128) char sAl[128 * ASTRIDE];
    __shared__ __align__(128) char sBh[128 * ASTRIDE];
    __shared__ __align__(128) char sBl[128 * ASTRIDE];

    const int tid = threadIdx.x;
    const int lane = tid & 31;
    const int warp = tid >> 5;
    const int wm = warp >> 2;        // 0..1
    const int wn = warp & 3;         // 0..3
    const int ntile = blockIdx.x;
    const int mtile = blockIdx.y;

    const uint32_t aAh = smem_u32(sAh);
    const uint32_t aAl = smem_u32(sAl);
    const uint32_t aBh = smem_u32(sBh);
    const uint32_t aBl = smem_u32(sBl);

    // per-thread tile-build coordinates
    const int brow = tid >> 1;       // 0..127
    const int bhalf = tid & 1;       // 16 floats each
    const int frame = ntile * NT + brow;
    const int bb = frame / NFRAMES;
    const int bt = frame - bb * NFRAMES;
    const float* ap = audio + (size_t)bb * CHUNK;
    const int sbase = bt * HOP - 200 + bhalf * 16;

    // ldmatrix base addresses (add ks*32 per k16 step)
    // A: rows wm*64 + mi*16 + (lane&15), col halves by lane>>4
    uint32_t aAddrOff = (uint32_t)((wm * 64 + (lane & 15)) * ASTRIDE + ((lane >> 4) << 4));
    // B: rows wn*32 + ni2*16 + (lane&7) + ((lane>>4)<<3), col halves by (lane>>3)&1
    uint32_t bAddrOff = (uint32_t)((wn * 32 + (lane & 7) + ((lane >> 4) << 3)) * ASTRIDE
                                   + (((lane >> 3) & 1) << 4));

    float acc[4][4][4];
#pragma unroll
    for (int mi = 0; mi < 4; ++mi)
#pragma unroll
        for (int ni = 0; ni < 4; ++ni)
#pragma unroll
            for (int q = 0; q < 4; ++q) acc[mi][ni][q] = 0.0f;

    for (int ch = 0; ch < NCHUNK; ++ch) {
        // ---- build B tile (hi/lo) from audio ----
        {
            const int s0 = sbase + ch * KC;
            float v[16];
            if (s0 >= 0 && s0 + 16 <= CHUNK) {
#pragma unroll
                for (int q = 0; q < 4; ++q) {
                    float4 x = *reinterpret_cast<const float4*>(ap + s0 + 4 * q);
                    v[4 * q] = x.x; v[4 * q + 1] = x.y; v[4 * q + 2] = x.z; v[4 * q + 3] = x.w;
                }
            } else {
#pragma unroll
                for (int q = 0; q < 16; ++q) {
                    int s = s0 + q;
                    if (s < 0) s = -s;
                    if (s >= CHUNK) s = 2 * CHUNK - 2 - s;
                    v[q] = ap[s];
                }
            }
            unsigned hi[8], lo[8];
#pragma unroll
            for (int q = 0; q < 8; ++q) {
                unsigned short h0, l0, h1, l1;
                split_bf16(v[2 * q], h0, l0);
                split_bf16(v[2 * q + 1], h1, l1);
                hi[q] = ((unsigned)h1 << 16) | h0;
                lo[q] = ((unsigned)l1 << 16) | l0;
            }
            char* dh = sBh + brow * ASTRIDE + bhalf * 32;
            char* dl = sBl + brow * ASTRIDE + bhalf * 32;
            *reinterpret_cast<uint4*>(dh)      = *reinterpret_cast<uint4*>(hi);
            *reinterpret_cast<uint4*>(dh + 16) = *reinterpret_cast<uint4*>(hi + 4);
            *reinterpret_cast<uint4*>(dl)      = *reinterpret_cast<uint4*>(lo);
            *reinterpret_cast<uint4*>(dl + 16) = *reinterpret_cast<uint4*>(lo + 4);
        }
        // ---- copy A tile (hi/lo) from gmem ----
        {
            const char* gh = reinterpret_cast<const char*>(g_ah)
                           + (size_t)(mtile * 128 + brow) * (KPAD * 2) + ch * (KC * 2) + bhalf * 32;
            const char* gl = reinterpret_cast<const char*>(g_al)
                           + (size_t)(mtile * 128 + brow) * (KPAD * 2) + ch * (KC * 2) + bhalf * 32;
            char* dh = sAh + brow * ASTRIDE + bhalf * 32;
            char* dl = sAl + brow * ASTRIDE + bhalf * 32;
            *reinterpret_cast<uint4*>(dh)      = *reinterpret_cast<const uint4*>(gh);
            *reinterpret_cast<uint4*>(dh + 16) = *reinterpret_cast<const uint4*>(gh + 16);
            *reinterpret_cast<uint4*>(dl)      = *reinterpret_cast<const uint4*>(gl);
            *reinterpret_cast<uint4*>(dl + 16) = *reinterpret_cast<const uint4*>(gl + 16);
        }
        __syncthreads();

        // ---- MMA: 2 k16 steps x (AhBh + AhBl + AlBh) ----
#pragma unroll
        for (int ks = 0; ks < 2; ++ks) {
            const uint32_t kb = (uint32_t)(ks * 32);
            uint32_t ah[4][4], bh[4][2], bl[4][2];
#pragma unroll
            for (int mi = 0; mi < 4; ++mi)
                ldsm_x4(ah[mi][0], ah[mi][1], ah[mi][2], ah[mi][3],
                        aAh + aAddrOff + (uint32_t)(mi * 16 * ASTRIDE) + kb);
#pragma unroll
            for (int ni2 = 0; ni2 < 2; ++ni2) {
                ldsm_x4(bh[2 * ni2][0], bh[2 * ni2][1], bh[2 * ni2 + 1][0], bh[2 * ni2 + 1][1],
                        aBh + bAddrOff + (uint32_t)(ni2 * 16 * ASTRIDE) + kb);
                ldsm_x4(bl[2 * ni2][0], bl[2 * ni2][1], bl[2 * ni2 + 1][0], bl[2 * ni2 + 1][1],
                        aBl + bAddrOff + (uint32_t)(ni2 * 16 * ASTRIDE) + kb);
            }
#pragma unroll
            for (int mi = 0; mi < 4; ++mi)
#pragma unroll
                for (int ni = 0; ni < 4; ++ni)
                    mma16816(acc[mi][ni], ah[mi], bh[ni][0], bh[ni][1]);
#pragma unroll
            for (int mi = 0; mi < 4; ++mi)
#pragma unroll
                for (int ni = 0; ni < 4; ++ni)
                    mma16816(acc[mi][ni], ah[mi], bl[ni][0], bl[ni][1]);
            // A-lo pass (load after Ah is dead so registers recycle)
            uint32_t al[4][4];
#pragma unroll
            for (int mi = 0; mi < 4; ++mi)
                ldsm_x4(al[mi][0], al[mi][1], al[mi][2], al[mi][3],
                        aAl + aAddrOff + (uint32_t)(mi * 16 * ASTRIDE) + kb);
#pragma unroll
            for (int mi = 0; mi < 4; ++mi)
#pragma unroll
                for (int ni = 0; ni < 4; ++ni)
                    mma16816(acc[mi][ni], al[mi], bh[ni][0], bh[ni][1]);
        }
        __syncthreads();
    }

    // ---- epilogue: power = re^2 + im^2 (row pairs are lane^4), write g_power ----
    const int r = lane >> 2;
    const bool evenr = (r & 1) == 0;
    const int Rw = mtile * 128 + wm * 64;
#pragma unroll
    for (int mi = 0; mi < 4; ++mi) {
#pragma unroll
        for (int ni = 0; ni < 4; ++ni) {
            float p0 = acc[mi][ni][0] * acc[mi][ni][0];
            float p1 = acc[mi][ni][1] * acc[mi][ni][1];
            float p2 = acc[mi][ni][2] * acc[mi][ni][2];
            float p3 = acc[mi][ni][3] * acc[mi][ni][3];
            p0 += __shfl_xor_sync(0xffffffffu, p0, 4);
            p1 += __shfl_xor_sync(0xffffffffu, p1, 4);
            p2 += __shfl_xor_sync(0xffffffffu, p2, 4);
            p3 += __shfl_xor_sync(0xffffffffu, p3, 4);
            if (evenr) {
                const int fr = ntile * NT + wn * 32 + ni * 8 + 2 * (lane & 3);
                const int R0 = Rw + mi * 16 + r;
                if (R0 < MROWS) {
                    float2* dst = reinterpret_cast<float2*>(g_power + (size_t)(R0 >> 1) * NFRTOT + fr);
                    *dst = make_float2(p0, p1);
                }
                const int R1 = R0 + 8;
                if (R1 < MROWS) {
                    float2* dst = reinterpret_cast<float2*>(g_power + (size_t)(R1 >> 1) * NFRTOT + fr);
                    *dst = make_float2(p2, p3);
                }
            }
        }
    }
}

// ---------------- mel + log10 + per-batch max -----------------------------------
__global__ void __launch_bounds__(256) mel_kernel(const float* __restrict__ fb,
                                                  float* __restrict__ out) {
    const int b = blockIdx.y;
    const int t = blockIdx.x * blockDim.x + threadIdx.x;
    float localmax = -3.0e38f;
    if (t < NFRAMES) {
        const float* pw = g_power + (size_t)b * NFRAMES + t;   // [f][global frame]
        float* op = out + (size_t)b * NMELS * NFRAMES + t;
        for (int m = 0; m < NMELS; ++m) {
            const int lo = g_lo[m];
            const int hi = g_hi[m];
            float acc = 0.0f;
            for (int f = lo; f < hi; ++f)
                acc = fmaf(fb[m * NFREQ + f], pw[(size_t)f * NFRTOT], acc);
            float lm = log10f(fmaxf(acc, 1e-10f));
            op[(size_t)m * NFRAMES] = lm;
            localmax = fmaxf(localmax, lm);
        }
    }
#pragma unroll
    for (int o = 16; o; o >>= 1)
        localmax = fmaxf(localmax, __shfl_xor_sync(0xffffffffu, localmax, o));
    if ((threadIdx.x & 31) == 0) atomicMax(&g_max[b], f2ord(localmax));
}

// ---------------- finalize: floor at max-8, normalize ---------------------------
__global__ void __launch_bounds__(256) fin_kernel(float* __restrict__ out) {
    const int b = blockIdx.y;
    const float floorv = ord2f(g_max[b]) - 8.0f;
    const size_t idx = (size_t)blockIdx.x * blockDim.x + threadIdx.x;
    const size_t per = (size_t)NMELS * NFRAMES / 4;
    if (idx < per) {
        float4* p = reinterpret_cast<float4*>(out + (size_t)b * NMELS * NFRAMES) + idx;
        float4 v = *p;
        v.x = (fmaxf(v.x, floorv) + 4.0f) * 0.25f;
        v.y = (fmaxf(v.y, floorv) + 4.0f) * 0.25f;
        v.z = (fmaxf(v.z, floorv) + 4.0f) * 0.25f;
        v.w = (fmaxf(v.w, floorv) + 4.0f) * 0.25f;
        *p = v;
    }
}

// ---------------- launch --------------------------------------------------------
extern "C" void kernel_launch(void* const* d_in, const int* in_sizes, int n_in,
                              void* d_out, int out_size) {
    const float* audio = (const float*)d_in[0];
    const float* cosk  = (const float*)d_in[1];
    const float* sink  = (const float*)d_in[2];
    const float* fb    = (const float*)d_in[3];
    float* out = (float*)d_out;

    prep_kernel<<<448, 256>>>(cosk, sink, fb);

    dim3 gs(NNT, 4);                               // (750, 4)
    stft_mma_kernel<<<gs, 256>>>(audio);

    dim3 gm((NFRAMES + 255) / 256, BATCH);
    mel_kernel<<<gm, 256>>>(fb, out);

    dim3 gf((NMELS * NFRAMES / 4 + 255) / 256, BATCH);
    fin_kernel<<<gf, 256>>>(out);
}

// round 5
// speedup vs baseline: 3.4199x; 1.8847x over previous
#include <cuda_runtime.h>
#include <cuda_fp16.h>
#include <cstdint>

#define BATCH   32
#define CHUNK   480000
#define NFFT    400
#define HOP     160
#define NMELS   128
#define NFREQ   201
#define NFRAMES 3000
#define NFRTOT  (BATCH * NFRAMES)   // 96000
#define MROWS   402                 // 201 freqs x (cos,sin)
#define MPAD    512                 // 4 tiles of 128
#define KTOT    400
#define KC      80
#define NCHUNK  (KTOT / KC)         // 5
#define NT      128                 // frames per block
#define NNT     (NFRTOT / NT)       // 750
#define ASTR    176                 // smem row stride bytes (80 fp16 = 160B + 16 pad)
#define ABYTES  (128 * ASTR)        // 22528 per tile
#define BUFB    (2 * ABYTES)        // one stage (A + B)
#define SMEMSZ  (2 * BUFB)          // 90112 (double buffered)

// ---------------- device scratch ------------------------------------------------
__device__ float  g_power[(size_t)NFREQ * NFRTOT];        // [f][global frame], 77 MB
__device__ __align__(16) __half g_ah[MPAD * KTOT];        // fp16 DFT table [512][400]
__device__ __align__(16) __half g_xh[(size_t)BATCH * CHUNK];  // fp16 audio, 30 MB
__device__ unsigned g_max[BATCH];
__device__ int      g_lo[NMELS];
__device__ int      g_hi[NMELS];

// ---------------- helpers -------------------------------------------------------
__device__ __forceinline__ uint32_t smem_u32(const void* p) {
    uint32_t a;
    asm("{ .reg .u64 t; cvta.to.shared.u64 t, %1; cvt.u32.u64 %0, t; }" : "=r"(a) : "l"(p));
    return a;
}
__device__ __forceinline__ void cp16(uint32_t saddr, const void* gaddr) {
    asm volatile("cp.async.cg.shared.global [%0], [%1], 16;" :: "r"(saddr), "l"(gaddr) : "memory");
}
__device__ __forceinline__ void ldsm_x4(uint32_t& r0, uint32_t& r1, uint32_t& r2, uint32_t& r3,
                                        uint32_t addr) {
    asm volatile("ldmatrix.sync.aligned.m8n8.x4.shared.b16 {%0,%1,%2,%3}, [%4];"
                 : "=r"(r0), "=r"(r1), "=r"(r2), "=r"(r3) : "r"(addr));
}
__device__ __forceinline__ void mma16816(float* d, const uint32_t* a, uint32_t b0, uint32_t b1) {
    asm volatile("mma.sync.aligned.m16n8k16.row.col.f32.f16.f16.f32 "
                 "{%0,%1,%2,%3}, {%4,%5,%6,%7}, {%8,%9}, {%0,%1,%2,%3};"
                 : "+f"(d[0]), "+f"(d[1]), "+f"(d[2]), "+f"(d[3])
                 : "r"(a[0]), "r"(a[1]), "r"(a[2]), "r"(a[3]), "r"(b0), "r"(b1));
}
__device__ __forceinline__ unsigned f2ord(float f) {
    unsigned u = __float_as_uint(f);
    return (u & 0x80000000u) ? ~u : (u | 0x80000000u);
}
__device__ __forceinline__ float ord2f(unsigned u) {
    return __uint_as_float((u & 0x80000000u) ? (u & 0x7fffffffu) : ~u);
}

// ---------------- prep: fp16 A table, fp16 audio, mel ranges, maxes -------------
__global__ void prep_kernel(const float* __restrict__ audio,
                            const float* __restrict__ cosk,
                            const float* __restrict__ sink,
                            const float* __restrict__ fb) {
    const int idx = blockIdx.x * blockDim.x + threadIdx.x;
    const int stride = gridDim.x * blockDim.x;

    // audio -> fp16 (vectorized by 4)
    const int n4 = BATCH * CHUNK / 4;
    for (int i = idx; i < n4; i += stride) {
        float4 x = reinterpret_cast<const float4*>(audio)[i];
        __half2 h0 = __floats2half2_rn(x.x, x.y);
        __half2 h1 = __floats2half2_rn(x.z, x.w);
        reinterpret_cast<__half2*>(g_xh)[2 * i]     = h0;
        reinterpret_cast<__half2*>(g_xh)[2 * i + 1] = h1;
    }
    // A table: row R = 2f + (0=cos,1=sin), col K
    const int total = MPAD * KTOT;
    for (int e = idx; e < total; e += stride) {
        int R = e / KTOT;
        int K = e - R * KTOT;
        float v = 0.0f;
        if (R < MROWS) {
            int f = R >> 1;
            v = (R & 1) ? sink[f * NFFT + K] : cosk[f * NFFT + K];
        }
        g_ah[e] = __float2half_rn(v);
    }
    if (idx < NMELS) {
        int lo = NFREQ, hi = 0;
        for (int f = 0; f < NFREQ; ++f) {
            if (fb[idx * NFREQ + f] != 0.0f) { if (f < lo) lo = f; hi = f + 1; }
        }
        if (lo >= hi) { lo = 0; hi = 0; }
        g_lo[idx] = lo;
        g_hi[idx] = hi;
    }
    if (idx < BATCH) g_max[idx] = f2ord(-3.0e38f);
}

// ---------------- STFT power via single-pass fp16 mma.sync ----------------------
// grid (750, 4): x = frame tile (128 frames), y = M tile (128 rows).
// 256 threads = 8 warps (2m x 4n), warp tile 64M x 32N.
struct LoadCtx {
    const __half* gA;     // A row base (this thread's 40-half slice, chunk 0)
    const __half* xp;     // audio (fp16) for this row's batch element
    int sbase;            // audio half-index of this thread's slice at chunk 0
    uint32_t dA;          // smem byte offset (buffer 0) for A slice
    uint32_t dB;          // smem byte offset (buffer 0) for B slice
};

__device__ __forceinline__ void issue_loads(const LoadCtx& L, char* smem, int c, int buf) {
    char* dA = smem + buf * BUFB + L.dA;
    char* dB = smem + buf * BUFB + L.dB;
    const __half* gA = L.gA + c * KC;
#pragma unroll
    for (int q = 0; q < 5; ++q)
        cp16(smem_u32(dA + 16 * q), gA + 8 * q);
    const int s0 = L.sbase + c * KC;
    if (s0 >= 0 && s0 + 40 <= CHUNK) {
        const __half* gB = L.xp + s0;
#pragma unroll
        for (int q = 0; q < 5; ++q)
            cp16(smem_u32(dB + 16 * q), gB + 8 * q);
    } else {
        __half* hB = reinterpret_cast<__half*>(dB);
#pragma unroll
        for (int q = 0; q < 40; ++q) {
            int s = s0 + q;
            if (s < 0) s = -s;
            if (s >= CHUNK) s = 2 * CHUNK - 2 - s;
            hB[q] = L.xp[s];
        }
    }
}

__global__ void __launch_bounds__(256, 2) stft_mma_kernel() {
    extern __shared__ __align__(128) char smem[];
    const int tid = threadIdx.x;
    const int lane = tid & 31;
    const int warp = tid >> 5;
    const int wm = warp >> 2;        // 0..1
    const int wn = warp & 3;         // 0..3
    const int ntile = blockIdx.x;
    const int mtile = blockIdx.y;

    // per-thread load slice: row = tid>>1 (0..127), half-slice = tid&1 (40 halves)
    const int brow = tid >> 1;
    const int bhalf = tid & 1;
    const int frame = ntile * NT + brow;
    const int bb = frame / NFRAMES;
    const int bt = frame - bb * NFRAMES;

    LoadCtx L;
    L.xp = g_xh + (size_t)bb * CHUNK;
    L.sbase = bt * HOP - 200 + bhalf * 40;
    L.gA = g_ah + (size_t)(mtile * 128 + brow) * KTOT + bhalf * 40;
    L.dA = (uint32_t)(brow * ASTR + bhalf * 80);
    L.dB = L.dA + ABYTES;

    // ldmatrix addressing (verified layout from R4)
    const uint32_t sbase32 = smem_u32(smem);
    const uint32_t aAddrOff = (uint32_t)((wm * 64 + (lane & 15)) * ASTR + ((lane >> 4) << 4));
    const uint32_t bAddrOff = (uint32_t)((wn * 32 + (lane & 7) + ((lane >> 4) << 3)) * ASTR
                                         + (((lane >> 3) & 1) << 4));

    float acc[4][4][4];
#pragma unroll
    for (int mi = 0; mi < 4; ++mi)
#pragma unroll
        for (int ni = 0; ni < 4; ++ni)
#pragma unroll
            for (int q = 0; q < 4; ++q) acc[mi][ni][q] = 0.0f;

    issue_loads(L, smem, 0, 0);
    asm volatile("cp.async.commit_group;" ::: "memory");

#pragma unroll
    for (int c = 0; c < NCHUNK; ++c) {
        if (c + 1 < NCHUNK) {
            issue_loads(L, smem, c + 1, (c + 1) & 1);
            asm volatile("cp.async.commit_group;" ::: "memory");
            asm volatile("cp.async.wait_group 1;" ::: "memory");
        } else {
            asm volatile("cp.async.wait_group 0;" ::: "memory");
        }
        __syncthreads();

        const uint32_t aA = sbase32 + (uint32_t)((c & 1) * BUFB);
        const uint32_t aB = aA + ABYTES;
#pragma unroll
        for (int ks = 0; ks < 5; ++ks) {
            const uint32_t kb = (uint32_t)(ks * 32);
            uint32_t ah[4][4], bq[4][2];
#pragma unroll
            for (int mi = 0; mi < 4; ++mi)
                ldsm_x4(ah[mi][0], ah[mi][1], ah[mi][2], ah[mi][3],
                        aA + aAddrOff + (uint32_t)(mi * 16 * ASTR) + kb);
#pragma unroll
            for (int ni2 = 0; ni2 < 2; ++ni2)
                ldsm_x4(bq[2 * ni2][0], bq[2 * ni2][1], bq[2 * ni2 + 1][0], bq[2 * ni2 + 1][1],
                        aB + bAddrOff + (uint32_t)(ni2 * 16 * ASTR) + kb);
#pragma unroll
            for (int mi = 0; mi < 4; ++mi)
#pragma unroll
                for (int ni = 0; ni < 4; ++ni)
                    mma16816(acc[mi][ni], ah[mi], bq[ni][0], bq[ni][1]);
        }
        __syncthreads();
    }

    // ---- epilogue: power = re^2 + im^2 (row pairs are lane^4), write g_power ----
    const int r = lane >> 2;
    const bool evenr = (r & 1) == 0;
    const int Rw = mtile * 128 + wm * 64;
#pragma unroll
    for (int mi = 0; mi < 4; ++mi) {
#pragma unroll
        for (int ni = 0; ni < 4; ++ni) {
            float p0 = acc[mi][ni][0] * acc[mi][ni][0];
            float p1 = acc[mi][ni][1] * acc[mi][ni][1];
            float p2 = acc[mi][ni][2] * acc[mi][ni][2];
            float p3 = acc[mi][ni][3] * acc[mi][ni][3];
            p0 += __shfl_xor_sync(0xffffffffu, p0, 4);
            p1 += __shfl_xor_sync(0xffffffffu, p1, 4);
            p2 += __shfl_xor_sync(0xffffffffu, p2, 4);
            p3 += __shfl_xor_sync(0xffffffffu, p3, 4);
            if (evenr) {
                const int fr = ntile * NT + wn * 32 + ni * 8 + 2 * (lane & 3);
                const int R0 = Rw + mi * 16 + r;
                if (R0 < MROWS) {
                    float2* dst = reinterpret_cast<float2*>(g_power + (size_t)(R0 >> 1) * NFRTOT + fr);
                    *dst = make_float2(p0, p1);
                }
                const int R1 = R0 + 8;
                if (R1 < MROWS) {
                    float2* dst = reinterpret_cast<float2*>(g_power + (size_t)(R1 >> 1) * NFRTOT + fr);
                    *dst = make_float2(p2, p3);
                }
            }
        }
    }
}

// ---------------- mel + log10 + per-batch max -----------------------------------
__global__ void __launch_bounds__(256) mel_kernel(const float* __restrict__ fb,
                                                  float* __restrict__ out) {
    const int b = blockIdx.y;
    const int t = blockIdx.x * blockDim.x + threadIdx.x;
    float localmax = -3.0e38f;
    if (t < NFRAMES) {
        const float* pw = g_power + (size_t)b * NFRAMES + t;   // [f][global frame]
        float* op = out + (size_t)b * NMELS * NFRAMES + t;
        for (int m = 0; m < NMELS; ++m) {
            const int lo = g_lo[m];
            const int hi = g_hi[m];
            float acc = 0.0f;
            for (int f = lo; f < hi; ++f)
                acc = fmaf(fb[m * NFREQ + f], pw[(size_t)f * NFRTOT], acc);
            float lm = log10f(fmaxf(acc, 1e-10f));
            op[(size_t)m * NFRAMES] = lm;
            localmax = fmaxf(localmax, lm);
        }
    }
#pragma unroll
    for (int o = 16; o; o >>= 1)
        localmax = fmaxf(localmax, __shfl_xor_sync(0xffffffffu, localmax, o));
    if ((threadIdx.x & 31) == 0) atomicMax(&g_max[b], f2ord(localmax));
}

// ---------------- finalize: floor at max-8, normalize ---------------------------
__global__ void __launch_bounds__(256) fin_kernel(float* __restrict__ out) {
    const int b = blockIdx.y;
    const float floorv = ord2f(g_max[b]) - 8.0f;
    const size_t idx = (size_t)blockIdx.x * blockDim.x + threadIdx.x;
    const size_t per = (size_t)NMELS * NFRAMES / 4;
    if (idx < per) {
        float4* p = reinterpret_cast<float4*>(out + (size_t)b * NMELS * NFRAMES) + idx;
        float4 v = *p;
        v.x = (fmaxf(v.x, floorv) + 4.0f) * 0.25f;
        v.y = (fmaxf(v.y, floorv) + 4.0f) * 0.25f;
        v.z = (fmaxf(v.z, floorv) + 4.0f) * 0.25f;
        v.w = (fmaxf(v.w, floorv) + 4.0f) * 0.25f;
        *p = v;
    }
}

// ---------------- launch --------------------------------------------------------
extern "C" void kernel_launch(void* const* d_in, const int* in_sizes, int n_in,
                              void* d_out, int out_size) {
    const float* audio = (const float*)d_in[0];
    const float* cosk  = (const float*)d_in[1];
    const float* sink  = (const float*)d_in[2];
    const float* fb    = (const float*)d_in[3];
    float* out = (float*)d_out;

    cudaFuncSetAttribute(stft_mma_kernel, cudaFuncAttributeMaxDynamicSharedMemorySize, SMEMSZ);

    prep_kernel<<<2048, 256>>>(audio, cosk, sink, fb);

    dim3 gs(NNT, 4);                               // (750, 4)
    stft_mma_kernel<<<gs, 256, SMEMSZ>>>();

    dim3 gm((NFRAMES + 255) / 256, BATCH);
    mel_kernel<<<gm, 256>>>(fb, out);

    dim3 gf((NMELS * NFRAMES / 4 + 255) / 256, BATCH);
    fin_kernel<<<gf, 256>>>(out);
}

// round 7
// speedup vs baseline: 3.5722x; 1.0445x over previous
#include <cuda_runtime.h>
#include <cuda_fp16.h>
#include <cstdint>

#define BATCH   32
#define CHUNK   480000
#define NFFT    400
#define HOP     160
#define NMELS   128
#define NFREQ   201
#define NFRAMES 3000
#define NFRTOT  (BATCH * NFRAMES)   // 96000
#define MROWS   402                 // 201 freqs x (cos,sin)
#define MPAD    512                 // table padded to 4 tiles of 128
#define KTOT    400
#define KC      80
#define NCHUNK  (KTOT / KC)         // 5
#define NT      128                 // frames per block
#define NNT     (NFRTOT / NT)       // 750
#define ASTR    176                 // smem row stride bytes (80 fp16 = 160B + 16 pad)
#define ABYTES  (128 * ASTR)        // 22528 per tile
#define BUFB    (2 * ABYTES)        // one stage (A + B)
#define SMEMSZ  (2 * BUFB)          // 90112 (double buffered)

// ---------------- device scratch ------------------------------------------------
__device__ float  g_power[(size_t)NFREQ * NFRTOT];        // [f][global frame], 77 MB
__device__ __align__(16) __half g_ah[MPAD * KTOT];        // fp16 DFT table [512][400]
__device__ __align__(16) __half g_xh[(size_t)BATCH * CHUNK];  // fp16 audio, 30 MB
__device__ unsigned g_max[BATCH];
__device__ int   g_idx[NFREQ];    // first mel bin with nonzero weight at freq f
__device__ float g_w0[NFREQ];     // weight into bin idx
__device__ float g_w1[NFREQ];     // weight into bin idx+1

// ---------------- helpers -------------------------------------------------------
__device__ __forceinline__ uint32_t smem_u32(const void* p) {
    uint32_t a;
    asm("{ .reg .u64 t; cvta.to.shared.u64 t, %1; cvt.u32.u64 %0, t; }" : "=r"(a) : "l"(p));
    return a;
}
__device__ __forceinline__ void cp16(uint32_t saddr, const void* gaddr) {
    asm volatile("cp.async.cg.shared.global [%0], [%1], 16;" :: "r"(saddr), "l"(gaddr) : "memory");
}
__device__ __forceinline__ void ldsm_x4(uint32_t& r0, uint32_t& r1, uint32_t& r2, uint32_t& r3,
                                        uint32_t addr) {
    asm volatile("ldmatrix.sync.aligned.m8n8.x4.shared.b16 {%0,%1,%2,%3}, [%4];"
                 : "=r"(r0), "=r"(r1), "=r"(r2), "=r"(r3) : "r"(addr));
}
__device__ __forceinline__ void mma16816(float* d, const uint32_t* a, uint32_t b0, uint32_t b1) {
    asm volatile("mma.sync.aligned.m16n8k16.row.col.f32.f16.f16.f32 "
                 "{%0,%1,%2,%3}, {%4,%5,%6,%7}, {%8,%9}, {%0,%1,%2,%3};"
                 : "+f"(d[0]), "+f"(d[1]), "+f"(d[2]), "+f"(d[3])
                 : "r"(a[0]), "r"(a[1]), "r"(a[2]), "r"(a[3]), "r"(b0), "r"(b1));
}
__device__ __forceinline__ unsigned f2ord(float f) {
    unsigned u = __float_as_uint(f);
    return (u & 0x80000000u) ? ~u : (u | 0x80000000u);
}
__device__ __forceinline__ float ord2f(unsigned u) {
    return __uint_as_float((u & 0x80000000u) ? (u & 0x7fffffffu) : ~u);
}

// ---------------- prep: fp16 A table, fp16 audio, mel bin map, maxes ------------
__global__ void prep_kernel(const float* __restrict__ audio,
                            const float* __restrict__ cosk,
                            const float* __restrict__ sink,
                            const float* __restrict__ fb) {
    const int idx = blockIdx.x * blockDim.x + threadIdx.x;
    const int stride = gridDim.x * blockDim.x;

    // audio -> fp16 (vectorized by 4)
    const int n4 = BATCH * CHUNK / 4;
    for (int i = idx; i < n4; i += stride) {
        float4 x = reinterpret_cast<const float4*>(audio)[i];
        __half2 h0 = __floats2half2_rn(x.x, x.y);
        __half2 h1 = __floats2half2_rn(x.z, x.w);
        reinterpret_cast<__half2*>(g_xh)[2 * i]     = h0;
        reinterpret_cast<__half2*>(g_xh)[2 * i + 1] = h1;
    }
    // A table: row R = 2f + (0=cos,1=sin), col K
    const int total = MPAD * KTOT;
    for (int e = idx; e < total; e += stride) {
        int R = e / KTOT;
        int K = e - R * KTOT;
        float v = 0.0f;
        if (R < MROWS) {
            int f = R >> 1;
            v = (R & 1) ? sink[f * NFFT + K] : cosk[f * NFFT + K];
        }
        g_ah[e] = __float2half_rn(v);
    }
    // per-freq mel map: each fft bin hits at most 2 adjacent mel filters
    if (idx < NFREQ) {
        int m0 = -1;
        float w0 = 0.0f, w1 = 0.0f;
        for (int m = 0; m < NMELS; ++m) {
            float w = fb[m * NFREQ + idx];
            if (w > 0.0f) {
                if (m0 < 0) { m0 = m; w0 = w; }
                else if (m == m0 + 1) { w1 = w; }
            }
        }
        if (m0 < 0) { m0 = 0; w0 = 0.0f; w1 = 0.0f; }
        g_idx[idx] = m0;
        g_w0[idx] = w0;
        g_w1[idx] = w1;
    }
    if (idx < BATCH) g_max[idx] = f2ord(-3.0e38f);
}

// ---------------- STFT power via single-pass fp16 mma.sync ----------------------
// grid (750, 4): x = frame tile (128 frames), y = M tile.
// mtiles 0..2: 128 rows; mtile 3: 64 real rows — rows 448..511 of the padded
// table are garbage, so wm==1 warps there skip MMA/epilogue (−12.5% HMMA).
struct LoadCtx {
    const __half* gA;
    const __half* xp;
    int sbase;
    uint32_t dA;
    uint32_t dB;
};

__device__ __forceinline__ void issue_loads(const LoadCtx& L, char* smem, int c, int buf) {
    char* dA = smem + buf * BUFB + L.dA;
    char* dB = smem + buf * BUFB + L.dB;
    const __half* gA = L.gA + c * KC;
#pragma unroll
    for (int q = 0; q < 5; ++q)
        cp16(smem_u32(dA + 16 * q), gA + 8 * q);
    const int s0 = L.sbase + c * KC;
    if (s0 >= 0 && s0 + 40 <= CHUNK) {
        const __half* gB = L.xp + s0;
#pragma unroll
        for (int q = 0; q < 5; ++q)
            cp16(smem_u32(dB + 16 * q), gB + 8 * q);
    } else {
        __half* hB = reinterpret_cast<__half*>(dB);
#pragma unroll
        for (int q = 0; q < 40; ++q) {
            int s = s0 + q;
            if (s < 0) s = -s;
            if (s >= CHUNK) s = 2 * CHUNK - 2 - s;
            hB[q] = L.xp[s];
        }
    }
}

__global__ void __launch_bounds__(256, 2) stft_mma_kernel() {
    extern __shared__ __align__(128) char smem[];
    const int tid = threadIdx.x;
    const int lane = tid & 31;
    const int warp = tid >> 5;
    const int wm = warp >> 2;        // 0..1
    const int wn = warp & 3;         // 0..3
    const int ntile = blockIdx.x;
    const int mtile = blockIdx.y;
    const bool active = !(mtile == 3 && wm == 1);   // half tile: upper warps idle in MMA

    const int brow = tid >> 1;
    const int bhalf = tid & 1;
    const int frame = ntile * NT + brow;
    const int bb = frame / NFRAMES;
    const int bt = frame - bb * NFRAMES;

    LoadCtx L;
    L.xp = g_xh + (size_t)bb * CHUNK;
    L.sbase = bt * HOP - 200 + bhalf * 40;
    L.gA = g_ah + (size_t)(mtile * 128 + brow) * KTOT + bhalf * 40;
    L.dA = (uint32_t)(brow * ASTR + bhalf * 80);
    L.dB = L.dA + ABYTES;

    const uint32_t sbase32 = smem_u32(smem);
    const uint32_t aAddrOff = (uint32_t)((wm * 64 + (lane & 15)) * ASTR + ((lane >> 4) << 4));
    const uint32_t bAddrOff = (uint32_t)((wn * 32 + (lane & 7) + ((lane >> 4) << 3)) * ASTR
                                         + (((lane >> 3) & 1) << 4));

    float acc[4][4][4];
#pragma unroll
    for (int mi = 0; mi < 4; ++mi)
#pragma unroll
        for (int ni = 0; ni < 4; ++ni)
#pragma unroll
            for (int q = 0; q < 4; ++q) acc[mi][ni][q] = 0.0f;

    issue_loads(L, smem, 0, 0);
    asm volatile("cp.async.commit_group;" ::: "memory");

#pragma unroll
    for (int c = 0; c < NCHUNK; ++c) {
        if (c + 1 < NCHUNK) {
            issue_loads(L, smem, c + 1, (c + 1) & 1);
            asm volatile("cp.async.commit_group;" ::: "memory");
            asm volatile("cp.async.wait_group 1;" ::: "memory");
        } else {
            asm volatile("cp.async.wait_group 0;" ::: "memory");
        }
        __syncthreads();

        if (active) {
            const uint32_t aA = sbase32 + (uint32_t)((c & 1) * BUFB);
            const uint32_t aB = aA + ABYTES;
#pragma unroll
            for (int ks = 0; ks < 5; ++ks) {
                const uint32_t kb = (uint32_t)(ks * 32);
                uint32_t ah[4][4], bq[4][2];
#pragma unroll
                for (int mi = 0; mi < 4; ++mi)
                    ldsm_x4(ah[mi][0], ah[mi][1], ah[mi][2], ah[mi][3],
                            aA + aAddrOff + (uint32_t)(mi * 16 * ASTR) + kb);
#pragma unroll
                for (int ni2 = 0; ni2 < 2; ++ni2)
                    ldsm_x4(bq[2 * ni2][0], bq[2 * ni2][1], bq[2 * ni2 + 1][0], bq[2 * ni2 + 1][1],
                            aB + bAddrOff + (uint32_t)(ni2 * 16 * ASTR) + kb);
#pragma unroll
                for (int mi = 0; mi < 4; ++mi)
#pragma unroll
                    for (int ni = 0; ni < 4; ++ni)
                        mma16816(acc[mi][ni], ah[mi], bq[ni][0], bq[ni][1]);
            }
        }
        __syncthreads();
    }

    if (!active) return;

    // ---- epilogue: power = re^2 + im^2 (row pairs are lane^4), write g_power ----
    const int r = lane >> 2;
    const bool evenr = (r & 1) == 0;
    const int Rw = mtile * 128 + wm * 64;
#pragma unroll
    for (int mi = 0; mi < 4; ++mi) {
#pragma unroll
        for (int ni = 0; ni < 4; ++ni) {
            float p0 = acc[mi][ni][0] * acc[mi][ni][0];
            float p1 = acc[mi][ni][1] * acc[mi][ni][1];
            float p2 = acc[mi][ni][2] * acc[mi][ni][2];
            float p3 = acc[mi][ni][3] * acc[mi][ni][3];
            p0 += __shfl_xor_sync(0xffffffffu, p0, 4);
            p1 += __shfl_xor_sync(0xffffffffu, p1, 4);
            p2 += __shfl_xor_sync(0xffffffffu, p2, 4);
            p3 += __shfl_xor_sync(0xffffffffu, p3, 4);
            if (evenr) {
                const int fr = ntile * NT + wn * 32 + ni * 8 + 2 * (lane & 3);
                const int R0 = Rw + mi * 16 + r;
                if (R0 < MROWS) {
                    float2* dst = reinterpret_cast<float2*>(g_power + (size_t)(R0 >> 1) * NFRTOT + fr);
                    *dst = make_float2(p0, p1);
                }
                const int R1 = R0 + 8;
                if (R1 < MROWS) {
                    float2* dst = reinterpret_cast<float2*>(g_power + (size_t)(R1 >> 1) * NFRTOT + fr);
                    *dst = make_float2(p2, p3);
                }
            }
        }
    }
}

// ---------------- mel: streaming 2-bin merge + log10 + per-batch max ------------
// Each fft bin contributes to mel bins idx[f] (w0) and idx[f]+1 (w1); idx is
// nondecreasing in f, so a two-register running-sum merge reads each power value
// exactly once.
__global__ void __launch_bounds__(256) mel_kernel(float* __restrict__ out) {
    const int b = blockIdx.y;
    const int t = blockIdx.x * blockDim.x + threadIdx.x;
    float localmax = -3.0e38f;
    if (t < NFRAMES) {
        const float* pw = g_power + (size_t)b * NFRAMES + t;   // [f][global frame]
        float* op = out + (size_t)b * NMELS * NFRAMES + t;
        float s0 = 0.0f, s1 = 0.0f;
        int f = 0;
        for (int c = 0; c < NMELS; ++c) {
            while (f < NFREQ && __ldg(&g_idx[f]) == c) {
                float p = pw[(size_t)f * NFRTOT];
                s0 = fmaf(__ldg(&g_w0[f]), p, s0);
                s1 = fmaf(__ldg(&g_w1[f]), p, s1);
                ++f;
            }
            float lm = log10f(fmaxf(s0, 1e-10f));
            op[(size_t)c * NFRAMES] = lm;
            localmax = fmaxf(localmax, lm);
            s0 = s1;
            s1 = 0.0f;
        }
    }
#pragma unroll
    for (int o = 16; o; o >>= 1)
        localmax = fmaxf(localmax, __shfl_xor_sync(0xffffffffu, localmax, o));
    if ((threadIdx.x & 31) == 0) atomicMax(&g_max[b], f2ord(localmax));
}

// ---------------- finalize: floor at max-8, normalize ---------------------------
__global__ void __launch_bounds__(256) fin_kernel(float* __restrict__ out) {
    const int b = blockIdx.y;
    const float floorv = ord2f(g_max[b]) - 8.0f;
    const size_t idx = (size_t)blockIdx.x * blockDim.x + threadIdx.x;
    const size_t per = (size_t)NMELS * NFRAMES / 4;
    if (idx < per) {
        float4* p = reinterpret_cast<float4*>(out + (size_t)b * NMELS * NFRAMES) + idx;
        float4 v = *p;
        v.x = (fmaxf(v.x, floorv) + 4.0f) * 0.25f;
        v.y = (fmaxf(v.y, floorv) + 4.0f) * 0.25f;
        v.z = (fmaxf(v.z, floorv) + 4.0f) * 0.25f;
        v.w = (fmaxf(v.w, floorv) + 4.0f) * 0.25f;
        *p = v;
    }
}

// ---------------- launch --------------------------------------------------------
extern "C" void kernel_launch(void* const* d_in, const int* in_sizes, int n_in,
                              void* d_out, int out_size) {
    const float* audio = (const float*)d_in[0];
    const float* cosk  = (const float*)d_in[1];
    const float* sink  = (const float*)d_in[2];
    const float* fb    = (const float*)d_in[3];
    float* out = (float*)d_out;

    cudaFuncSetAttribute(stft_mma_kernel, cudaFuncAttributeMaxDynamicSharedMemorySize, SMEMSZ);

    prep_kernel<<<2048, 256>>>(audio, cosk, sink, fb);

    dim3 gs(NNT, 4);                               // (750, 4)
    stft_mma_kernel<<<gs, 256, SMEMSZ>>>();

    dim3 gm((NFRAMES + 255) / 256, BATCH);
    mel_kernel<<<gm, 256>>>(out);

    dim3 gf((NMELS * NFRAMES / 4 + 255) / 256, BATCH);
    fin_kernel<<<gf, 256>>>(out);
}

// round 8
// speedup vs baseline: 3.6418x; 1.0195x over previous
#include <cuda_runtime.h>
#include <cuda_fp16.h>
#include <cstdint>

#define BATCH   32
#define CHUNK   480000
#define NFFT    400
#define HOP     160
#define NMELS   128
#define NFREQ   201
#define NFRAMES 3000
#define NFRTOT  (BATCH * NFRAMES)   // 96000
#define MROWS   402                 // 201 freqs x (cos,sin)
#define MPAD    512                 // table padded to 4 tiles of 128
#define KTOT    400
#define KC      80
#define NCHUNK  (KTOT / KC)         // 5
#define NT      128                 // frames per block
#define NNT     (NFRTOT / NT)       // 750
#define ASTR    176                 // smem row stride bytes (80 fp16 = 160B + 16 pad)
#define ABYTES  (128 * ASTR)        // 22528 per tile
#define BUFB    (2 * ABYTES)        // one stage (A + B)
#define SMEMSZ  (2 * BUFB)          // 90112 (double buffered)

// ---------------- device scratch ------------------------------------------------
__device__ __align__(16) __half g_powh[(size_t)NFREQ * NFRTOT];   // fp16 power, 38.5 MB
__device__ __align__(16) __half g_ah[MPAD * KTOT];                // fp16 DFT table [512][400]
__device__ __align__(16) __half g_xh[(size_t)BATCH * CHUNK];      // fp16 audio, 30 MB
__device__ unsigned g_max[BATCH];
__device__ int   g_idx[NFREQ];    // first mel bin with nonzero weight at freq f
__device__ float g_w0[NFREQ];     // weight into bin idx
__device__ float g_w1[NFREQ];     // weight into bin idx+1

// ---------------- helpers -------------------------------------------------------
__device__ __forceinline__ uint32_t smem_u32(const void* p) {
    uint32_t a;
    asm("{ .reg .u64 t; cvta.to.shared.u64 t, %1; cvt.u32.u64 %0, t; }" : "=r"(a) : "l"(p));
    return a;
}
__device__ __forceinline__ void cp16(uint32_t saddr, const void* gaddr) {
    asm volatile("cp.async.cg.shared.global [%0], [%1], 16;" :: "r"(saddr), "l"(gaddr) : "memory");
}
__device__ __forceinline__ void ldsm_x4(uint32_t& r0, uint32_t& r1, uint32_t& r2, uint32_t& r3,
                                        uint32_t addr) {
    asm volatile("ldmatrix.sync.aligned.m8n8.x4.shared.b16 {%0,%1,%2,%3}, [%4];"
                 : "=r"(r0), "=r"(r1), "=r"(r2), "=r"(r3) : "r"(addr));
}
__device__ __forceinline__ void mma16816(float* d, const uint32_t* a, uint32_t b0, uint32_t b1) {
    asm volatile("mma.sync.aligned.m16n8k16.row.col.f32.f16.f16.f32 "
                 "{%0,%1,%2,%3}, {%4,%5,%6,%7}, {%8,%9}, {%0,%1,%2,%3};"
                 : "+f"(d[0]), "+f"(d[1]), "+f"(d[2]), "+f"(d[3])
                 : "r"(a[0]), "r"(a[1]), "r"(a[2]), "r"(a[3]), "r"(b0), "r"(b1));
}
__device__ __forceinline__ unsigned f2ord(float f) {
    unsigned u = __float_as_uint(f);
    return (u & 0x80000000u) ? ~u : (u | 0x80000000u);
}
__device__ __forceinline__ float ord2f(unsigned u) {
    return __uint_as_float((u & 0x80000000u) ? (u & 0x7fffffffu) : ~u);
}

// ---------------- prep: fp16 A table, fp16 audio, mel bin map, maxes ------------
__global__ void prep_kernel(const float* __restrict__ audio,
                            const float* __restrict__ cosk,
                            const float* __restrict__ sink,
                            const float* __restrict__ fb) {
    const int idx = blockIdx.x * blockDim.x + threadIdx.x;
    const int stride = gridDim.x * blockDim.x;

    // audio -> fp16 (vectorized by 4)
    const int n4 = BATCH * CHUNK / 4;
    for (int i = idx; i < n4; i += stride) {
        float4 x = reinterpret_cast<const float4*>(audio)[i];
        __half2 h0 = __floats2half2_rn(x.x, x.y);
        __half2 h1 = __floats2half2_rn(x.z, x.w);
        reinterpret_cast<__half2*>(g_xh)[2 * i]     = h0;
        reinterpret_cast<__half2*>(g_xh)[2 * i + 1] = h1;
    }
    // A table: row R = 2f + (0=cos,1=sin), col K
    const int total = MPAD * KTOT;
    for (int e = idx; e < total; e += stride) {
        int R = e / KTOT;
        int K = e - R * KTOT;
        float v = 0.0f;
        if (R < MROWS) {
            int f = R >> 1;
            v = (R & 1) ? sink[f * NFFT + K] : cosk[f * NFFT + K];
        }
        g_ah[e] = __float2half_rn(v);
    }
    // per-freq mel map: each fft bin hits at most 2 adjacent mel filters
    if (idx < NFREQ) {
        int m0 = -1;
        float w0 = 0.0f, w1 = 0.0f;
        for (int m = 0; m < NMELS; ++m) {
            float w = fb[m * NFREQ + idx];
            if (w > 0.0f) {
                if (m0 < 0) { m0 = m; w0 = w; }
                else if (m == m0 + 1) { w1 = w; }
            }
        }
        if (m0 < 0) { m0 = 0; w0 = 0.0f; w1 = 0.0f; }
        g_idx[idx] = m0;
        g_w0[idx] = w0;
        g_w1[idx] = w1;
    }
    if (idx < BATCH) g_max[idx] = f2ord(-3.0e38f);
}

// ---------------- STFT power via single-pass fp16 mma.sync ----------------------
// Templated on MI (warp M-extent in 16-row units):
//   MI=4: full tiles, grid (750, 3), warp tile 64M x 32N, rows 0..383.
//   MI=1: edge tile,  grid (750, 1), warp tile 16M x 32N, rows 384..415 (>= 402 real).
// All 8 warps active in both variants.
struct LoadCtx {
    const __half* gA;
    const __half* xp;
    int sbase;
    uint32_t dA;
    uint32_t dB;
};

__device__ __forceinline__ void issue_loads(const LoadCtx& L, char* smem, int c, int buf) {
    char* dA = smem + buf * BUFB + L.dA;
    char* dB = smem + buf * BUFB + L.dB;
    const __half* gA = L.gA + c * KC;
#pragma unroll
    for (int q = 0; q < 5; ++q)
        cp16(smem_u32(dA + 16 * q), gA + 8 * q);
    const int s0 = L.sbase + c * KC;
    if (s0 >= 0 && s0 + 40 <= CHUNK) {
        const __half* gB = L.xp + s0;
#pragma unroll
        for (int q = 0; q < 5; ++q)
            cp16(smem_u32(dB + 16 * q), gB + 8 * q);
    } else {
        __half* hB = reinterpret_cast<__half*>(dB);
#pragma unroll
        for (int q = 0; q < 40; ++q) {
            int s = s0 + q;
            if (s < 0) s = -s;
            if (s >= CHUNK) s = 2 * CHUNK - 2 - s;
            hB[q] = L.xp[s];
        }
    }
}

template <int MI>
__global__ void __launch_bounds__(256, 2) stft_mma_kernel(int mtile0) {
    extern __shared__ __align__(128) char smem[];
    const int tid = threadIdx.x;
    const int lane = tid & 31;
    const int warp = tid >> 5;
    const int wm = warp >> 2;        // 0..1
    const int wn = warp & 3;         // 0..3
    const int ntile = blockIdx.x;
    const int mtile = mtile0 + blockIdx.y;

    const int brow = tid >> 1;
    const int bhalf = tid & 1;
    const int frame = ntile * NT + brow;
    const int bb = frame / NFRAMES;
    const int bt = frame - bb * NFRAMES;

    LoadCtx L;
    L.xp = g_xh + (size_t)bb * CHUNK;
    L.sbase = bt * HOP - 200 + bhalf * 40;
    L.gA = g_ah + (size_t)(mtile * 128 + brow) * KTOT + bhalf * 40;
    L.dA = (uint32_t)(brow * ASTR + bhalf * 80);
    L.dB = L.dA + ABYTES;

    const uint32_t sbase32 = smem_u32(smem);
    const uint32_t aAddrOff = (uint32_t)((wm * 16 * MI + (lane & 15)) * ASTR + ((lane >> 4) << 4));
    const uint32_t bAddrOff = (uint32_t)((wn * 32 + (lane & 7) + ((lane >> 4) << 3)) * ASTR
                                         + (((lane >> 3) & 1) << 4));

    float acc[MI][4][4];
#pragma unroll
    for (int mi = 0; mi < MI; ++mi)
#pragma unroll
        for (int ni = 0; ni < 4; ++ni)
#pragma unroll
            for (int q = 0; q < 4; ++q) acc[mi][ni][q] = 0.0f;

    issue_loads(L, smem, 0, 0);
    asm volatile("cp.async.commit_group;" ::: "memory");

#pragma unroll
    for (int c = 0; c < NCHUNK; ++c) {
        if (c + 1 < NCHUNK) {
            issue_loads(L, smem, c + 1, (c + 1) & 1);
            asm volatile("cp.async.commit_group;" ::: "memory");
            asm volatile("cp.async.wait_group 1;" ::: "memory");
        } else {
            asm volatile("cp.async.wait_group 0;" ::: "memory");
        }
        __syncthreads();

        const uint32_t aA = sbase32 + (uint32_t)((c & 1) * BUFB);
        const uint32_t aB = aA + ABYTES;
#pragma unroll
        for (int ks = 0; ks < 5; ++ks) {
            const uint32_t kb = (uint32_t)(ks * 32);
            uint32_t ah[MI][4], bq[4][2];
#pragma unroll
            for (int mi = 0; mi < MI; ++mi)
                ldsm_x4(ah[mi][0], ah[mi][1], ah[mi][2], ah[mi][3],
                        aA + aAddrOff + (uint32_t)(mi * 16 * ASTR) + kb);
#pragma unroll
            for (int ni2 = 0; ni2 < 2; ++ni2)
                ldsm_x4(bq[2 * ni2][0], bq[2 * ni2][1], bq[2 * ni2 + 1][0], bq[2 * ni2 + 1][1],
                        aB + bAddrOff + (uint32_t)(ni2 * 16 * ASTR) + kb);
#pragma unroll
            for (int mi = 0; mi < MI; ++mi)
#pragma unroll
                for (int ni = 0; ni < 4; ++ni)
                    mma16816(acc[mi][ni], ah[mi], bq[ni][0], bq[ni][1]);
        }
        __syncthreads();
    }

    // ---- epilogue: power = re^2 + im^2 (row pairs are lane^4), fp16 stores ------
    const int r = lane >> 2;
    const bool evenr = (r & 1) == 0;
    const int Rw = mtile * 128 + wm * 16 * MI;
#pragma unroll
    for (int mi = 0; mi < MI; ++mi) {
#pragma unroll
        for (int ni = 0; ni < 4; ++ni) {
            float p0 = acc[mi][ni][0] * acc[mi][ni][0];
            float p1 = acc[mi][ni][1] * acc[mi][ni][1];
            float p2 = acc[mi][ni][2] * acc[mi][ni][2];
            float p3 = acc[mi][ni][3] * acc[mi][ni][3];
            p0 += __shfl_xor_sync(0xffffffffu, p0, 4);
            p1 += __shfl_xor_sync(0xffffffffu, p1, 4);
            p2 += __shfl_xor_sync(0xffffffffu, p2, 4);
            p3 += __shfl_xor_sync(0xffffffffu, p3, 4);
            if (evenr) {
                const int fr = ntile * NT + wn * 32 + ni * 8 + 2 * (lane & 3);
                const int R0 = Rw + mi * 16 + r;
                if (R0 < MROWS) {
                    __half2* dst = reinterpret_cast<__half2*>(g_powh + (size_t)(R0 >> 1) * NFRTOT + fr);
                    *dst = __floats2half2_rn(p0, p1);
                }
                const int R1 = R0 + 8;
                if (R1 < MROWS) {
                    __half2* dst = reinterpret_cast<__half2*>(g_powh + (size_t)(R1 >> 1) * NFRTOT + fr);
                    *dst = __floats2half2_rn(p2, p3);
                }
            }
        }
    }
}

// ---------------- mel: streaming 2-bin merge + log10 + per-batch max ------------
__global__ void __launch_bounds__(256) mel_kernel(float* __restrict__ out) {
    const int b = blockIdx.y;
    const int t = blockIdx.x * blockDim.x + threadIdx.x;
    float localmax = -3.0e38f;
    if (t < NFRAMES) {
        const __half* pw = g_powh + (size_t)b * NFRAMES + t;   // [f][global frame]
        float* op = out + (size_t)b * NMELS * NFRAMES + t;
        float s0 = 0.0f, s1 = 0.0f;
        int f = 0;
        for (int c = 0; c < NMELS; ++c) {
            while (f < NFREQ && __ldg(&g_idx[f]) == c) {
                float p = __half2float(pw[(size_t)f * NFRTOT]);
                s0 = fmaf(__ldg(&g_w0[f]), p, s0);
                s1 = fmaf(__ldg(&g_w1[f]), p, s1);
                ++f;
            }
            float lm = log10f(fmaxf(s0, 1e-10f));
            op[(size_t)c * NFRAMES] = lm;
            localmax = fmaxf(localmax, lm);
            s0 = s1;
            s1 = 0.0f;
        }
    }
#pragma unroll
    for (int o = 16; o; o >>= 1)
        localmax = fmaxf(localmax, __shfl_xor_sync(0xffffffffu, localmax, o));
    if ((threadIdx.x & 31) == 0) atomicMax(&g_max[b], f2ord(localmax));
}

// ---------------- finalize: floor at max-8, normalize (2 float4 / thread) -------
__global__ void __launch_bounds__(256) fin_kernel(float* __restrict__ out) {
    const int b = blockIdx.y;
    const float floorv = ord2f(g_max[b]) - 8.0f;
    const size_t base = 2 * ((size_t)blockIdx.x * blockDim.x + threadIdx.x);
    const size_t per = (size_t)NMELS * NFRAMES / 4;   // 96000 float4s
    float4* pb = reinterpret_cast<float4*>(out + (size_t)b * NMELS * NFRAMES);
#pragma unroll
    for (int j = 0; j < 2; ++j) {
        const size_t idx = base + j;
        if (idx < per) {
            float4 v = pb[idx];
            v.x = (fmaxf(v.x, floorv) + 4.0f) * 0.25f;
            v.y = (fmaxf(v.y, floorv) + 4.0f) * 0.25f;
            v.z = (fmaxf(v.z, floorv) + 4.0f) * 0.25f;
            v.w = (fmaxf(v.w, floorv) + 4.0f) * 0.25f;
            pb[idx] = v;
        }
    }
}

// ---------------- launch --------------------------------------------------------
extern "C" void kernel_launch(void* const* d_in, const int* in_sizes, int n_in,
                              void* d_out, int out_size) {
    const float* audio = (const float*)d_in[0];
    const float* cosk  = (const float*)d_in[1];
    const float* sink  = (const float*)d_in[2];
    const float* fb    = (const float*)d_in[3];
    float* out = (float*)d_out;

    cudaFuncSetAttribute(stft_mma_kernel<4>, cudaFuncAttributeMaxDynamicSharedMemorySize, SMEMSZ);
    cudaFuncSetAttribute(stft_mma_kernel<1>, cudaFuncAttributeMaxDynamicSharedMemorySize, SMEMSZ);

    prep_kernel<<<2048, 256>>>(audio, cosk, sink, fb);

    stft_mma_kernel<4><<<dim3(NNT, 3), 256, SMEMSZ>>>(0);   // rows 0..383
    stft_mma_kernel<1><<<dim3(NNT, 1), 256, SMEMSZ>>>(3);   // rows 384..415 (402 real)

    dim3 gm((NFRAMES + 255) / 256, BATCH);
    mel_kernel<<<gm, 256>>>(out);

    dim3 gf((NMELS * NFRAMES / 8 + 255) / 256, BATCH);
    fin_kernel<<<gf, 256>>>(out);
}

// round 9
// speedup vs baseline: 3.8277x; 1.0511x over previous
#include <cuda_runtime.h>
#include <cuda_fp16.h>
#include <cstdint>

#define BATCH   32
#define CHUNK   480000
#define NFFT    400
#define HOP     160
#define NMELS   128
#define NFREQ   201
#define NFRAMES 3000
#define NFRTOT  (BATCH * NFRAMES)   // 96000
#define MROWS   402                 // 201 freqs x (cos,sin)
#define MPAD    512                 // table padded to 4 tiles of 128
#define KTOT    400
#define KC      80
#define NCHUNK  (KTOT / KC)         // 5
#define NT      128                 // frames per block
#define NNT     (NFRTOT / NT)       // 750
#define ASTR    176                 // smem row stride bytes (80 fp16 = 160B + 16 pad)
#define ABYTES  (128 * ASTR)        // 22528 per tile
#define BUFB    (2 * ABYTES)        // one stage (A + B)
#define SMEMSZ  (2 * BUFB)          // 90112 (double buffered)

// ---------------- device scratch ------------------------------------------------
__device__ __align__(16) __half g_powh[(size_t)NFREQ * NFRTOT];   // fp16 power, 38.5 MB
__device__ __align__(16) __half g_ah[MPAD * KTOT];                // fp16 DFT table [512][400]
__device__ __align__(16) __half g_xh[(size_t)BATCH * CHUNK];      // fp16 audio, 30 MB
__device__ unsigned g_max[BATCH];
__device__ int g_flo[NMELS];      // first nonzero freq of mel bin m
__device__ int g_fhi[NMELS];      // one past last nonzero freq

// ---------------- helpers -------------------------------------------------------
__device__ __forceinline__ uint32_t smem_u32(const void* p) {
    uint32_t a;
    asm("{ .reg .u64 t; cvta.to.shared.u64 t, %1; cvt.u32.u64 %0, t; }" : "=r"(a) : "l"(p));
    return a;
}
__device__ __forceinline__ void cp16(uint32_t saddr, const void* gaddr) {
    asm volatile("cp.async.cg.shared.global [%0], [%1], 16;" :: "r"(saddr), "l"(gaddr) : "memory");
}
__device__ __forceinline__ void ldsm_x4(uint32_t& r0, uint32_t& r1, uint32_t& r2, uint32_t& r3,
                                        uint32_t addr) {
    asm volatile("ldmatrix.sync.aligned.m8n8.x4.shared.b16 {%0,%1,%2,%3}, [%4];"
                 : "=r"(r0), "=r"(r1), "=r"(r2), "=r"(r3) : "r"(addr));
}
__device__ __forceinline__ void mma16816(float* d, const uint32_t* a, uint32_t b0, uint32_t b1) {
    asm volatile("mma.sync.aligned.m16n8k16.row.col.f32.f16.f16.f32 "
                 "{%0,%1,%2,%3}, {%4,%5,%6,%7}, {%8,%9}, {%0,%1,%2,%3};"
                 : "+f"(d[0]), "+f"(d[1]), "+f"(d[2]), "+f"(d[3])
                 : "r"(a[0]), "r"(a[1]), "r"(a[2]), "r"(a[3]), "r"(b0), "r"(b1));
}
__device__ __forceinline__ unsigned f2ord(float f) {
    unsigned u = __float_as_uint(f);
    return (u & 0x80000000u) ? ~u : (u | 0x80000000u);
}
__device__ __forceinline__ float ord2f(unsigned u) {
    return __uint_as_float((u & 0x80000000u) ? (u & 0x7fffffffu) : ~u);
}

// ---------------- prep: fp16 A table, fp16 audio, mel ranges, maxes -------------
__global__ void prep_kernel(const float* __restrict__ audio,
                            const float* __restrict__ cosk,
                            const float* __restrict__ sink,
                            const float* __restrict__ fb) {
    const int idx = blockIdx.x * blockDim.x + threadIdx.x;
    const int stride = gridDim.x * blockDim.x;

    // audio -> fp16 (vectorized by 4)
    const int n4 = BATCH * CHUNK / 4;
    for (int i = idx; i < n4; i += stride) {
        float4 x = reinterpret_cast<const float4*>(audio)[i];
        __half2 h0 = __floats2half2_rn(x.x, x.y);
        __half2 h1 = __floats2half2_rn(x.z, x.w);
        reinterpret_cast<__half2*>(g_xh)[2 * i]     = h0;
        reinterpret_cast<__half2*>(g_xh)[2 * i + 1] = h1;
    }
    // A table: row R = 2f + (0=cos,1=sin), col K
    const int total = MPAD * KTOT;
    for (int e = idx; e < total; e += stride) {
        int R = e / KTOT;
        int K = e - R * KTOT;
        float v = 0.0f;
        if (R < MROWS) {
            int f = R >> 1;
            v = (R & 1) ? sink[f * NFFT + K] : cosk[f * NFFT + K];
        }
        g_ah[e] = __float2half_rn(v);
    }
    // per-mel-bin nonzero freq range
    if (idx < NMELS) {
        int lo = NFREQ, hi = 0;
        for (int f = 0; f < NFREQ; ++f) {
            if (fb[idx * NFREQ + f] != 0.0f) { if (f < lo) lo = f; hi = f + 1; }
        }
        if (lo >= hi) { lo = 0; hi = 0; }
        g_flo[idx] = lo;
        g_fhi[idx] = hi;
    }
    if (idx < BATCH) g_max[idx] = f2ord(-3.0e38f);
}

// ---------------- STFT power via single-pass fp16 mma.sync ----------------------
// Templated on MI (warp M-extent in 16-row units):
//   MI=4: full tiles, grid (750, 3), warp tile 64M x 32N, rows 0..383.
//   MI=1: edge tile,  grid (750, 1), warp tile 16M x 32N, rows 384..415 (>= 402 real).
struct LoadCtx {
    const __half* gA;
    const __half* xp;
    int sbase;
    uint32_t dA;
    uint32_t dB;
};

__device__ __forceinline__ void issue_loads(const LoadCtx& L, char* smem, int c, int buf) {
    char* dA = smem + buf * BUFB + L.dA;
    char* dB = smem + buf * BUFB + L.dB;
    const __half* gA = L.gA + c * KC;
#pragma unroll
    for (int q = 0; q < 5; ++q)
        cp16(smem_u32(dA + 16 * q), gA + 8 * q);
    const int s0 = L.sbase + c * KC;
    if (s0 >= 0 && s0 + 40 <= CHUNK) {
        const __half* gB = L.xp + s0;
#pragma unroll
        for (int q = 0; q < 5; ++q)
            cp16(smem_u32(dB + 16 * q), gB + 8 * q);
    } else {
        __half* hB = reinterpret_cast<__half*>(dB);
#pragma unroll
        for (int q = 0; q < 40; ++q) {
            int s = s0 + q;
            if (s < 0) s = -s;
            if (s >= CHUNK) s = 2 * CHUNK - 2 - s;
            hB[q] = L.xp[s];
        }
    }
}

template <int MI>
__global__ void __launch_bounds__(256, 2) stft_mma_kernel(int mtile0) {
    extern __shared__ __align__(128) char smem[];
    const int tid = threadIdx.x;
    const int lane = tid & 31;
    const int warp = tid >> 5;
    const int wm = warp >> 2;        // 0..1
    const int wn = warp & 3;         // 0..3
    const int ntile = blockIdx.x;
    const int mtile = mtile0 + blockIdx.y;

    const int brow = tid >> 1;
    const int bhalf = tid & 1;
    const int frame = ntile * NT + brow;
    const int bb = frame / NFRAMES;
    const int bt = frame - bb * NFRAMES;

    LoadCtx L;
    L.xp = g_xh + (size_t)bb * CHUNK;
    L.sbase = bt * HOP - 200 + bhalf * 40;
    L.gA = g_ah + (size_t)(mtile * 128 + brow) * KTOT + bhalf * 40;
    L.dA = (uint32_t)(brow * ASTR + bhalf * 80);
    L.dB = L.dA + ABYTES;

    const uint32_t sbase32 = smem_u32(smem);
    const uint32_t aAddrOff = (uint32_t)((wm * 16 * MI + (lane & 15)) * ASTR + ((lane >> 4) << 4));
    const uint32_t bAddrOff = (uint32_t)((wn * 32 + (lane & 7) + ((lane >> 4) << 3)) * ASTR
                                         + (((lane >> 3) & 1) << 4));

    float acc[MI][4][4];
#pragma unroll
    for (int mi = 0; mi < MI; ++mi)
#pragma unroll
        for (int ni = 0; ni < 4; ++ni)
#pragma unroll
            for (int q = 0; q < 4; ++q) acc[mi][ni][q] = 0.0f;

    issue_loads(L, smem, 0, 0);
    asm volatile("cp.async.commit_group;" ::: "memory");

#pragma unroll
    for (int c = 0; c < NCHUNK; ++c) {
        if (c + 1 < NCHUNK) {
            issue_loads(L, smem, c + 1, (c + 1) & 1);
            asm volatile("cp.async.commit_group;" ::: "memory");
            asm volatile("cp.async.wait_group 1;" ::: "memory");
        } else {
            asm volatile("cp.async.wait_group 0;" ::: "memory");
        }
        __syncthreads();

        const uint32_t aA = sbase32 + (uint32_t)((c & 1) * BUFB);
        const uint32_t aB = aA + ABYTES;
#pragma unroll
        for (int ks = 0; ks < 5; ++ks) {
            const uint32_t kb = (uint32_t)(ks * 32);
            uint32_t ah[MI][4], bq[4][2];
#pragma unroll
            for (int mi = 0; mi < MI; ++mi)
                ldsm_x4(ah[mi][0], ah[mi][1], ah[mi][2], ah[mi][3],
                        aA + aAddrOff + (uint32_t)(mi * 16 * ASTR) + kb);
#pragma unroll
            for (int ni2 = 0; ni2 < 2; ++ni2)
                ldsm_x4(bq[2 * ni2][0], bq[2 * ni2][1], bq[2 * ni2 + 1][0], bq[2 * ni2 + 1][1],
                        aB + bAddrOff + (uint32_t)(ni2 * 16 * ASTR) + kb);
#pragma unroll
            for (int mi = 0; mi < MI; ++mi)
#pragma unroll
                for (int ni = 0; ni < 4; ++ni)
                    mma16816(acc[mi][ni], ah[mi], bq[ni][0], bq[ni][1]);
        }
        __syncthreads();
    }

    // ---- epilogue: power = re^2 + im^2 (row pairs are lane^4), fp16 stores ------
    const int r = lane >> 2;
    const bool evenr = (r & 1) == 0;
    const int Rw = mtile * 128 + wm * 16 * MI;
#pragma unroll
    for (int mi = 0; mi < MI; ++mi) {
#pragma unroll
        for (int ni = 0; ni < 4; ++ni) {
            float p0 = acc[mi][ni][0] * acc[mi][ni][0];
            float p1 = acc[mi][ni][1] * acc[mi][ni][1];
            float p2 = acc[mi][ni][2] * acc[mi][ni][2];
            float p3 = acc[mi][ni][3] * acc[mi][ni][3];
            p0 += __shfl_xor_sync(0xffffffffu, p0, 4);
            p1 += __shfl_xor_sync(0xffffffffu, p1, 4);
            p2 += __shfl_xor_sync(0xffffffffu, p2, 4);
            p3 += __shfl_xor_sync(0xffffffffu, p3, 4);
            if (evenr) {
                const int fr = ntile * NT + wn * 32 + ni * 8 + 2 * (lane & 3);
                const int R0 = Rw + mi * 16 + r;
                if (R0 < MROWS) {
                    __half2* dst = reinterpret_cast<__half2*>(g_powh + (size_t)(R0 >> 1) * NFRTOT + fr);
                    *dst = __floats2half2_rn(p0, p1);
                }
                const int R1 = R0 + 8;
                if (R1 < MROWS) {
                    __half2* dst = reinterpret_cast<__half2*>(g_powh + (size_t)(R1 >> 1) * NFRTOT + fr);
                    *dst = __floats2half2_rn(p2, p3);
                }
            }
        }
    }
}

// ---------------- mel: one thread per (batch, mel, frame) -----------------------
// grid (ceil(3000/256), 128, 32). Bin span is block-uniform (m = blockIdx.y), so
// the loop has zero divergence; fb reads are block-uniform (const-cache broadcast);
// power reads are fully coalesced across t.
__global__ void __launch_bounds__(256) mel_kernel(const float* __restrict__ fb,
                                                  float* __restrict__ out) {
    const int t = blockIdx.x * blockDim.x + threadIdx.x;
    const int m = blockIdx.y;
    const int b = blockIdx.z;
    float lm = -3.0e38f;
    if (t < NFRAMES) {
        const int lo = g_flo[m];
        const int hi = g_fhi[m];
        const __half* pw = g_powh + (size_t)b * NFRAMES + t;
        float acc = 0.0f;
        for (int f = lo; f < hi; ++f)
            acc = fmaf(__ldg(&fb[m * NFREQ + f]), __half2float(pw[(size_t)f * NFRTOT]), acc);
        lm = log10f(fmaxf(acc, 1e-10f));
        out[((size_t)b * NMELS + m) * NFRAMES + t] = lm;
    }
    // block-wide max -> one atomic per block
    __shared__ float wmax[8];
#pragma unroll
    for (int o = 16; o; o >>= 1)
        lm = fmaxf(lm, __shfl_xor_sync(0xffffffffu, lm, o));
    if ((threadIdx.x & 31) == 0) wmax[threadIdx.x >> 5] = lm;
    __syncthreads();
    if (threadIdx.x < 8) {
        float v = wmax[threadIdx.x];
#pragma unroll
        for (int o = 4; o; o >>= 1)
            v = fmaxf(v, __shfl_xor_sync(0xffu, v, o));
        if (threadIdx.x == 0) atomicMax(&g_max[b], f2ord(v));
    }
}

// ---------------- finalize: floor at max-8, normalize (2 float4 / thread) -------
__global__ void __launch_bounds__(256) fin_kernel(float* __restrict__ out) {
    const int b = blockIdx.y;
    const float floorv = ord2f(g_max[b]) - 8.0f;
    const size_t base = 2 * ((size_t)blockIdx.x * blockDim.x + threadIdx.x);
    const size_t per = (size_t)NMELS * NFRAMES / 4;   // 96000 float4s
    float4* pb = reinterpret_cast<float4*>(out + (size_t)b * NMELS * NFRAMES);
#pragma unroll
    for (int j = 0; j < 2; ++j) {
        const size_t idx = base + j;
        if (idx < per) {
            float4 v = pb[idx];
            v.x = (fmaxf(v.x, floorv) + 4.0f) * 0.25f;
            v.y = (fmaxf(v.y, floorv) + 4.0f) * 0.25f;
            v.z = (fmaxf(v.z, floorv) + 4.0f) * 0.25f;
            v.w = (fmaxf(v.w, floorv) + 4.0f) * 0.25f;
            pb[idx] = v;
        }
    }
}

// ---------------- launch --------------------------------------------------------
extern "C" void kernel_launch(void* const* d_in, const int* in_sizes, int n_in,
                              void* d_out, int out_size) {
    const float* audio = (const float*)d_in[0];
    const float* cosk  = (const float*)d_in[1];
    const float* sink  = (const float*)d_in[2];
    const float* fb    = (const float*)d_in[3];
    float* out = (float*)d_out;

    cudaFuncSetAttribute(stft_mma_kernel<4>, cudaFuncAttributeMaxDynamicSharedMemorySize, SMEMSZ);
    cudaFuncSetAttribute(stft_mma_kernel<1>, cudaFuncAttributeMaxDynamicSharedMemorySize, SMEMSZ);

    prep_kernel<<<2048, 256>>>(audio, cosk, sink, fb);

    stft_mma_kernel<4><<<dim3(NNT, 3), 256, SMEMSZ>>>(0);   // rows 0..383
    stft_mma_kernel<1><<<dim3(NNT, 1), 256, SMEMSZ>>>(3);   // rows 384..415 (402 real)

    dim3 gm((NFRAMES + 255) / 256, NMELS, BATCH);           // (12, 128, 32)
    mel_kernel<<<gm, 256>>>(fb, out);

    dim3 gf((NMELS * NFRAMES / 8 + 255) / 256, BATCH);
    fin_kernel<<<gf, 256>>>(out);
}

// round 10
// speedup vs baseline: 4.3391x; 1.1336x over previous
#include <cuda_runtime.h>
#include <cuda_fp16.h>
#include <cstdint>

#define BATCH   32
#define CHUNK   480000
#define NFFT    400
#define HOP     160
#define NMELS   128
#define NFREQ   201
#define NFRAMES 3000
#define NFRTOT  (BATCH * NFRAMES)   // 96000
#define MROWS   402                 // 201 freqs x (cos,sin)
#define MPAD    512                 // table padded to 4 tiles of 128
#define KTOT    400
#define KC      80
#define NCHUNK  (KTOT / KC)         // 5
#define NT      128                 // frames per block
#define NNT     (NFRTOT / NT)       // 750
#define ASTR    176                 // smem row stride bytes (80 fp16 = 160B + 16 pad)
#define ABYTES  (128 * ASTR)        // 22528 per tile
#define BUFB    (2 * ABYTES)        // one stage (A + B)
#define SMEMSZ  (2 * BUFB)          // 90112 (double buffered)

// ---------------- device scratch ------------------------------------------------
__device__ __align__(16) __half g_powh[(size_t)NFREQ * NFRTOT];   // fp16 power, 38.5 MB
__device__ __align__(16) __half g_ah[MPAD * KTOT];                // fp16 DFT table [512][400]
__device__ __align__(16) __half g_xh[(size_t)BATCH * CHUNK];      // fp16 audio, 30 MB
__device__ unsigned g_max[BATCH];
__device__ int g_flo[NMELS];      // first nonzero freq of mel bin m
__device__ int g_fhi[NMELS];      // one past last nonzero freq

// ---------------- helpers -------------------------------------------------------
__device__ __forceinline__ uint32_t smem_u32(const void* p) {
    uint32_t a;
    asm("{ .reg .u64 t; cvta.to.shared.u64 t, %1; cvt.u32.u64 %0, t; }" : "=r"(a) : "l"(p));
    return a;
}
__device__ __forceinline__ void cp16(uint32_t saddr, const void* gaddr) {
    asm volatile("cp.async.cg.shared.global [%0], [%1], 16;" :: "r"(saddr), "l"(gaddr) : "memory");
}
__device__ __forceinline__ void ldsm_x4(uint32_t& r0, uint32_t& r1, uint32_t& r2, uint32_t& r3,
                                        uint32_t addr) {
    asm volatile("ldmatrix.sync.aligned.m8n8.x4.shared.b16 {%0,%1,%2,%3}, [%4];"
                 : "=r"(r0), "=r"(r1), "=r"(r2), "=r"(r3) : "r"(addr));
}
__device__ __forceinline__ void mma16816(float* d, const uint32_t* a, uint32_t b0, uint32_t b1) {
    asm volatile("mma.sync.aligned.m16n8k16.row.col.f32.f16.f16.f32 "
                 "{%0,%1,%2,%3}, {%4,%5,%6,%7}, {%8,%9}, {%0,%1,%2,%3};"
                 : "+f"(d[0]), "+f"(d[1]), "+f"(d[2]), "+f"(d[3])
                 : "r"(a[0]), "r"(a[1]), "r"(a[2]), "r"(a[3]), "r"(b0), "r"(b1));
}
__device__ __forceinline__ unsigned f2ord(float f) {
    unsigned u = __float_as_uint(f);
    return (u & 0x80000000u) ? ~u : (u | 0x80000000u);
}
__device__ __forceinline__ float ord2f(unsigned u) {
    return __uint_as_float((u & 0x80000000u) ? (u & 0x7fffffffu) : ~u);
}

// ---------------- prep: fp16 A table, fp16 audio, mel ranges, maxes -------------
__global__ void prep_kernel(const float* __restrict__ audio,
                            const float* __restrict__ cosk,
                            const float* __restrict__ sink,
                            const float* __restrict__ fb) {
    const int idx = blockIdx.x * blockDim.x + threadIdx.x;
    const int stride = gridDim.x * blockDim.x;

    // audio -> fp16 (vectorized by 4)
    const int n4 = BATCH * CHUNK / 4;
    for (int i = idx; i < n4; i += stride) {
        float4 x = reinterpret_cast<const float4*>(audio)[i];
        __half2 h0 = __floats2half2_rn(x.x, x.y);
        __half2 h1 = __floats2half2_rn(x.z, x.w);
        reinterpret_cast<__half2*>(g_xh)[2 * i]     = h0;
        reinterpret_cast<__half2*>(g_xh)[2 * i + 1] = h1;
    }
    // A table: row R = 2f + (0=cos,1=sin), col K
    const int total = MPAD * KTOT;
    for (int e = idx; e < total; e += stride) {
        int R = e / KTOT;
        int K = e - R * KTOT;
        float v = 0.0f;
        if (R < MROWS) {
            int f = R >> 1;
            v = (R & 1) ? sink[f * NFFT + K] : cosk[f * NFFT + K];
        }
        g_ah[e] = __float2half_rn(v);
    }
    // per-mel-bin nonzero freq range
    if (idx < NMELS) {
        int lo = NFREQ, hi = 0;
        for (int f = 0; f < NFREQ; ++f) {
            if (fb[idx * NFREQ + f] != 0.0f) { if (f < lo) lo = f; hi = f + 1; }
        }
        if (lo >= hi) { lo = 0; hi = 0; }
        g_flo[idx] = lo;
        g_fhi[idx] = hi;
    }
    if (idx < BATCH) g_max[idx] = f2ord(-3.0e38f);
}

// ---------------- STFT power via single-pass fp16 mma.sync ----------------------
// Templated on MI (warp M-extent in 16-row units):
//   MI=4: full tiles, grid (750, 3), warp tile 64M x 32N, rows 0..383.
//   MI=1: edge tile,  grid (750, 1), warp tile 16M x 32N, rows 384..415 (>= 402 real).
struct LoadCtx {
    const __half* gA;
    const __half* xp;
    int sbase;
    uint32_t dA;
    uint32_t dB;
};

__device__ __forceinline__ void issue_loads(const LoadCtx& L, char* smem, int c, int buf) {
    char* dA = smem + buf * BUFB + L.dA;
    char* dB = smem + buf * BUFB + L.dB;
    const __half* gA = L.gA + c * KC;
#pragma unroll
    for (int q = 0; q < 5; ++q)
        cp16(smem_u32(dA + 16 * q), gA + 8 * q);
    const int s0 = L.sbase + c * KC;
    if (s0 >= 0 && s0 + 40 <= CHUNK) {
        const __half* gB = L.xp + s0;
#pragma unroll
        for (int q = 0; q < 5; ++q)
            cp16(smem_u32(dB + 16 * q), gB + 8 * q);
    } else {
        __half* hB = reinterpret_cast<__half*>(dB);
#pragma unroll
        for (int q = 0; q < 40; ++q) {
            int s = s0 + q;
            if (s < 0) s = -s;
            if (s >= CHUNK) s = 2 * CHUNK - 2 - s;
            hB[q] = L.xp[s];
        }
    }
}

template <int MI>
__global__ void __launch_bounds__(256, 2) stft_mma_kernel(int mtile0) {
    extern __shared__ __align__(128) char smem[];
    const int tid = threadIdx.x;
    const int lane = tid & 31;
    const int warp = tid >> 5;
    const int wm = warp >> 2;        // 0..1
    const int wn = warp & 3;         // 0..3
    const int ntile = blockIdx.x;
    const int mtile = mtile0 + blockIdx.y;

    const int brow = tid >> 1;
    const int bhalf = tid & 1;
    const int frame = ntile * NT + brow;
    const int bb = frame / NFRAMES;
    const int bt = frame - bb * NFRAMES;

    LoadCtx L;
    L.xp = g_xh + (size_t)bb * CHUNK;
    L.sbase = bt * HOP - 200 + bhalf * 40;
    L.gA = g_ah + (size_t)(mtile * 128 + brow) * KTOT + bhalf * 40;
    L.dA = (uint32_t)(brow * ASTR + bhalf * 80);
    L.dB = L.dA + ABYTES;

    const uint32_t sbase32 = smem_u32(smem);
    const uint32_t aAddrOff = (uint32_t)((wm * 16 * MI + (lane & 15)) * ASTR + ((lane >> 4) << 4));
    const uint32_t bAddrOff = (uint32_t)((wn * 32 + (lane & 7) + ((lane >> 4) << 3)) * ASTR
                                         + (((lane >> 3) & 1) << 4));

    float acc[MI][4][4];
#pragma unroll
    for (int mi = 0; mi < MI; ++mi)
#pragma unroll
        for (int ni = 0; ni < 4; ++ni)
#pragma unroll
            for (int q = 0; q < 4; ++q) acc[mi][ni][q] = 0.0f;

    issue_loads(L, smem, 0, 0);
    asm volatile("cp.async.commit_group;" ::: "memory");

#pragma unroll
    for (int c = 0; c < NCHUNK; ++c) {
        if (c + 1 < NCHUNK) {
            issue_loads(L, smem, c + 1, (c + 1) & 1);
            asm volatile("cp.async.commit_group;" ::: "memory");
            asm volatile("cp.async.wait_group 1;" ::: "memory");
        } else {
            asm volatile("cp.async.wait_group 0;" ::: "memory");
        }
        __syncthreads();

        const uint32_t aA = sbase32 + (uint32_t)((c & 1) * BUFB);
        const uint32_t aB = aA + ABYTES;
#pragma unroll
        for (int ks = 0; ks < 5; ++ks) {
            const uint32_t kb = (uint32_t)(ks * 32);
            uint32_t ah[MI][4], bq[4][2];
#pragma unroll
            for (int mi = 0; mi < MI; ++mi)
                ldsm_x4(ah[mi][0], ah[mi][1], ah[mi][2], ah[mi][3],
                        aA + aAddrOff + (uint32_t)(mi * 16 * ASTR) + kb);
#pragma unroll
            for (int ni2 = 0; ni2 < 2; ++ni2)
                ldsm_x4(bq[2 * ni2][0], bq[2 * ni2][1], bq[2 * ni2 + 1][0], bq[2 * ni2 + 1][1],
                        aB + bAddrOff + (uint32_t)(ni2 * 16 * ASTR) + kb);
#pragma unroll
            for (int mi = 0; mi < MI; ++mi)
#pragma unroll
                for (int ni = 0; ni < 4; ++ni)
                    mma16816(acc[mi][ni], ah[mi], bq[ni][0], bq[ni][1]);
        }
        __syncthreads();
    }

    // ---- epilogue: power = re^2 + im^2 (row pairs are lane^4), fp16 stores ------
    const int r = lane >> 2;
    const bool evenr = (r & 1) == 0;
    const int Rw = mtile * 128 + wm * 16 * MI;
#pragma unroll
    for (int mi = 0; mi < MI; ++mi) {
#pragma unroll
        for (int ni = 0; ni < 4; ++ni) {
            float p0 = acc[mi][ni][0] * acc[mi][ni][0];
            float p1 = acc[mi][ni][1] * acc[mi][ni][1];
            float p2 = acc[mi][ni][2] * acc[mi][ni][2];
            float p3 = acc[mi][ni][3] * acc[mi][ni][3];
            p0 += __shfl_xor_sync(0xffffffffu, p0, 4);
            p1 += __shfl_xor_sync(0xffffffffu, p1, 4);
            p2 += __shfl_xor_sync(0xffffffffu, p2, 4);
            p3 += __shfl_xor_sync(0xffffffffu, p3, 4);
            if (evenr) {
                const int fr = ntile * NT + wn * 32 + ni * 8 + 2 * (lane & 3);
                const int R0 = Rw + mi * 16 + r;
                if (R0 < MROWS) {
                    __half2* dst = reinterpret_cast<__half2*>(g_powh + (size_t)(R0 >> 1) * NFRTOT + fr);
                    *dst = __floats2half2_rn(p0, p1);
                }
                const int R1 = R0 + 8;
                if (R1 < MROWS) {
                    __half2* dst = reinterpret_cast<__half2*>(g_powh + (size_t)(R1 >> 1) * NFRTOT + fr);
                    *dst = __floats2half2_rn(p2, p3);
                }
            }
        }
    }
}

// ---------------- mel: one thread per (batch, mel, 4 frames) --------------------
// grid (3, 128, 32), 256 threads; q indexes groups of 4 frames (750 per (m,b)).
// Per f: one 8B load (4 fp16), uniform weight, 4 FMAs, pointer increment.
__global__ void __launch_bounds__(256) mel_kernel(const float* __restrict__ fb,
                                                  float* __restrict__ out) {
    const int q = blockIdx.x * blockDim.x + threadIdx.x;   // 0..767 (750 active)
    const int m = blockIdx.y;
    const int b = blockIdx.z;
    float lmax = -3.0e38f;
    if (q < NFRAMES / 4) {
        const int t0 = q * 4;
        const int lo = g_flo[m];
        const int hi = g_fhi[m];
        const float* fbm = fb + m * NFREQ;
        const uint2* p = reinterpret_cast<const uint2*>(
            g_powh + (size_t)lo * NFRTOT + (size_t)b * NFRAMES + t0);
        const size_t stride8 = NFRTOT / 4;   // uint2 units per freq row
        float4 acc = make_float4(0.f, 0.f, 0.f, 0.f);
        for (int f = lo; f < hi; ++f) {
            const float w = __ldg(&fbm[f]);
            uint2 raw = *p;
            p += stride8;
            const float2 v01 = __half22float2(*reinterpret_cast<const __half2*>(&raw.x));
            const float2 v23 = __half22float2(*reinterpret_cast<const __half2*>(&raw.y));
            acc.x = fmaf(w, v01.x, acc.x);
            acc.y = fmaf(w, v01.y, acc.y);
            acc.z = fmaf(w, v23.x, acc.z);
            acc.w = fmaf(w, v23.y, acc.w);
        }
        float4 r;
        r.x = log10f(fmaxf(acc.x, 1e-10f));
        r.y = log10f(fmaxf(acc.y, 1e-10f));
        r.z = log10f(fmaxf(acc.z, 1e-10f));
        r.w = log10f(fmaxf(acc.w, 1e-10f));
        *reinterpret_cast<float4*>(out + ((size_t)b * NMELS + m) * NFRAMES + t0) = r;
        lmax = fmaxf(fmaxf(r.x, r.y), fmaxf(r.z, r.w));
    }
    // block-wide max -> one atomic per block
    __shared__ float wmax[8];
#pragma unroll
    for (int o = 16; o; o >>= 1)
        lmax = fmaxf(lmax, __shfl_xor_sync(0xffffffffu, lmax, o));
    if ((threadIdx.x & 31) == 0) wmax[threadIdx.x >> 5] = lmax;
    __syncthreads();
    if (threadIdx.x < 8) {
        float v = wmax[threadIdx.x];
#pragma unroll
        for (int o = 4; o; o >>= 1)
            v = fmaxf(v, __shfl_xor_sync(0xffu, v, o));
        if (threadIdx.x == 0) atomicMax(&g_max[b], f2ord(v));
    }
}

// ---------------- finalize: floor at max-8, normalize (2 float4 / thread) -------
__global__ void __launch_bounds__(256) fin_kernel(float* __restrict__ out) {
    const int b = blockIdx.y;
    const float floorv = ord2f(g_max[b]) - 8.0f;
    const size_t base = 2 * ((size_t)blockIdx.x * blockDim.x + threadIdx.x);
    const size_t per = (size_t)NMELS * NFRAMES / 4;   // 96000 float4s
    float4* pb = reinterpret_cast<float4*>(out + (size_t)b * NMELS * NFRAMES);
#pragma unroll
    for (int j = 0; j < 2; ++j) {
        const size_t idx = base + j;
        if (idx < per) {
            float4 v = pb[idx];
            v.x = (fmaxf(v.x, floorv) + 4.0f) * 0.25f;
            v.y = (fmaxf(v.y, floorv) + 4.0f) * 0.25f;
            v.z = (fmaxf(v.z, floorv) + 4.0f) * 0.25f;
            v.w = (fmaxf(v.w, floorv) + 4.0f) * 0.25f;
            pb[idx] = v;
        }
    }
}

// ---------------- launch --------------------------------------------------------
extern "C" void kernel_launch(void* const* d_in, const int* in_sizes, int n_in,
                              void* d_out, int out_size) {
    const float* audio = (const float*)d_in[0];
    const float* cosk  = (const float*)d_in[1];
    const float* sink  = (const float*)d_in[2];
    const float* fb    = (const float*)d_in[3];
    float* out = (float*)d_out;

    cudaFuncSetAttribute(stft_mma_kernel<4>, cudaFuncAttributeMaxDynamicSharedMemorySize, SMEMSZ);
    cudaFuncSetAttribute(stft_mma_kernel<1>, cudaFuncAttributeMaxDynamicSharedMemorySize, SMEMSZ);

    prep_kernel<<<2048, 256>>>(audio, cosk, sink, fb);

    stft_mma_kernel<4><<<dim3(NNT, 3), 256, SMEMSZ>>>(0);   // rows 0..383
    stft_mma_kernel<1><<<dim3(NNT, 1), 256, SMEMSZ>>>(3);   // rows 384..415 (402 real)

    dim3 gm((NFRAMES / 4 + 255) / 256, NMELS, BATCH);       // (3, 128, 32)
    mel_kernel<<<gm, 256>>>(fb, out);

    dim3 gf((NMELS * NFRAMES / 8 + 255) / 256, BATCH);
    fin_kernel<<<gf, 256>>>(out);
}

// round 11
// speedup vs baseline: 4.6876x; 1.0803x over previous
#include <cuda_runtime.h>
#include <cuda_fp16.h>
#include <cstdint>
#include <math.h>

#define BATCH   32
#define CHUNK   480000
#define NFFT    400
#define HOP     160
#define NMELS   128
#define NFREQ   201
#define NFRAMES 3000
#define NFRTOT  (BATCH * NFRAMES)   // 96000
#define KP      208                 // padded half-K (200 real + 8 zero)
#define NT      128                 // frames per block
#define NNT     (NFRTOT / NT)       // 750
#define ASTR    176                 // smem row stride bytes (max chunk 80 fp16 + 16 pad)
#define ABYTES  (128 * ASTR)        // 22528 per tile
#define BUFB    (2 * ABYTES)        // one stage (A + B)
#define SMEMSZ  (2 * BUFB)          // 90112 (double buffered)
#define MLIM_E  202                 // even-class real rows (k=0,2,...,200)
#define MLIM_O  200                 // odd-class real rows  (k=1,3,...,199)

// ---------------- device scratch ------------------------------------------------
__device__ __align__(16) __half g_powh[(size_t)NFREQ * NFRTOT];   // fp16 power, 38.5 MB
__device__ __align__(16) __half g_u[(size_t)NFRTOT * KP];         // even-class B, 40 MB
__device__ __align__(16) __half g_v[(size_t)NFRTOT * KP];         // odd-class B, 40 MB
__device__ __align__(16) __half g_ae[256 * KP];                   // even basis [256][208]
__device__ __align__(16) __half g_ao[256 * KP];                   // odd basis
__device__ unsigned g_max[BATCH];
__device__ int g_flo[NMELS];
__device__ int g_fhi[NMELS];

// ---------------- helpers -------------------------------------------------------
__device__ __forceinline__ uint32_t smem_u32(const void* p) {
    uint32_t a;
    asm("{ .reg .u64 t; cvta.to.shared.u64 t, %1; cvt.u32.u64 %0, t; }" : "=r"(a) : "l"(p));
    return a;
}
__device__ __forceinline__ void cp16(uint32_t saddr, const void* gaddr) {
    asm volatile("cp.async.cg.shared.global [%0], [%1], 16;" :: "r"(saddr), "l"(gaddr) : "memory");
}
__device__ __forceinline__ void ldsm_x4(uint32_t& r0, uint32_t& r1, uint32_t& r2, uint32_t& r3,
                                        uint32_t addr) {
    asm volatile("ldmatrix.sync.aligned.m8n8.x4.shared.b16 {%0,%1,%2,%3}, [%4];"
                 : "=r"(r0), "=r"(r1), "=r"(r2), "=r"(r3) : "r"(addr));
}
__device__ __forceinline__ void mma16816(float* d, const uint32_t* a, uint32_t b0, uint32_t b1) {
    asm volatile("mma.sync.aligned.m16n8k16.row.col.f32.f16.f16.f32 "
                 "{%0,%1,%2,%3}, {%4,%5,%6,%7}, {%8,%9}, {%0,%1,%2,%3};"
                 : "+f"(d[0]), "+f"(d[1]), "+f"(d[2]), "+f"(d[3])
                 : "r"(a[0]), "r"(a[1]), "r"(a[2]), "r"(a[3]), "r"(b0), "r"(b1));
}
__device__ __forceinline__ unsigned f2ord(float f) {
    unsigned u = __float_as_uint(f);
    return (u & 0x80000000u) ? ~u : (u | 0x80000000u);
}
__device__ __forceinline__ float ord2f(unsigned u) {
    return __uint_as_float((u & 0x80000000u) ? (u & 0x7fffffffu) : ~u);
}

// ---------------- prep: basis tables (fp64), mel ranges, maxes ------------------
__global__ void prep_kernel(const float* __restrict__ fb) {
    const int idx = blockIdx.x * blockDim.x + threadIdx.x;
    const int stride = gridDim.x * blockDim.x;
    const int total = 2 * 256 * KP;
    for (int e = idx; e < total; e += stride) {
        int tab = e / (256 * KP);
        int rem = e - tab * (256 * KP);
        int R = rem / KP;
        int r = rem - R * KP;
        int mlim = tab ? MLIM_O : MLIM_E;
        __half v = __float2half_rn(0.0f);
        if (R < mlim && r < 200) {
            int k = 2 * (R >> 1) + tab;
            double ang = (2.0 * M_PI / 400.0) * (double)k * (double)r;
            double bv = (R & 1) ? -sin(ang) : cos(ang);
            v = __float2half_rn((float)bv);
        }
        (tab ? g_ao : g_ae)[R * KP + r] = v;
    }
    if (idx < NMELS) {
        int lo = NFREQ, hi = 0;
        for (int f = 0; f < NFREQ; ++f) {
            if (fb[idx * NFREQ + f] != 0.0f) { if (f < lo) lo = f; hi = f + 1; }
        }
        if (lo >= hi) { lo = 0; hi = 0; }
        g_flo[idx] = lo;
        g_fhi[idx] = hi;
    }
    if (idx < BATCH) g_max[idx] = f2ord(-3.0e38f);
}

// ---------------- prep: radix-2 folded inputs u,v (window from cosk row 0) ------
__global__ void __launch_bounds__(256) prep_uv(const float* __restrict__ audio,
                                               const float* __restrict__ cosk) {
    const int t = blockIdx.x;
    const int b = blockIdx.y;
    const int r = threadIdx.x;
    if (r >= KP) return;
    const size_t o = ((size_t)b * NFRAMES + t) * KP + r;
    if (r >= 200) {
        g_u[o] = __float2half_rn(0.0f);
        g_v[o] = __float2half_rn(0.0f);
        return;
    }
    int s = t * HOP - 200 + r;               // reflect low end only
    if (s < 0) s = -s;
    int s2 = t * HOP + r;                    // reflect high end only
    if (s2 >= CHUNK) s2 = 2 * CHUNK - 2 - s2;
    const float x1 = audio[(size_t)b * CHUNK + s];
    const float x2 = audio[(size_t)b * CHUNK + s2];
    const float wa = cosk[r];                // cos_kernel[k=0][n] = window[n]
    const float wb = cosk[200 + r];
    g_u[o] = __float2half_rn(fmaf(wa, x1,  wb * x2));
    g_v[o] = __float2half_rn(fmaf(wa, x1, -wb * x2));
}

// ---------------- STFT power via radix-2 fp16 mma.sync --------------------------
// grid (750, 2): y = class (0 even/u, 1 odd/v). Templated MI:
//   MI=4: rows [aRow, aRow+128)   MI=3: rows [aRow, aRow+96)  (aRow=128 edge)
// K = 208 in chunks {80, 64, 64}; B rows are global frames (u/v prepadded).
__device__ __constant__ int c_CO[3]  = {0, 80, 144};   // chunk elem offsets
__device__ __constant__ int c_CLb[3] = {160, 128, 128};// chunk bytes

template <int MI>
__global__ void __launch_bounds__(256, 2) stft_mma_kernel(int aRow) {
    extern __shared__ __align__(128) char smem[];
    const int tid = threadIdx.x;
    const int lane = tid & 31;
    const int warp = tid >> 5;
    const int wm = warp >> 2;        // 0..1
    const int wn = warp & 3;         // 0..3
    const int ntile = blockIdx.x;
    const int cls = blockIdx.y;
    const int mlim = cls ? MLIM_O : MLIM_E;
    const __half* Atab = cls ? g_ao : g_ae;
    const __half* Btab = cls ? g_v : g_u;

    const int brow = tid >> 1;       // 0..127
    const int bhalf = tid & 1;
    const size_t gArow = (size_t)(aRow + brow) * KP;
    const size_t gBrow = (size_t)(ntile * NT + brow) * KP;
    const uint32_t dBase = (uint32_t)(brow * ASTR);

    const uint32_t sbase32 = smem_u32(smem);
    const uint32_t aAddrOff = (uint32_t)((wm * 16 * MI + (lane & 15)) * ASTR + ((lane >> 4) << 4));
    const uint32_t bAddrOff = (uint32_t)((wn * 32 + (lane & 7) + ((lane >> 4) << 3)) * ASTR
                                         + (((lane >> 3) & 1) << 4));

    float acc[MI][4][4];
#pragma unroll
    for (int mi = 0; mi < MI; ++mi)
#pragma unroll
        for (int ni = 0; ni < 4; ++ni)
#pragma unroll
            for (int q = 0; q < 4; ++q) acc[mi][ni][q] = 0.0f;

    // chunk constants (compile-time via unrolled loops)
    const int CO[3] = {0, 80, 144};
    const int CLB[3] = {160, 128, 128};   // bytes per row per chunk
    const int KSN[3] = {5, 4, 4};         // k16 steps (= 16B granules per half)

    // issue chunk 0
    {
        const int c = 0;
        char* dA = smem + dBase + bhalf * (CLB[c] / 2);
        char* dB = dA + ABYTES;
        const __half* gA = Atab + gArow + CO[c] + bhalf * (CLB[c] / 4);
        const __half* gB = Btab + gBrow + CO[c] + bhalf * (CLB[c] / 4);
#pragma unroll
        for (int q = 0; q < 5; ++q) {
            cp16(smem_u32(dA + 16 * q), gA + 8 * q);
            cp16(smem_u32(dB + 16 * q), gB + 8 * q);
        }
        asm volatile("cp.async.commit_group;" ::: "memory");
    }

#pragma unroll
    for (int c = 0; c < 3; ++c) {
        if (c + 1 < 3) {
            const int cn = c + 1;
            char* dA = smem + ((cn & 1) * BUFB) + dBase + bhalf * (CLB[cn] / 2);
            char* dB = dA + ABYTES;
            const __half* gA = Atab + gArow + CO[cn] + bhalf * (CLB[cn] / 4);
            const __half* gB = Btab + gBrow + CO[cn] + bhalf * (CLB[cn] / 4);
#pragma unroll
            for (int q = 0; q < 4; ++q) {
                cp16(smem_u32(dA + 16 * q), gA + 8 * q);
                cp16(smem_u32(dB + 16 * q), gB + 8 * q);
            }
            asm volatile("cp.async.commit_group;" ::: "memory");
            asm volatile("cp.async.wait_group 1;" ::: "memory");
        } else {
            asm volatile("cp.async.wait_group 0;" ::: "memory");
        }
        __syncthreads();

        const uint32_t aA = sbase32 + (uint32_t)((c & 1) * BUFB);
        const uint32_t aB = aA + ABYTES;
#pragma unroll
        for (int ks = 0; ks < KSN[c]; ++ks) {
            const uint32_t kb = (uint32_t)(ks * 32);
            uint32_t ah[MI][4], bq[4][2];
#pragma unroll
            for (int mi = 0; mi < MI; ++mi)
                ldsm_x4(ah[mi][0], ah[mi][1], ah[mi][2], ah[mi][3],
                        aA + aAddrOff + (uint32_t)(mi * 16 * ASTR) + kb);
#pragma unroll
            for (int ni2 = 0; ni2 < 2; ++ni2)
                ldsm_x4(bq[2 * ni2][0], bq[2 * ni2][1], bq[2 * ni2 + 1][0], bq[2 * ni2 + 1][1],
                        aB + bAddrOff + (uint32_t)(ni2 * 16 * ASTR) + kb);
#pragma unroll
            for (int mi = 0; mi < MI; ++mi)
#pragma unroll
                for (int ni = 0; ni < 4; ++ni)
                    mma16816(acc[mi][ni], ah[mi], bq[ni][0], bq[ni][1]);
        }
        __syncthreads();
    }

    // ---- epilogue: power = re^2 + im^2 (row pairs are lane^4), fp16 stores ------
    const int r = lane >> 2;
    const bool evenr = (r & 1) == 0;
    const int Rbase = aRow + wm * 16 * MI;
#pragma unroll
    for (int mi = 0; mi < MI; ++mi) {
#pragma unroll
        for (int ni = 0; ni < 4; ++ni) {
            float p0 = acc[mi][ni][0] * acc[mi][ni][0];
            float p1 = acc[mi][ni][1] * acc[mi][ni][1];
            float p2 = acc[mi][ni][2] * acc[mi][ni][2];
            float p3 = acc[mi][ni][3] * acc[mi][ni][3];
            p0 += __shfl_xor_sync(0xffffffffu, p0, 4);
            p1 += __shfl_xor_sync(0xffffffffu, p1, 4);
            p2 += __shfl_xor_sync(0xffffffffu, p2, 4);
            p3 += __shfl_xor_sync(0xffffffffu, p3, 4);
            if (evenr) {
                const int fr = ntile * NT + wn * 32 + ni * 8 + 2 * (lane & 3);
                const int R0 = Rbase + mi * 16 + r;
                if (R0 < mlim) {
                    const int f = 2 * (R0 >> 1) + cls;
                    __half2* dst = reinterpret_cast<__half2*>(g_powh + (size_t)f * NFRTOT + fr);
                    *dst = __floats2half2_rn(p0, p1);
                }
                const int R1 = R0 + 8;
                if (R1 < mlim) {
                    const int f = 2 * (R1 >> 1) + cls;
                    __half2* dst = reinterpret_cast<__half2*>(g_powh + (size_t)f * NFRTOT + fr);
                    *dst = __floats2half2_rn(p2, p3);
                }
            }
        }
    }
}

// ---------------- mel: one thread per (batch, mel, 4 frames) --------------------
__global__ void __launch_bounds__(256) mel_kernel(const float* __restrict__ fb,
                                                  float* __restrict__ out) {
    const int q = blockIdx.x * blockDim.x + threadIdx.x;
    const int m = blockIdx.y;
    const int b = blockIdx.z;
    float lmax = -3.0e38f;
    if (q < NFRAMES / 4) {
        const int t0 = q * 4;
        const int lo = g_flo[m];
        const int hi = g_fhi[m];
        const float* fbm = fb + m * NFREQ;
        const uint2* p = reinterpret_cast<const uint2*>(
            g_powh + (size_t)lo * NFRTOT + (size_t)b * NFRAMES + t0);
        const size_t stride8 = NFRTOT / 4;
        float4 acc = make_float4(0.f, 0.f, 0.f, 0.f);
        for (int f = lo; f < hi; ++f) {
            const float w = __ldg(&fbm[f]);
            uint2 raw = *p;
            p += stride8;
            const float2 v01 = __half22float2(*reinterpret_cast<const __half2*>(&raw.x));
            const float2 v23 = __half22float2(*reinterpret_cast<const __half2*>(&raw.y));
            acc.x = fmaf(w, v01.x, acc.x);
            acc.y = fmaf(w, v01.y, acc.y);
            acc.z = fmaf(w, v23.x, acc.z);
            acc.w = fmaf(w, v23.y, acc.w);
        }
        float4 r;
        r.x = log10f(fmaxf(acc.x, 1e-10f));
        r.y = log10f(fmaxf(acc.y, 1e-10f));
        r.z = log10f(fmaxf(acc.z, 1e-10f));
        r.w = log10f(fmaxf(acc.w, 1e-10f));
        *reinterpret_cast<float4*>(out + ((size_t)b * NMELS + m) * NFRAMES + t0) = r;
        lmax = fmaxf(fmaxf(r.x, r.y), fmaxf(r.z, r.w));
    }
    __shared__ float wmax[8];
#pragma unroll
    for (int o = 16; o; o >>= 1)
        lmax = fmaxf(lmax, __shfl_xor_sync(0xffffffffu, lmax, o));
    if ((threadIdx.x & 31) == 0) wmax[threadIdx.x >> 5] = lmax;
    __syncthreads();
    if (threadIdx.x < 8) {
        float v = wmax[threadIdx.x];
#pragma unroll
        for (int o = 4; o; o >>= 1)
            v = fmaxf(v, __shfl_xor_sync(0xffu, v, o));
        if (threadIdx.x == 0) atomicMax(&g_max[b], f2ord(v));
    }
}

// ---------------- finalize: floor at max-8, normalize (2 float4 / thread) -------
__global__ void __launch_bounds__(256) fin_kernel(float* __restrict__ out) {
    const int b = blockIdx.y;
    const float floorv = ord2f(g_max[b]) - 8.0f;
    const size_t base = 2 * ((size_t)blockIdx.x * blockDim.x + threadIdx.x);
    const size_t per = (size_t)NMELS * NFRAMES / 4;
    float4* pb = reinterpret_cast<float4*>(out + (size_t)b * NMELS * NFRAMES);
#pragma unroll
    for (int j = 0; j < 2; ++j) {
        const size_t idx = base + j;
        if (idx < per) {
            float4 v = pb[idx];
            v.x = (fmaxf(v.x, floorv) + 4.0f) * 0.25f;
            v.y = (fmaxf(v.y, floorv) + 4.0f) * 0.25f;
            v.z = (fmaxf(v.z, floorv) + 4.0f) * 0.25f;
            v.w = (fmaxf(v.w, floorv) + 4.0f) * 0.25f;
            pb[idx] = v;
        }
    }
}

// ---------------- launch --------------------------------------------------------
extern "C" void kernel_launch(void* const* d_in, const int* in_sizes, int n_in,
                              void* d_out, int out_size) {
    const float* audio = (const float*)d_in[0];
    const float* cosk  = (const float*)d_in[1];
    const float* fb    = (const float*)d_in[3];
    float* out = (float*)d_out;

    cudaFuncSetAttribute(stft_mma_kernel<4>, cudaFuncAttributeMaxDynamicSharedMemorySize, SMEMSZ);
    cudaFuncSetAttribute(stft_mma_kernel<3>, cudaFuncAttributeMaxDynamicSharedMemorySize, SMEMSZ);

    prep_kernel<<<1024, 256>>>(fb);
    prep_uv<<<dim3(NFRAMES, BATCH), 256>>>(audio, cosk);

    stft_mma_kernel<4><<<dim3(NNT, 2), 256, SMEMSZ>>>(0);     // rows 0..127 per class
    stft_mma_kernel<3><<<dim3(NNT, 2), 256, SMEMSZ>>>(128);   // rows 128..223 per class

    dim3 gm((NFRAMES / 4 + 255) / 256, NMELS, BATCH);         // (3, 128, 32)
    mel_kernel<<<gm, 256>>>(fb, out);

    dim3 gf((NMELS * NFRAMES / 8 + 255) / 256, BATCH);
    fin_kernel<<<gf, 256>>>(out);
}

// round 12
// speedup vs baseline: 4.7991x; 1.0238x over previous
#include <cuda_runtime.h>
#include <cuda_fp16.h>
#include <cstdint>
#include <math.h>

#define BATCH   32
#define CHUNK   480000
#define NFFT    400
#define HOP     160
#define NMELS   128
#define NFREQ   201
#define NFRAMES 3000
#define NFRTOT  (BATCH * NFRAMES)   // 96000
#define KP      208                 // padded half-K (200 real + 8 zero)
#define NT      128                 // frames per block
#define NNT     (NFRTOT / NT)       // 750
#define ASTR    432                 // smem row stride bytes (208 fp16 = 416B + 16 pad)
#define ABYTES  (128 * ASTR)        // 55296 per tile
#define SMEMSZ  (2 * ABYTES)        // 110592 (A + B, single buffer, full K)
#define MLIM_E  202                 // even-class real rows (k=0,2,...,200)
#define MLIM_O  200                 // odd-class real rows  (k=1,3,...,199)
#define NKS     13                  // k16 steps (208 / 16)

// ---------------- device scratch ------------------------------------------------
__device__ __align__(16) __half g_powh[(size_t)NFREQ * NFRTOT];   // fp16 power, 38.5 MB
__device__ __align__(16) __half g_u[(size_t)NFRTOT * KP];         // even-class B, 40 MB
__device__ __align__(16) __half g_v[(size_t)NFRTOT * KP];         // odd-class B, 40 MB
__device__ __align__(16) __half g_ae[256 * KP];                   // even basis [256][208]
__device__ __align__(16) __half g_ao[256 * KP];                   // odd basis
__device__ unsigned g_max[BATCH];
__device__ int g_flo[NMELS];
__device__ int g_fhi[NMELS];

// ---------------- helpers -------------------------------------------------------
__device__ __forceinline__ uint32_t smem_u32(const void* p) {
    uint32_t a;
    asm("{ .reg .u64 t; cvta.to.shared.u64 t, %1; cvt.u32.u64 %0, t; }" : "=r"(a) : "l"(p));
    return a;
}
__device__ __forceinline__ void cp16(uint32_t saddr, const void* gaddr) {
    asm volatile("cp.async.cg.shared.global [%0], [%1], 16;" :: "r"(saddr), "l"(gaddr) : "memory");
}
__device__ __forceinline__ void ldsm_x4(uint32_t& r0, uint32_t& r1, uint32_t& r2, uint32_t& r3,
                                        uint32_t addr) {
    asm volatile("ldmatrix.sync.aligned.m8n8.x4.shared.b16 {%0,%1,%2,%3}, [%4];"
                 : "=r"(r0), "=r"(r1), "=r"(r2), "=r"(r3) : "r"(addr));
}
__device__ __forceinline__ void mma16816(float* d, const uint32_t* a, uint32_t b0, uint32_t b1) {
    asm volatile("mma.sync.aligned.m16n8k16.row.col.f32.f16.f16.f32 "
                 "{%0,%1,%2,%3}, {%4,%5,%6,%7}, {%8,%9}, {%0,%1,%2,%3};"
                 : "+f"(d[0]), "+f"(d[1]), "+f"(d[2]), "+f"(d[3])
                 : "r"(a[0]), "r"(a[1]), "r"(a[2]), "r"(a[3]), "r"(b0), "r"(b1));
}
__device__ __forceinline__ unsigned f2ord(float f) {
    unsigned u = __float_as_uint(f);
    return (u & 0x80000000u) ? ~u : (u | 0x80000000u);
}
__device__ __forceinline__ float ord2f(unsigned u) {
    return __uint_as_float((u & 0x80000000u) ? (u & 0x7fffffffu) : ~u);
}

// ---------------- prep: basis tables (fp64), mel ranges, maxes ------------------
__global__ void prep_kernel(const float* __restrict__ fb) {
    const int idx = blockIdx.x * blockDim.x + threadIdx.x;
    const int stride = gridDim.x * blockDim.x;
    const int total = 2 * 256 * KP;
    for (int e = idx; e < total; e += stride) {
        int tab = e / (256 * KP);
        int rem = e - tab * (256 * KP);
        int R = rem / KP;
        int r = rem - R * KP;
        int mlim = tab ? MLIM_O : MLIM_E;
        __half v = __float2half_rn(0.0f);
        if (R < mlim && r < 200) {
            int k = 2 * (R >> 1) + tab;
            double ang = (2.0 * M_PI / 400.0) * (double)k * (double)r;
            double bv = (R & 1) ? -sin(ang) : cos(ang);
            v = __float2half_rn((float)bv);
        }
        (tab ? g_ao : g_ae)[R * KP + r] = v;
    }
    if (idx < NMELS) {
        int lo = NFREQ, hi = 0;
        for (int f = 0; f < NFREQ; ++f) {
            if (fb[idx * NFREQ + f] != 0.0f) { if (f < lo) lo = f; hi = f + 1; }
        }
        if (lo >= hi) { lo = 0; hi = 0; }
        g_flo[idx] = lo;
        g_fhi[idx] = hi;
    }
    if (idx < BATCH) g_max[idx] = f2ord(-3.0e38f);
}

// ---------------- prep: radix-2 folded inputs u,v (window from cosk row 0) ------
__global__ void __launch_bounds__(256) prep_uv(const float* __restrict__ audio,
                                               const float* __restrict__ cosk) {
    const int t = blockIdx.x;
    const int b = blockIdx.y;
    const int r = threadIdx.x;
    if (r >= KP) return;
    const size_t o = ((size_t)b * NFRAMES + t) * KP + r;
    if (r >= 200) {
        g_u[o] = __float2half_rn(0.0f);
        g_v[o] = __float2half_rn(0.0f);
        return;
    }
    int s = t * HOP - 200 + r;               // reflect low end only
    if (s < 0) s = -s;
    int s2 = t * HOP + r;                    // reflect high end only
    if (s2 >= CHUNK) s2 = 2 * CHUNK - 2 - s2;
    const float x1 = audio[(size_t)b * CHUNK + s];
    const float x2 = audio[(size_t)b * CHUNK + s2];
    const float wa = cosk[r];                // cos_kernel[k=0][n] = window[n]
    const float wb = cosk[200 + r];
    g_u[o] = __float2half_rn(fmaf(wa, x1,  wb * x2));
    g_v[o] = __float2half_rn(fmaf(wa, x1, -wb * x2));
}

// ---------------- STFT power via radix-2 fp16 mma.sync (single-shot K) ----------
// grid (750, 2): y = class (0 even/u, 1 odd/v). Templated MI:
//   MI=4: rows [aRow, aRow+128)   MI=3: rows [aRow, aRow+96)  (aRow=128 edge)
// Whole K=208 loaded to smem in one burst; ONE sync; 13 uninterrupted k16 steps.
// Latency hiding via 2 resident blocks/SM (one loads while the other computes).
template <int MI>
__global__ void __launch_bounds__(256, 2) stft_mma_kernel(int aRow) {
    extern __shared__ __align__(128) char smem[];
    const int tid = threadIdx.x;
    const int lane = tid & 31;
    const int warp = tid >> 5;
    const int wm = warp >> 2;        // 0..1
    const int wn = warp & 3;         // 0..3
    const int ntile = blockIdx.x;
    const int cls = blockIdx.y;
    const int mlim = cls ? MLIM_O : MLIM_E;
    const __half* Atab = cls ? g_ao : g_ae;
    const __half* Btab = cls ? g_v : g_u;

    const int brow = tid >> 1;       // 0..127
    const int bhalf = tid & 1;       // 104-half slice (13 x 16B granules)

    // ---- one-shot load: whole 128x208 A and B tiles ----
    {
        char* dA = smem + brow * ASTR + bhalf * 208;
        char* dB = dA + ABYTES;
        const __half* gA = Atab + (size_t)(aRow + brow) * KP + bhalf * 104;
        const __half* gB = Btab + (size_t)(ntile * NT + brow) * KP + bhalf * 104;
#pragma unroll
        for (int q = 0; q < 13; ++q) {
            cp16(smem_u32(dA + 16 * q), gA + 8 * q);
            cp16(smem_u32(dB + 16 * q), gB + 8 * q);
        }
        asm volatile("cp.async.commit_group;" ::: "memory");
    }

    const uint32_t sbase32 = smem_u32(smem);
    const uint32_t aAddrOff = (uint32_t)((wm * 16 * MI + (lane & 15)) * ASTR + ((lane >> 4) << 4));
    const uint32_t bAddrOff = (uint32_t)((wn * 32 + (lane & 7) + ((lane >> 4) << 3)) * ASTR
                                         + (((lane >> 3) & 1) << 4));

    float acc[MI][4][4];
#pragma unroll
    for (int mi = 0; mi < MI; ++mi)
#pragma unroll
        for (int ni = 0; ni < 4; ++ni)
#pragma unroll
            for (int q = 0; q < 4; ++q) acc[mi][ni][q] = 0.0f;

    asm volatile("cp.async.wait_group 0;" ::: "memory");
    __syncthreads();

    const uint32_t aA = sbase32;
    const uint32_t aB = sbase32 + ABYTES;
#pragma unroll
    for (int ks = 0; ks < NKS; ++ks) {
        const uint32_t kb = (uint32_t)(ks * 32);
        uint32_t ah[MI][4], bq[4][2];
#pragma unroll
        for (int mi = 0; mi < MI; ++mi)
            ldsm_x4(ah[mi][0], ah[mi][1], ah[mi][2], ah[mi][3],
                    aA + aAddrOff + (uint32_t)(mi * 16 * ASTR) + kb);
#pragma unroll
        for (int ni2 = 0; ni2 < 2; ++ni2)
            ldsm_x4(bq[2 * ni2][0], bq[2 * ni2][1], bq[2 * ni2 + 1][0], bq[2 * ni2 + 1][1],
                    aB + bAddrOff + (uint32_t)(ni2 * 16 * ASTR) + kb);
#pragma unroll
        for (int mi = 0; mi < MI; ++mi)
#pragma unroll
            for (int ni = 0; ni < 4; ++ni)
                mma16816(acc[mi][ni], ah[mi], bq[ni][0], bq[ni][1]);
    }

    // ---- epilogue: power = re^2 + im^2 (row pairs are lane^4), fp16 stores ------
    const int r = lane >> 2;
    const bool evenr = (r & 1) == 0;
    const int Rbase = aRow + wm * 16 * MI;
#pragma unroll
    for (int mi = 0; mi < MI; ++mi) {
#pragma unroll
        for (int ni = 0; ni < 4; ++ni) {
            float p0 = acc[mi][ni][0] * acc[mi][ni][0];
            float p1 = acc[mi][ni][1] * acc[mi][ni][1];
            float p2 = acc[mi][ni][2] * acc[mi][ni][2];
            float p3 = acc[mi][ni][3] * acc[mi][ni][3];
            p0 += __shfl_xor_sync(0xffffffffu, p0, 4);
            p1 += __shfl_xor_sync(0xffffffffu, p1, 4);
            p2 += __shfl_xor_sync(0xffffffffu, p2, 4);
            p3 += __shfl_xor_sync(0xffffffffu, p3, 4);
            if (evenr) {
                const int fr = ntile * NT + wn * 32 + ni * 8 + 2 * (lane & 3);
                const int R0 = Rbase + mi * 16 + r;
                if (R0 < mlim) {
                    const int f = 2 * (R0 >> 1) + cls;
                    __half2* dst = reinterpret_cast<__half2*>(g_powh + (size_t)f * NFRTOT + fr);
                    *dst = __floats2half2_rn(p0, p1);
                }
                const int R1 = R0 + 8;
                if (R1 < mlim) {
                    const int f = 2 * (R1 >> 1) + cls;
                    __half2* dst = reinterpret_cast<__half2*>(g_powh + (size_t)f * NFRTOT + fr);
                    *dst = __floats2half2_rn(p2, p3);
                }
            }
        }
    }
}

// ---------------- mel: one thread per (batch, mel, 4 frames) --------------------
__global__ void __launch_bounds__(256) mel_kernel(const float* __restrict__ fb,
                                                  float* __restrict__ out) {
    const int q = blockIdx.x * blockDim.x + threadIdx.x;
    const int m = blockIdx.y;
    const int b = blockIdx.z;
    float lmax = -3.0e38f;
    if (q < NFRAMES / 4) {
        const int t0 = q * 4;
        const int lo = g_flo[m];
        const int hi = g_fhi[m];
        const float* fbm = fb + m * NFREQ;
        const uint2* p = reinterpret_cast<const uint2*>(
            g_powh + (size_t)lo * NFRTOT + (size_t)b * NFRAMES + t0);
        const size_t stride8 = NFRTOT / 4;
        float4 acc = make_float4(0.f, 0.f, 0.f, 0.f);
        for (int f = lo; f < hi; ++f) {
            const float w = __ldg(&fbm[f]);
            uint2 raw = *p;
            p += stride8;
            const float2 v01 = __half22float2(*reinterpret_cast<const __half2*>(&raw.x));
            const float2 v23 = __half22float2(*reinterpret_cast<const __half2*>(&raw.y));
            acc.x = fmaf(w, v01.x, acc.x);
            acc.y = fmaf(w, v01.y, acc.y);
            acc.z = fmaf(w, v23.x, acc.z);
            acc.w = fmaf(w, v23.y, acc.w);
        }
        float4 r;
        r.x = log10f(fmaxf(acc.x, 1e-10f));
        r.y = log10f(fmaxf(acc.y, 1e-10f));
        r.z = log10f(fmaxf(acc.z, 1e-10f));
        r.w = log10f(fmaxf(acc.w, 1e-10f));
        *reinterpret_cast<float4*>(out + ((size_t)b * NMELS + m) * NFRAMES + t0) = r;
        lmax = fmaxf(fmaxf(r.x, r.y), fmaxf(r.z, r.w));
    }
    __shared__ float wmax[8];
#pragma unroll
    for (int o = 16; o; o >>= 1)
        lmax = fmaxf(lmax, __shfl_xor_sync(0xffffffffu, lmax, o));
    if ((threadIdx.x & 31) == 0) wmax[threadIdx.x >> 5] = lmax;
    __syncthreads();
    if (threadIdx.x < 8) {
        float v = wmax[threadIdx.x];
#pragma unroll
        for (int o = 4; o; o >>= 1)
            v = fmaxf(v, __shfl_xor_sync(0xffu, v, o));
        if (threadIdx.x == 0) atomicMax(&g_max[b], f2ord(v));
    }
}

// ---------------- finalize: floor at max-8, normalize (2 float4 / thread) -------
__global__ void __launch_bounds__(256) fin_kernel(float* __restrict__ out) {
    const int b = blockIdx.y;
    const float floorv = ord2f(g_max[b]) - 8.0f;
    const size_t base = 2 * ((size_t)blockIdx.x * blockDim.x + threadIdx.x);
    const size_t per = (size_t)NMELS * NFRAMES / 4;
    float4* pb = reinterpret_cast<float4*>(out + (size_t)b * NMELS * NFRAMES);
#pragma unroll
    for (int j = 0; j < 2; ++j) {
        const size_t idx = base + j;
        if (idx < per) {
            float4 v = pb[idx];
            v.x = (fmaxf(v.x, floorv) + 4.0f) * 0.25f;
            v.y = (fmaxf(v.y, floorv) + 4.0f) * 0.25f;
            v.z = (fmaxf(v.z, floorv) + 4.0f) * 0.25f;
            v.w = (fmaxf(v.w, floorv) + 4.0f) * 0.25f;
            pb[idx] = v;
        }
    }
}

// ---------------- launch --------------------------------------------------------
extern "C" void kernel_launch(void* const* d_in, const int* in_sizes, int n_in,
                              void* d_out, int out_size) {
    const float* audio = (const float*)d_in[0];
    const float* cosk  = (const float*)d_in[1];
    const float* fb    = (const float*)d_in[3];
    float* out = (float*)d_out;

    cudaFuncSetAttribute(stft_mma_kernel<4>, cudaFuncAttributeMaxDynamicSharedMemorySize, SMEMSZ);
    cudaFuncSetAttribute(stft_mma_kernel<3>, cudaFuncAttributeMaxDynamicSharedMemorySize, SMEMSZ);

    prep_kernel<<<1024, 256>>>(fb);
    prep_uv<<<dim3(NFRAMES, BATCH), 256>>>(audio, cosk);

    stft_mma_kernel<4><<<dim3(NNT, 2), 256, SMEMSZ>>>(0);     // rows 0..127 per class
    stft_mma_kernel<3><<<dim3(NNT, 2), 256, SMEMSZ>>>(128);   // rows 128..223 per class

    dim3 gm((NFRAMES / 4 + 255) / 256, NMELS, BATCH);         // (3, 128, 32)
    mel_kernel<<<gm, 256>>>(fb, out);

    dim3 gf((NMELS * NFRAMES / 8 + 255) / 256, BATCH);
    fin_kernel<<<gf, 256>>>(out);
}

// round 13
// speedup vs baseline: 5.5928x; 1.1654x over previous
#include <cuda_runtime.h>
#include <cuda_fp16.h>
#include <cstdint>
#include <math.h>

#define BATCH   32
#define CHUNK   480000
#define NFFT    400
#define HOP     160
#define NMELS   128
#define NFREQ   201
#define NFRAMES 3000
#define NFRTOT  (BATCH * NFRAMES)   // 96000
#define KP      208                 // padded half-K (200 real + 8 zero)
#define NT      128                 // frames per B tile
#define NNT     (NFRTOT / NT)       // 750
#define ASTR    432                 // smem row stride bytes (208 fp16 = 416B + 16 pad)
#define MR      224                 // M rows per block (covers 202 real + pad)
#define A_BYTES (MR * ASTR)         // 96768
#define B_BYTES (128 * ASTR)        // 55296 per buffer
#define SMEMSZ  (A_BYTES + 2 * B_BYTES)   // 207360
#define MLIM_E  202                 // even-class real rows (k=0,2,...,200)
#define MLIM_O  200                 // odd-class real rows  (k=1,3,...,199)
#define NKS     13                  // k16 steps (208 / 16)
#define NSMB    148                 // grid x (persistent slots)

// ---------------- device scratch ------------------------------------------------
__device__ __align__(16) __half g_powh[(size_t)NFREQ * NFRTOT];   // fp16 power, 38.5 MB
__device__ __align__(16) __half g_u[(size_t)NFRTOT * KP];         // even-class B, 40 MB
__device__ __align__(16) __half g_v[(size_t)NFRTOT * KP];         // odd-class B, 40 MB
__device__ __align__(16) __half g_ae[256 * KP];                   // even basis
__device__ __align__(16) __half g_ao[256 * KP];                   // odd basis
__device__ unsigned g_max[BATCH];
__device__ int g_flo[NMELS];
__device__ int g_fhi[NMELS];

// ---------------- helpers -------------------------------------------------------
__device__ __forceinline__ uint32_t smem_u32(const void* p) {
    uint32_t a;
    asm("{ .reg .u64 t; cvta.to.shared.u64 t, %1; cvt.u32.u64 %0, t; }" : "=r"(a) : "l"(p));
    return a;
}
__device__ __forceinline__ void cp16(uint32_t saddr, const void* gaddr) {
    asm volatile("cp.async.cg.shared.global [%0], [%1], 16;" :: "r"(saddr), "l"(gaddr) : "memory");
}
__device__ __forceinline__ void ldsm_x4(uint32_t& r0, uint32_t& r1, uint32_t& r2, uint32_t& r3,
                                        uint32_t addr) {
    asm volatile("ldmatrix.sync.aligned.m8n8.x4.shared.b16 {%0,%1,%2,%3}, [%4];"
                 : "=r"(r0), "=r"(r1), "=r"(r2), "=r"(r3) : "r"(addr));
}
__device__ __forceinline__ void mma16816(float* d, const uint32_t* a, uint32_t b0, uint32_t b1) {
    asm volatile("mma.sync.aligned.m16n8k16.row.col.f32.f16.f16.f32 "
                 "{%0,%1,%2,%3}, {%4,%5,%6,%7}, {%8,%9}, {%0,%1,%2,%3};"
                 : "+f"(d[0]), "+f"(d[1]), "+f"(d[2]), "+f"(d[3])
                 : "r"(a[0]), "r"(a[1]), "r"(a[2]), "r"(a[3]), "r"(b0), "r"(b1));
}
__device__ __forceinline__ unsigned f2ord(float f) {
    unsigned u = __float_as_uint(f);
    return (u & 0x80000000u) ? ~u : (u | 0x80000000u);
}
__device__ __forceinline__ float ord2f(unsigned u) {
    return __uint_as_float((u & 0x80000000u) ? (u & 0x7fffffffu) : ~u);
}

// ---------------- prep: basis tables (fp64), mel ranges, maxes ------------------
__global__ void prep_kernel(const float* __restrict__ fb) {
    const int idx = blockIdx.x * blockDim.x + threadIdx.x;
    const int stride = gridDim.x * blockDim.x;
    const int total = 2 * 256 * KP;
    for (int e = idx; e < total; e += stride) {
        int tab = e / (256 * KP);
        int rem = e - tab * (256 * KP);
        int R = rem / KP;
        int r = rem - R * KP;
        int mlim = tab ? MLIM_O : MLIM_E;
        __half v = __float2half_rn(0.0f);
        if (R < mlim && r < 200) {
            int k = 2 * (R >> 1) + tab;
            double ang = (2.0 * M_PI / 400.0) * (double)k * (double)r;
            double bv = (R & 1) ? -sin(ang) : cos(ang);
            v = __float2half_rn((float)bv);
        }
        (tab ? g_ao : g_ae)[R * KP + r] = v;
    }
    if (idx < NMELS) {
        int lo = NFREQ, hi = 0;
        for (int f = 0; f < NFREQ; ++f) {
            if (fb[idx * NFREQ + f] != 0.0f) { if (f < lo) lo = f; hi = f + 1; }
        }
        if (lo >= hi) { lo = 0; hi = 0; }
        g_flo[idx] = lo;
        g_fhi[idx] = hi;
    }
    if (idx < BATCH) g_max[idx] = f2ord(-3.0e38f);
}

// ---------------- prep: radix-2 folded inputs u,v (window from cosk row 0) ------
__global__ void __launch_bounds__(256) prep_uv(const float* __restrict__ audio,
                                               const float* __restrict__ cosk) {
    const int t = blockIdx.x;
    const int b = blockIdx.y;
    const int r = threadIdx.x;
    if (r >= KP) return;
    const size_t o = ((size_t)b * NFRAMES + t) * KP + r;
    if (r >= 200) {
        g_u[o] = __float2half_rn(0.0f);
        g_v[o] = __float2half_rn(0.0f);
        return;
    }
    int s = t * HOP - 200 + r;
    if (s < 0) s = -s;
    int s2 = t * HOP + r;
    if (s2 >= CHUNK) s2 = 2 * CHUNK - 2 - s2;
    const float x1 = audio[(size_t)b * CHUNK + s];
    const float x2 = audio[(size_t)b * CHUNK + s2];
    const float wa = cosk[r];
    const float wb = cosk[200 + r];
    g_u[o] = __float2half_rn(fmaf(wa, x1,  wb * x2));
    g_v[o] = __float2half_rn(fmaf(wa, x1, -wb * x2));
}

// ---------------- STFT: persistent-A radix-2 fp16 mma.sync ----------------------
// grid (148, 2): y = class. Block loads its class's WHOLE A (224 x 208) once,
// then iterates ntiles = bx, bx+148, ..., double-buffering only B (55KB x2).
// Warp grid 2m x 4n; warp tile 112M x 32N (MI=7). One B load feeds 2912 HMMA.
__global__ void __launch_bounds__(256, 1) stft_mma_kernel() {
    extern __shared__ __align__(128) char smem[];
    const int tid = threadIdx.x;
    const int lane = tid & 31;
    const int warp = tid >> 5;
    const int wm = warp >> 2;        // 0..1
    const int wn = warp & 3;         // 0..3
    const int bx = blockIdx.x;
    const int cls = blockIdx.y;
    const int mlim = cls ? MLIM_O : MLIM_E;
    const __half* Atab = cls ? g_ao : g_ae;
    const __half* Btab = cls ? g_v : g_u;

    const int brow = tid >> 1;       // 0..127
    const int bhalf = tid & 1;       // 104-half slice (13 x 16B granules)
    const int nit = (NNT - bx + NSMB - 1) / NSMB;   // 5 or 6

    // ---- load A (once): 224 rows x 208 halves ----
#pragma unroll
    for (int j = 0; j < 2; ++j) {
        const int r = brow + 128 * j;
        if (r < MR) {
            char* dA = smem + r * ASTR + bhalf * 208;
            const __half* gA = Atab + (size_t)r * KP + bhalf * 104;
#pragma unroll
            for (int q = 0; q < 13; ++q)
                cp16(smem_u32(dA + 16 * q), gA + 8 * q);
        }
    }
    // ---- load B for first ntile into buffer 0 ----
    {
        char* dB = smem + A_BYTES + brow * ASTR + bhalf * 208;
        const __half* gB = Btab + (size_t)(bx * NT + brow) * KP + bhalf * 104;
#pragma unroll
        for (int q = 0; q < 13; ++q)
            cp16(smem_u32(dB + 16 * q), gB + 8 * q);
    }
    asm volatile("cp.async.commit_group;" ::: "memory");

    const uint32_t sbase32 = smem_u32(smem);
    const uint32_t aAddrOff = (uint32_t)((wm * 112 + (lane & 15)) * ASTR + ((lane >> 4) << 4));
    const uint32_t bAddrOff = (uint32_t)((wn * 32 + (lane & 7) + ((lane >> 4) << 3)) * ASTR
                                         + (((lane >> 3) & 1) << 4));
    const int r = lane >> 2;
    const bool evenr = (r & 1) == 0;

    for (int it = 0; it < nit; ++it) {
        const int ntile = bx + NSMB * it;
        if (it + 1 < nit) {
            const int ntn = bx + NSMB * (it + 1);
            char* dB = smem + A_BYTES + ((it + 1) & 1) * B_BYTES + brow * ASTR + bhalf * 208;
            const __half* gB = Btab + (size_t)(ntn * NT + brow) * KP + bhalf * 104;
#pragma unroll
            for (int q = 0; q < 13; ++q)
                cp16(smem_u32(dB + 16 * q), gB + 8 * q);
            asm volatile("cp.async.commit_group;" ::: "memory");
            asm volatile("cp.async.wait_group 1;" ::: "memory");
        } else {
            asm volatile("cp.async.wait_group 0;" ::: "memory");
        }
        __syncthreads();

        float acc[7][4][4];
#pragma unroll
        for (int mi = 0; mi < 7; ++mi)
#pragma unroll
            for (int ni = 0; ni < 4; ++ni)
#pragma unroll
                for (int q = 0; q < 4; ++q) acc[mi][ni][q] = 0.0f;

        const uint32_t aA = sbase32;
        const uint32_t aB = sbase32 + (uint32_t)(A_BYTES + (it & 1) * B_BYTES);
#pragma unroll
        for (int ks = 0; ks < NKS; ++ks) {
            const uint32_t kb = (uint32_t)(ks * 32);
            uint32_t ah[7][4], bq[4][2];
#pragma unroll
            for (int mi = 0; mi < 7; ++mi)
                ldsm_x4(ah[mi][0], ah[mi][1], ah[mi][2], ah[mi][3],
                        aA + aAddrOff + (uint32_t)(mi * 16 * ASTR) + kb);
#pragma unroll
            for (int ni2 = 0; ni2 < 2; ++ni2)
                ldsm_x4(bq[2 * ni2][0], bq[2 * ni2][1], bq[2 * ni2 + 1][0], bq[2 * ni2 + 1][1],
                        aB + bAddrOff + (uint32_t)(ni2 * 16 * ASTR) + kb);
#pragma unroll
            for (int mi = 0; mi < 7; ++mi)
#pragma unroll
                for (int ni = 0; ni < 4; ++ni)
                    mma16816(acc[mi][ni], ah[mi], bq[ni][0], bq[ni][1]);
        }

        // ---- epilogue: power = re^2 + im^2 (row pairs lane^4), fp16 stores ------
#pragma unroll
        for (int mi = 0; mi < 7; ++mi) {
#pragma unroll
            for (int ni = 0; ni < 4; ++ni) {
                float p0 = acc[mi][ni][0] * acc[mi][ni][0];
                float p1 = acc[mi][ni][1] * acc[mi][ni][1];
                float p2 = acc[mi][ni][2] * acc[mi][ni][2];
                float p3 = acc[mi][ni][3] * acc[mi][ni][3];
                p0 += __shfl_xor_sync(0xffffffffu, p0, 4);
                p1 += __shfl_xor_sync(0xffffffffu, p1, 4);
                p2 += __shfl_xor_sync(0xffffffffu, p2, 4);
                p3 += __shfl_xor_sync(0xffffffffu, p3, 4);
                if (evenr) {
                    const int fr = ntile * NT + wn * 32 + ni * 8 + 2 * (lane & 3);
                    const int R0 = wm * 112 + mi * 16 + r;
                    if (R0 < mlim) {
                        const int f = 2 * (R0 >> 1) + cls;
                        __half2* dst = reinterpret_cast<__half2*>(g_powh + (size_t)f * NFRTOT + fr);
                        *dst = __floats2half2_rn(p0, p1);
                    }
                    const int R1 = R0 + 8;
                    if (R1 < mlim) {
                        const int f = 2 * (R1 >> 1) + cls;
                        __half2* dst = reinterpret_cast<__half2*>(g_powh + (size_t)f * NFRTOT + fr);
                        *dst = __floats2half2_rn(p2, p3);
                    }
                }
            }
        }
        __syncthreads();   // protect next iteration's B buffer overwrite
    }
}

// ---------------- mel: one thread per (batch, mel, 4 frames) --------------------
__global__ void __launch_bounds__(256) mel_kernel(const float* __restrict__ fb,
                                                  float* __restrict__ out) {
    const int q = blockIdx.x * blockDim.x + threadIdx.x;
    const int m = blockIdx.y;
    const int b = blockIdx.z;
    float lmax = -3.0e38f;
    if (q < NFRAMES / 4) {
        const int t0 = q * 4;
        const int lo = g_flo[m];
        const int hi = g_fhi[m];
        const float* fbm = fb + m * NFREQ;
        const uint2* p = reinterpret_cast<const uint2*>(
            g_powh + (size_t)lo * NFRTOT + (size_t)b * NFRAMES + t0);
        const size_t stride8 = NFRTOT / 4;
        float4 acc = make_float4(0.f, 0.f, 0.f, 0.f);
        for (int f = lo; f < hi; ++f) {
            const float w = __ldg(&fbm[f]);
            uint2 raw = *p;
            p += stride8;
            const float2 v01 = __half22float2(*reinterpret_cast<const __half2*>(&raw.x));
            const float2 v23 = __half22float2(*reinterpret_cast<const __half2*>(&raw.y));
            acc.x = fmaf(w, v01.x, acc.x);
            acc.y = fmaf(w, v01.y, acc.y);
            acc.z = fmaf(w, v23.x, acc.z);
            acc.w = fmaf(w, v23.y, acc.w);
        }
        float4 rr;
        rr.x = log10f(fmaxf(acc.x, 1e-10f));
        rr.y = log10f(fmaxf(acc.y, 1e-10f));
        rr.z = log10f(fmaxf(acc.z, 1e-10f));
        rr.w = log10f(fmaxf(acc.w, 1e-10f));
        *reinterpret_cast<float4*>(out + ((size_t)b * NMELS + m) * NFRAMES + t0) = rr;
        lmax = fmaxf(fmaxf(rr.x, rr.y), fmaxf(rr.z, rr.w));
    }
    __shared__ float wmax[8];
#pragma unroll
    for (int o = 16; o; o >>= 1)
        lmax = fmaxf(lmax, __shfl_xor_sync(0xffffffffu, lmax, o));
    if ((threadIdx.x & 31) == 0) wmax[threadIdx.x >> 5] = lmax;
    __syncthreads();
    if (threadIdx.x < 8) {
        float v = wmax[threadIdx.x];
#pragma unroll
        for (int o = 4; o; o >>= 1)
            v = fmaxf(v, __shfl_xor_sync(0xffu, v, o));
        if (threadIdx.x == 0) atomicMax(&g_max[b], f2ord(v));
    }
}

// ---------------- finalize: floor at max-8, normalize (2 float4 / thread) -------
__global__ void __launch_bounds__(256) fin_kernel(float* __restrict__ out) {
    const int b = blockIdx.y;
    const float floorv = ord2f(g_max[b]) - 8.0f;
    const size_t base = 2 * ((size_t)blockIdx.x * blockDim.x + threadIdx.x);
    const size_t per = (size_t)NMELS * NFRAMES / 4;
    float4* pb = reinterpret_cast<float4*>(out + (size_t)b * NMELS * NFRAMES);
#pragma unroll
    for (int j = 0; j < 2; ++j) {
        const size_t idx = base + j;
        if (idx < per) {
            float4 v = pb[idx];
            v.x = (fmaxf(v.x, floorv) + 4.0f) * 0.25f;
            v.y = (fmaxf(v.y, floorv) + 4.0f) * 0.25f;
            v.z = (fmaxf(v.z, floorv) + 4.0f) * 0.25f;
            v.w = (fmaxf(v.w, floorv) + 4.0f) * 0.25f;
            pb[idx] = v;
        }
    }
}

// ---------------- launch --------------------------------------------------------
extern "C" void kernel_launch(void* const* d_in, const int* in_sizes, int n_in,
                              void* d_out, int out_size) {
    const float* audio = (const float*)d_in[0];
    const float* cosk  = (const float*)d_in[1];
    const float* fb    = (const float*)d_in[3];
    float* out = (float*)d_out;

    cudaFuncSetAttribute(stft_mma_kernel, cudaFuncAttributeMaxDynamicSharedMemorySize, SMEMSZ);

    prep_kernel<<<1024, 256>>>(fb);
    prep_uv<<<dim3(NFRAMES, BATCH), 256>>>(audio, cosk);

    stft_mma_kernel<<<dim3(NSMB, 2), 256, SMEMSZ>>>();

    dim3 gm((NFRAMES / 4 + 255) / 256, NMELS, BATCH);         // (3, 128, 32)
    mel_kernel<<<gm, 256>>>(fb, out);

    dim3 gf((NMELS * NFRAMES / 8 + 255) / 256, BATCH);
    fin_kernel<<<gf, 256>>>(out);
}

// round 15
// speedup vs baseline: 7.4767x; 1.3368x over previous
#include <cuda_runtime.h>
#include <cuda_fp16.h>
#include <cstdint>
#include <math.h>

#define BATCH   32
#define CHUNK   480000
#define NFFT    400
#define HOP     160
#define NMELS   128
#define NFREQ   201
#define NFRAMES 3000
#define NFRTOT  (BATCH * NFRAMES)   // 96000
#define KP      208                 // padded half-K (200 real + 8 zero)
#define NT      128                 // frames per B tile
#define NNT     (NFRTOT / NT)       // 750
#define ASTR    432                 // smem row stride bytes (208 fp16 = 416B + 16 pad)
#define MR      224                 // M rows per block (covers 202 real + pad)
#define A_BYTES (MR * ASTR)         // 96768
#define B_BYTES (128 * ASTR)        // 55296 per buffer
#define SMEMSZ  (A_BYTES + 2 * B_BYTES)   // 207360
#define MLIM_E  202                 // even-class real rows (k=0,2,...,200)
#define MLIM_O  200                 // odd-class real rows  (k=1,3,...,199)
#define NKS     13                  // k16 steps (208 / 16)
#define NGR     26                  // 16B granules per 416B row
#define NSMB    148                 // grid x (persistent slots)
#define STH     512                 // stft threads

// ---------------- device scratch ------------------------------------------------
__device__ __align__(16) __half g_powh[(size_t)NFREQ * NFRTOT];   // fp16 power, 38.5 MB
__device__ __align__(16) __half g_u[(size_t)NFRTOT * KP];         // even-class B, 40 MB
__device__ __align__(16) __half g_v[(size_t)NFRTOT * KP];         // odd-class B, 40 MB
__device__ __align__(16) __half g_ae[256 * KP];                   // even basis
__device__ __align__(16) __half g_ao[256 * KP];                   // odd basis
__device__ unsigned g_max[BATCH];
__device__ int g_flo[NMELS];
__device__ int g_fhi[NMELS];

// ---------------- helpers -------------------------------------------------------
__device__ __forceinline__ uint32_t smem_u32(const void* p) {
    uint32_t a;
    asm("{ .reg .u64 t; cvta.to.shared.u64 t, %1; cvt.u32.u64 %0, t; }" : "=r"(a) : "l"(p));
    return a;
}
__device__ __forceinline__ void cp16(uint32_t saddr, const void* gaddr) {
    asm volatile("cp.async.cg.shared.global [%0], [%1], 16;" :: "r"(saddr), "l"(gaddr) : "memory");
}
__device__ __forceinline__ void ldsm_x4(uint32_t& r0, uint32_t& r1, uint32_t& r2, uint32_t& r3,
                                        uint32_t addr) {
    asm volatile("ldmatrix.sync.aligned.m8n8.x4.shared.b16 {%0,%1,%2,%3}, [%4];"
                 : "=r"(r0), "=r"(r1), "=r"(r2), "=r"(r3) : "r"(addr));
}
__device__ __forceinline__ void mma16816(float* d, const uint32_t* a, uint32_t b0, uint32_t b1) {
    asm volatile("mma.sync.aligned.m16n8k16.row.col.f32.f16.f16.f32 "
                 "{%0,%1,%2,%3}, {%4,%5,%6,%7}, {%8,%9}, {%0,%1,%2,%3};"
                 : "+f"(d[0]), "+f"(d[1]), "+f"(d[2]), "+f"(d[3])
                 : "r"(a[0]), "r"(a[1]), "r"(a[2]), "r"(a[3]), "r"(b0), "r"(b1));
}
__device__ __forceinline__ unsigned f2ord(float f) {
    unsigned u = __float_as_uint(f);
    return (u & 0x80000000u) ? ~u : (u | 0x80000000u);
}
__device__ __forceinline__ float ord2f(unsigned u) {
    return __uint_as_float((u & 0x80000000u) ? (u & 0x7fffffffu) : ~u);
}

// ---------------- prep: basis tables (fp64), mel ranges, maxes ------------------
__global__ void prep_kernel(const float* __restrict__ fb) {
    const int idx = blockIdx.x * blockDim.x + threadIdx.x;
    const int stride = gridDim.x * blockDim.x;
    const int total = 2 * 256 * KP;
    for (int e = idx; e < total; e += stride) {
        int tab = e / (256 * KP);
        int rem = e - tab * (256 * KP);
        int R = rem / KP;
        int r = rem - R * KP;
        int mlim = tab ? MLIM_O : MLIM_E;
        __half v = __float2half_rn(0.0f);
        if (R < mlim && r < 200) {
            int k = 2 * (R >> 1) + tab;
            double ang = (2.0 * M_PI / 400.0) * (double)k * (double)r;
            double bv = (R & 1) ? -sin(ang) : cos(ang);
            v = __float2half_rn((float)bv);
        }
        (tab ? g_ao : g_ae)[R * KP + r] = v;
    }
    if (idx < NMELS) {
        int lo = NFREQ, hi = 0;
        for (int f = 0; f < NFREQ; ++f) {
            if (fb[idx * NFREQ + f] != 0.0f) { if (f < lo) lo = f; hi = f + 1; }
        }
        if (lo >= hi) { lo = 0; hi = 0; }
        g_flo[idx] = lo;
        g_fhi[idx] = hi;
    }
    if (idx < BATCH) g_max[idx] = f2ord(-3.0e38f);
}

// ---------------- prep: radix-2 folded inputs u,v (vectorized) ------------------
// grid (750, 32), 224 threads: thread -> (local frame fl = tid/52, quad q = tid%52),
// covering 4 frames x 52 quads (r = 4q). Interior frames use float4 loads + uint2
// stores; edges (t = 0, 1, 2999) scalar-reflect. q >= 50 -> zero padding.
__global__ void __launch_bounds__(224) prep_uv(const float* __restrict__ audio,
                                               const float* __restrict__ cosk) {
    const int tid = threadIdx.x;
    const int fl = tid / 52;
    const int q = tid - fl * 52;
    if (fl >= 4) return;
    const int t = blockIdx.x * 4 + fl;
    const int b = blockIdx.y;
    const int r0 = 4 * q;
    const size_t o = ((size_t)b * NFRAMES + t) * KP + r0;
    uint2* du = reinterpret_cast<uint2*>(g_u + o);
    uint2* dv = reinterpret_cast<uint2*>(g_v + o);
    if (q >= 50) {                       // r in [200, 208): zero pad
        *du = make_uint2(0u, 0u);
        *dv = make_uint2(0u, 0u);
        return;
    }
    const float* ap = audio + (size_t)b * CHUNK;
    float x1[4], x2[4];
    if (t >= 2 && t <= 2998) {
        const float4 a1 = *reinterpret_cast<const float4*>(ap + (t * HOP - 200 + r0));
        const float4 a2 = *reinterpret_cast<const float4*>(ap + (t * HOP + r0));
        x1[0] = a1.x; x1[1] = a1.y; x1[2] = a1.z; x1[3] = a1.w;
        x2[0] = a2.x; x2[1] = a2.y; x2[2] = a2.z; x2[3] = a2.w;
    } else {
#pragma unroll
        for (int j = 0; j < 4; ++j) {
            int s = t * HOP - 200 + r0 + j;
            if (s < 0) s = -s;
            int s2 = t * HOP + r0 + j;
            if (s2 >= CHUNK) s2 = 2 * CHUNK - 2 - s2;
            x1[j] = ap[s];
            x2[j] = ap[s2];
        }
    }
    const float4 wav = *reinterpret_cast<const float4*>(cosk + r0);
    const float4 wbv = *reinterpret_cast<const float4*>(cosk + 200 + r0);
    const float wa[4] = {wav.x, wav.y, wav.z, wav.w};
    const float wb[4] = {wbv.x, wbv.y, wbv.z, wbv.w};
    __half uh[4], vh[4];
#pragma unroll
    for (int j = 0; j < 4; ++j) {
        uh[j] = __float2half_rn(fmaf(wa[j], x1[j],  wb[j] * x2[j]));
        vh[j] = __float2half_rn(fmaf(wa[j], x1[j], -wb[j] * x2[j]));
    }
    *du = *reinterpret_cast<uint2*>(uh);
    *dv = *reinterpret_cast<uint2*>(vh);
}

// ---------------- STFT: persistent-A radix-2 fp16 mma.sync (512 thr) ------------
// grid (148, 2): y = class. Block loads its class's WHOLE A (224 x 208) once,
// then iterates ntiles, double-buffering only B. 16 warps: 2m x 8n,
// warp tile 112M x 16N (MI=7, NI=2). One B load feeds 2912 HMMA.
// Loaders: 26 x 16B granules per 416B row (g = row * 26 + granule).
__global__ void __launch_bounds__(STH, 1) stft_mma_kernel() {
    extern __shared__ __align__(128) char smem[];
    const int tid = threadIdx.x;
    const int lane = tid & 31;
    const int warp = tid >> 5;       // 0..15
    const int wm = warp >> 3;        // 0..1
    const int wn = warp & 7;         // 0..7
    const int bx = blockIdx.x;
    const int cls = blockIdx.y;
    const int mlim = cls ? MLIM_O : MLIM_E;
    const __half* Atab = cls ? g_ao : g_ae;
    const __half* Btab = cls ? g_v : g_u;
    const int nit = (NNT - bx + NSMB - 1) / NSMB;

    // ---- load A (once): 224 rows x 26 granules ----
    for (int g = tid; g < MR * NGR; g += STH) {
        const int row = g / NGR;
        const int gi = g - row * NGR;
        cp16(smem_u32(smem + row * ASTR + gi * 16), Atab + (size_t)row * KP + gi * 8);
    }
    // ---- load B for first ntile into buffer 0 ----
    for (int g = tid; g < NT * NGR; g += STH) {
        const int row = g / NGR;
        const int gi = g - row * NGR;
        cp16(smem_u32(smem + A_BYTES + row * ASTR + gi * 16),
             Btab + (size_t)(bx * NT + row) * KP + gi * 8);
    }
    asm volatile("cp.async.commit_group;" ::: "memory");

    const uint32_t sbase32 = smem_u32(smem);
    const uint32_t aAddrOff = (uint32_t)((wm * 112 + (lane & 15)) * ASTR + ((lane >> 4) << 4));
    const uint32_t bAddrOff = (uint32_t)((wn * 16 + (lane & 7) + ((lane >> 4) << 3)) * ASTR
                                         + (((lane >> 3) & 1) << 4));
    const int r = lane >> 2;
    const bool evenr = (r & 1) == 0;

    for (int it = 0; it < nit; ++it) {
        const int ntile = bx + NSMB * it;
        if (it + 1 < nit) {
            const int ntn = bx + NSMB * (it + 1);
            char* bbuf = smem + A_BYTES + ((it + 1) & 1) * B_BYTES;
            for (int g = tid; g < NT * NGR; g += STH) {
                const int row = g / NGR;
                const int gi = g - row * NGR;
                cp16(smem_u32(bbuf + row * ASTR + gi * 16),
                     Btab + (size_t)(ntn * NT + row) * KP + gi * 8);
            }
            asm volatile("cp.async.commit_group;" ::: "memory");
            asm volatile("cp.async.wait_group 1;" ::: "memory");
        } else {
            asm volatile("cp.async.wait_group 0;" ::: "memory");
        }
        __syncthreads();

        float acc[7][2][4];
#pragma unroll
        for (int mi = 0; mi < 7; ++mi)
#pragma unroll
            for (int ni = 0; ni < 2; ++ni)
#pragma unroll
                for (int qq = 0; qq < 4; ++qq) acc[mi][ni][qq] = 0.0f;

        const uint32_t aA = sbase32;
        const uint32_t aB = sbase32 + (uint32_t)(A_BYTES + (it & 1) * B_BYTES);
#pragma unroll
        for (int ks = 0; ks < NKS; ++ks) {
            const uint32_t kb = (uint32_t)(ks * 32);
            uint32_t ah[7][4], bq[2][2];
#pragma unroll
            for (int mi = 0; mi < 7; ++mi)
                ldsm_x4(ah[mi][0], ah[mi][1], ah[mi][2], ah[mi][3],
                        aA + aAddrOff + (uint32_t)(mi * 16 * ASTR) + kb);
            ldsm_x4(bq[0][0], bq[0][1], bq[1][0], bq[1][1], aB + bAddrOff + kb);
#pragma unroll
            for (int mi = 0; mi < 7; ++mi)
#pragma unroll
                for (int ni = 0; ni < 2; ++ni)
                    mma16816(acc[mi][ni], ah[mi], bq[ni][0], bq[ni][1]);
        }

        // ---- epilogue: power = re^2 + im^2 (row pairs lane^4), fp16 stores ------
#pragma unroll
        for (int mi = 0; mi < 7; ++mi) {
#pragma unroll
            for (int ni = 0; ni < 2; ++ni) {
                float p0 = acc[mi][ni][0] * acc[mi][ni][0];
                float p1 = acc[mi][ni][1] * acc[mi][ni][1];
                float p2 = acc[mi][ni][2] * acc[mi][ni][2];
                float p3 = acc[mi][ni][3] * acc[mi][ni][3];
                p0 += __shfl_xor_sync(0xffffffffu, p0, 4);
                p1 += __shfl_xor_sync(0xffffffffu, p1, 4);
                p2 += __shfl_xor_sync(0xffffffffu, p2, 4);
                p3 += __shfl_xor_sync(0xffffffffu, p3, 4);
                if (evenr) {
                    const int fr = ntile * NT + wn * 16 + ni * 8 + 2 * (lane & 3);
                    const int R0 = wm * 112 + mi * 16 + r;
                    if (R0 < mlim) {
                        const int f = 2 * (R0 >> 1) + cls;
                        __half2* dst = reinterpret_cast<__half2*>(g_powh + (size_t)f * NFRTOT + fr);
                        *dst = __floats2half2_rn(p0, p1);
                    }
                    const int R1 = R0 + 8;
                    if (R1 < mlim) {
                        const int f = 2 * (R1 >> 1) + cls;
                        __half2* dst = reinterpret_cast<__half2*>(g_powh + (size_t)f * NFRTOT + fr);
                        *dst = __floats2half2_rn(p2, p3);
                    }
                }
            }
        }
        __syncthreads();   // protect next iteration's B buffer overwrite
    }
}

// ---------------- mel: one thread per (batch, mel, 4 frames) --------------------
__global__ void __launch_bounds__(256) mel_kernel(const float* __restrict__ fb,
                                                  float* __restrict__ out) {
    const int q = blockIdx.x * blockDim.x + threadIdx.x;
    const int m = blockIdx.y;
    const int b = blockIdx.z;
    float lmax = -3.0e38f;
    if (q < NFRAMES / 4) {
        const int t0 = q * 4;
        const int lo = g_flo[m];
        const int hi = g_fhi[m];
        const float* fbm = fb + m * NFREQ;
        const uint2* p = reinterpret_cast<const uint2*>(
            g_powh + (size_t)lo * NFRTOT + (size_t)b * NFRAMES + t0);
        const size_t stride8 = NFRTOT / 4;
        float4 acc = make_float4(0.f, 0.f, 0.f, 0.f);
        for (int f = lo; f < hi; ++f) {
            const float w = __ldg(&fbm[f]);
            uint2 raw = *p;
            p += stride8;
            const float2 v01 = __half22float2(*reinterpret_cast<const __half2*>(&raw.x));
            const float2 v23 = __half22float2(*reinterpret_cast<const __half2*>(&raw.y));
            acc.x = fmaf(w, v01.x, acc.x);
            acc.y = fmaf(w, v01.y, acc.y);
            acc.z = fmaf(w, v23.x, acc.z);
            acc.w = fmaf(w, v23.y, acc.w);
        }
        float4 rr;
        rr.x = log10f(fmaxf(acc.x, 1e-10f));
        rr.y = log10f(fmaxf(acc.y, 1e-10f));
        rr.z = log10f(fmaxf(acc.z, 1e-10f));
        rr.w = log10f(fmaxf(acc.w, 1e-10f));
        *reinterpret_cast<float4*>(out + ((size_t)b * NMELS + m) * NFRAMES + t0) = rr;
        lmax = fmaxf(fmaxf(rr.x, rr.y), fmaxf(rr.z, rr.w));
    }
    __shared__ float wmax[8];
#pragma unroll
    for (int o = 16; o; o >>= 1)
        lmax = fmaxf(lmax, __shfl_xor_sync(0xffffffffu, lmax, o));
    if ((threadIdx.x & 31) == 0) wmax[threadIdx.x >> 5] = lmax;
    __syncthreads();
    if (threadIdx.x < 8) {
        float v = wmax[threadIdx.x];
#pragma unroll
        for (int o = 4; o; o >>= 1)
            v = fmaxf(v, __shfl_xor_sync(0xffu, v, o));
        if (threadIdx.x == 0) atomicMax(&g_max[b], f2ord(v));
    }
}

// ---------------- finalize: floor at max-8, normalize (2 float4 / thread) -------
__global__ void __launch_bounds__(256) fin_kernel(float* __restrict__ out) {
    const int b = blockIdx.y;
    const float floorv = ord2f(g_max[b]) - 8.0f;
    const size_t base = 2 * ((size_t)blockIdx.x * blockDim.x + threadIdx.x);
    const size_t per = (size_t)NMELS * NFRAMES / 4;
    float4* pb = reinterpret_cast<float4*>(out + (size_t)b * NMELS * NFRAMES);
#pragma unroll
    for (int j = 0; j < 2; ++j) {
        const size_t idx = base + j;
        if (idx < per) {
            float4 v = pb[idx];
            v.x = (fmaxf(v.x, floorv) + 4.0f) * 0.25f;
            v.y = (fmaxf(v.y, floorv) + 4.0f) * 0.25f;
            v.z = (fmaxf(v.z, floorv) + 4.0f) * 0.25f;
            v.w = (fmaxf(v.w, floorv) + 4.0f) * 0.25f;
            pb[idx] = v;
        }
    }
}

// ---------------- launch --------------------------------------------------------
extern "C" void kernel_launch(void* const* d_in, const int* in_sizes, int n_in,
                              void* d_out, int out_size) {
    const float* audio = (const float*)d_in[0];
    const float* cosk  = (const float*)d_in[1];
    const float* fb    = (const float*)d_in[3];
    float* out = (float*)d_out;

    cudaFuncSetAttribute(stft_mma_kernel, cudaFuncAttributeMaxDynamicSharedMemorySize, SMEMSZ);

    prep_kernel<<<1024, 256>>>(fb);
    prep_uv<<<dim3(NNT, BATCH), 224>>>(audio, cosk);

    stft_mma_kernel<<<dim3(NSMB, 2), STH, SMEMSZ>>>();

    dim3 gm((NFRAMES / 4 + 255) / 256, NMELS, BATCH);         // (3, 128, 32)
    mel_kernel<<<gm, 256>>>(fb, out);

    dim3 gf((NMELS * NFRAMES / 8 + 255) / 256, BATCH);
    fin_kernel<<<gf, 256>>>(out);
}

// round 16
// speedup vs baseline: 7.5842x; 1.0144x over previous
#include <cuda_runtime.h>
#include <cuda_fp16.h>
#include <cstdint>
#include <math.h>

#define BATCH   32
#define CHUNK   480000
#define NFFT    400
#define HOP     160
#define NMELS   128
#define NFREQ   201
#define NFRAMES 3000
#define NFRTOT  (BATCH * NFRAMES)   // 96000
#define KP      208                 // padded half-K (200 real + 8 zero)
#define NT      128                 // frames per B tile
#define NNT     (NFRTOT / NT)       // 750
#define ASTR    432                 // smem row stride bytes (208 fp16 = 416B + 16 pad)
#define MR      224                 // M rows per block (covers 202 real + pad)
#define A_BYTES (MR * ASTR)         // 96768
#define B_BYTES (128 * ASTR)        // 55296 per buffer
#define SMEMSZ  (A_BYTES + 2 * B_BYTES)   // 207360
#define MLIM_E  202                 // even-class real rows (k=0,2,...,200)
#define MLIM_O  200                 // odd-class real rows  (k=1,3,...,199)
#define NKS     13                  // k16 steps (208 / 16)
#define NGR     26                  // 16B granules per 416B row
#define NSMB    148                 // grid x (persistent slots)
#define STH     512                 // stft threads

// ---------------- device scratch ------------------------------------------------
__device__ __align__(16) __half g_powh[(size_t)NFREQ * NFRTOT];   // fp16 power, 38.5 MB
__device__ __align__(16) __half g_u[(size_t)NFRTOT * KP];         // even-class B, 40 MB
__device__ __align__(16) __half g_v[(size_t)NFRTOT * KP];         // odd-class B, 40 MB
__device__ __align__(16) __half g_ae[256 * KP];                   // even basis
__device__ __align__(16) __half g_ao[256 * KP];                   // odd basis
__device__ unsigned g_max[BATCH];
__device__ int g_flo[NMELS];
__device__ int g_fhi[NMELS];

// ---------------- helpers -------------------------------------------------------
__device__ __forceinline__ uint32_t smem_u32(const void* p) {
    uint32_t a;
    asm("{ .reg .u64 t; cvta.to.shared.u64 t, %1; cvt.u32.u64 %0, t; }" : "=r"(a) : "l"(p));
    return a;
}
__device__ __forceinline__ void cp16(uint32_t saddr, const void* gaddr) {
    asm volatile("cp.async.cg.shared.global [%0], [%1], 16;" :: "r"(saddr), "l"(gaddr) : "memory");
}
__device__ __forceinline__ void ldsm_x4(uint32_t& r0, uint32_t& r1, uint32_t& r2, uint32_t& r3,
                                        uint32_t addr) {
    asm volatile("ldmatrix.sync.aligned.m8n8.x4.shared.b16 {%0,%1,%2,%3}, [%4];"
                 : "=r"(r0), "=r"(r1), "=r"(r2), "=r"(r3) : "r"(addr));
}
__device__ __forceinline__ void mma16816(float* d, const uint32_t* a, uint32_t b0, uint32_t b1) {
    asm volatile("mma.sync.aligned.m16n8k16.row.col.f32.f16.f16.f32 "
                 "{%0,%1,%2,%3}, {%4,%5,%6,%7}, {%8,%9}, {%0,%1,%2,%3};"
                 : "+f"(d[0]), "+f"(d[1]), "+f"(d[2]), "+f"(d[3])
                 : "r"(a[0]), "r"(a[1]), "r"(a[2]), "r"(a[3]), "r"(b0), "r"(b1));
}
__device__ __forceinline__ unsigned f2ord(float f) {
    unsigned u = __float_as_uint(f);
    return (u & 0x80000000u) ? ~u : (u | 0x80000000u);
}
__device__ __forceinline__ float ord2f(unsigned u) {
    return __uint_as_float((u & 0x80000000u) ? (u & 0x7fffffffu) : ~u);
}

// ---------------- prep: basis tables (fp64), mel ranges, maxes ------------------
__global__ void prep_kernel(const float* __restrict__ fb) {
    const int idx = blockIdx.x * blockDim.x + threadIdx.x;
    const int stride = gridDim.x * blockDim.x;
    const int total = 2 * 256 * KP;
    for (int e = idx; e < total; e += stride) {
        int tab = e / (256 * KP);
        int rem = e - tab * (256 * KP);
        int R = rem / KP;
        int r = rem - R * KP;
        int mlim = tab ? MLIM_O : MLIM_E;
        __half v = __float2half_rn(0.0f);
        if (R < mlim && r < 200) {
            int k = 2 * (R >> 1) + tab;
            double ang = (2.0 * M_PI / 400.0) * (double)k * (double)r;
            double bv = (R & 1) ? -sin(ang) : cos(ang);
            v = __float2half_rn((float)bv);
        }
        (tab ? g_ao : g_ae)[R * KP + r] = v;
    }
    if (idx < NMELS) {
        int lo = NFREQ, hi = 0;
        for (int f = 0; f < NFREQ; ++f) {
            if (fb[idx * NFREQ + f] != 0.0f) { if (f < lo) lo = f; hi = f + 1; }
        }
        if (lo >= hi) { lo = 0; hi = 0; }
        g_flo[idx] = lo;
        g_fhi[idx] = hi;
    }
    if (idx < BATCH) g_max[idx] = f2ord(-3.0e38f);
}

// ---------------- prep: radix-2 folded inputs u,v (vectorized) ------------------
__global__ void __launch_bounds__(224) prep_uv(const float* __restrict__ audio,
                                               const float* __restrict__ cosk) {
    const int tid = threadIdx.x;
    const int fl = tid / 52;
    const int q = tid - fl * 52;
    if (fl >= 4) return;
    const int t = blockIdx.x * 4 + fl;
    const int b = blockIdx.y;
    const int r0 = 4 * q;
    const size_t o = ((size_t)b * NFRAMES + t) * KP + r0;
    uint2* du = reinterpret_cast<uint2*>(g_u + o);
    uint2* dv = reinterpret_cast<uint2*>(g_v + o);
    if (q >= 50) {                       // r in [200, 208): zero pad
        *du = make_uint2(0u, 0u);
        *dv = make_uint2(0u, 0u);
        return;
    }
    const float* ap = audio + (size_t)b * CHUNK;
    float x1[4], x2[4];
    if (t >= 2 && t <= 2998) {
        const float4 a1 = *reinterpret_cast<const float4*>(ap + (t * HOP - 200 + r0));
        const float4 a2 = *reinterpret_cast<const float4*>(ap + (t * HOP + r0));
        x1[0] = a1.x; x1[1] = a1.y; x1[2] = a1.z; x1[3] = a1.w;
        x2[0] = a2.x; x2[1] = a2.y; x2[2] = a2.z; x2[3] = a2.w;
    } else {
#pragma unroll
        for (int j = 0; j < 4; ++j) {
            int s = t * HOP - 200 + r0 + j;
            if (s < 0) s = -s;
            int s2 = t * HOP + r0 + j;
            if (s2 >= CHUNK) s2 = 2 * CHUNK - 2 - s2;
            x1[j] = ap[s];
            x2[j] = ap[s2];
        }
    }
    const float4 wav = *reinterpret_cast<const float4*>(cosk + r0);
    const float4 wbv = *reinterpret_cast<const float4*>(cosk + 200 + r0);
    const float wa[4] = {wav.x, wav.y, wav.z, wav.w};
    const float wb[4] = {wbv.x, wbv.y, wbv.z, wbv.w};
    __half uh[4], vh[4];
#pragma unroll
    for (int j = 0; j < 4; ++j) {
        uh[j] = __float2half_rn(fmaf(wa[j], x1[j],  wb[j] * x2[j]));
        vh[j] = __float2half_rn(fmaf(wa[j], x1[j], -wb[j] * x2[j]));
    }
    *du = *reinterpret_cast<uint2*>(uh);
    *dv = *reinterpret_cast<uint2*>(vh);
}

// ---------------- STFT: persistent-A radix-2 fp16 mma.sync (512 thr) ------------
// grid (148, 2): y = class. Whole-class A (224 x 208) resident; B double-buffered.
// 16 warps: 2m x 8n, warp tile 112M x 16N (MI=7, NI=2).
// wm==1, mi==6 covers rows 208..223 (all padding) -> uniformly skipped.
__global__ void __launch_bounds__(STH, 1) stft_mma_kernel() {
    extern __shared__ __align__(128) char smem[];
    const int tid = threadIdx.x;
    const int lane = tid & 31;
    const int warp = tid >> 5;       // 0..15
    const int wm = warp >> 3;        // 0..1
    const int wn = warp & 7;         // 0..7
    const int bx = blockIdx.x;
    const int cls = blockIdx.y;
    const int mlim = cls ? MLIM_O : MLIM_E;
    const __half* Atab = cls ? g_ao : g_ae;
    const __half* Btab = cls ? g_v : g_u;
    const int nit = (NNT - bx + NSMB - 1) / NSMB;
    const int milim = (wm == 1) ? 6 : 7;   // skip all-padding m-tile

    // ---- load A (once): 224 rows x 26 granules ----
    for (int g = tid; g < MR * NGR; g += STH) {
        const int row = g / NGR;
        const int gi = g - row * NGR;
        cp16(smem_u32(smem + row * ASTR + gi * 16), Atab + (size_t)row * KP + gi * 8);
    }
    // ---- load B for first ntile into buffer 0 ----
    for (int g = tid; g < NT * NGR; g += STH) {
        const int row = g / NGR;
        const int gi = g - row * NGR;
        cp16(smem_u32(smem + A_BYTES + row * ASTR + gi * 16),
             Btab + (size_t)(bx * NT + row) * KP + gi * 8);
    }
    asm volatile("cp.async.commit_group;" ::: "memory");

    const uint32_t sbase32 = smem_u32(smem);
    const uint32_t aAddrOff = (uint32_t)((wm * 112 + (lane & 15)) * ASTR + ((lane >> 4) << 4));
    const uint32_t bAddrOff = (uint32_t)((wn * 16 + (lane & 7) + ((lane >> 4) << 3)) * ASTR
                                         + (((lane >> 3) & 1) << 4));
    const int r = lane >> 2;
    const bool evenr = (r & 1) == 0;

    for (int it = 0; it < nit; ++it) {
        const int ntile = bx + NSMB * it;
        if (it + 1 < nit) {
            const int ntn = bx + NSMB * (it + 1);
            char* bbuf = smem + A_BYTES + ((it + 1) & 1) * B_BYTES;
            for (int g = tid; g < NT * NGR; g += STH) {
                const int row = g / NGR;
                const int gi = g - row * NGR;
                cp16(smem_u32(bbuf + row * ASTR + gi * 16),
                     Btab + (size_t)(ntn * NT + row) * KP + gi * 8);
            }
            asm volatile("cp.async.commit_group;" ::: "memory");
            asm volatile("cp.async.wait_group 1;" ::: "memory");
        } else {
            asm volatile("cp.async.wait_group 0;" ::: "memory");
        }
        __syncthreads();

        float acc[7][2][4];
#pragma unroll
        for (int mi = 0; mi < 7; ++mi)
#pragma unroll
            for (int ni = 0; ni < 2; ++ni)
#pragma unroll
                for (int qq = 0; qq < 4; ++qq) acc[mi][ni][qq] = 0.0f;

        const uint32_t aA = sbase32;
        const uint32_t aB = sbase32 + (uint32_t)(A_BYTES + (it & 1) * B_BYTES);
#pragma unroll
        for (int ks = 0; ks < NKS; ++ks) {
            const uint32_t kb = (uint32_t)(ks * 32);
            uint32_t ah[7][4], bq[2][2];
#pragma unroll
            for (int mi = 0; mi < 7; ++mi)
                if (mi < milim)
                    ldsm_x4(ah[mi][0], ah[mi][1], ah[mi][2], ah[mi][3],
                            aA + aAddrOff + (uint32_t)(mi * 16 * ASTR) + kb);
            ldsm_x4(bq[0][0], bq[0][1], bq[1][0], bq[1][1], aB + bAddrOff + kb);
#pragma unroll
            for (int mi = 0; mi < 7; ++mi)
                if (mi < milim)
#pragma unroll
                    for (int ni = 0; ni < 2; ++ni)
                        mma16816(acc[mi][ni], ah[mi], bq[ni][0], bq[ni][1]);
        }

        // ---- epilogue: power = re^2 + im^2 (row pairs lane^4), fp16 stores ------
#pragma unroll
        for (int mi = 0; mi < 7; ++mi) {
            if (mi >= milim) continue;
#pragma unroll
            for (int ni = 0; ni < 2; ++ni) {
                float p0 = acc[mi][ni][0] * acc[mi][ni][0];
                float p1 = acc[mi][ni][1] * acc[mi][ni][1];
                float p2 = acc[mi][ni][2] * acc[mi][ni][2];
                float p3 = acc[mi][ni][3] * acc[mi][ni][3];
                p0 += __shfl_xor_sync(0xffffffffu, p0, 4);
                p1 += __shfl_xor_sync(0xffffffffu, p1, 4);
                p2 += __shfl_xor_sync(0xffffffffu, p2, 4);
                p3 += __shfl_xor_sync(0xffffffffu, p3, 4);
                if (evenr) {
                    const int fr = ntile * NT + wn * 16 + ni * 8 + 2 * (lane & 3);
                    const int R0 = wm * 112 + mi * 16 + r;
                    if (R0 < mlim) {
                        const int f = 2 * (R0 >> 1) + cls;
                        __half2* dst = reinterpret_cast<__half2*>(g_powh + (size_t)f * NFRTOT + fr);
                        *dst = __floats2half2_rn(p0, p1);
                    }
                    const int R1 = R0 + 8;
                    if (R1 < mlim) {
                        const int f = 2 * (R1 >> 1) + cls;
                        __half2* dst = reinterpret_cast<__half2*>(g_powh + (size_t)f * NFRTOT + fr);
                        *dst = __floats2half2_rn(p2, p3);
                    }
                }
            }
        }
        __syncthreads();   // protect next iteration's B buffer overwrite
    }
}

// ---------------- mel: one thread per (batch, mel, 8 frames) --------------------
// grid (2, 128, 32); q < 375. Per f: one 16B load (8 fp16), uniform weight,
// 8 FMAs. Fast __log10f (MUFU.LG2) — error ~1e-7, negligible vs fp16 noise.
__global__ void __launch_bounds__(256) mel_kernel(const float* __restrict__ fb,
                                                  float* __restrict__ out) {
    const int q = blockIdx.x * blockDim.x + threadIdx.x;
    const int m = blockIdx.y;
    const int b = blockIdx.z;
    float lmax = -3.0e38f;
    if (q < NFRAMES / 8) {
        const int t0 = q * 8;
        const int lo = g_flo[m];
        const int hi = g_fhi[m];
        const float* fbm = fb + m * NFREQ;
        const uint4* p = reinterpret_cast<const uint4*>(
            g_powh + (size_t)lo * NFRTOT + (size_t)b * NFRAMES + t0);
        const size_t stride16 = NFRTOT / 8;
        float acc[8];
#pragma unroll
        for (int j = 0; j < 8; ++j) acc[j] = 0.0f;
        for (int f = lo; f < hi; ++f) {
            const float w = __ldg(&fbm[f]);
            uint4 raw = *p;
            p += stride16;
            const float2 v01 = __half22float2(*reinterpret_cast<const __half2*>(&raw.x));
            const float2 v23 = __half22float2(*reinterpret_cast<const __half2*>(&raw.y));
            const float2 v45 = __half22float2(*reinterpret_cast<const __half2*>(&raw.z));
            const float2 v67 = __half22float2(*reinterpret_cast<const __half2*>(&raw.w));
            acc[0] = fmaf(w, v01.x, acc[0]);
            acc[1] = fmaf(w, v01.y, acc[1]);
            acc[2] = fmaf(w, v23.x, acc[2]);
            acc[3] = fmaf(w, v23.y, acc[3]);
            acc[4] = fmaf(w, v45.x, acc[4]);
            acc[5] = fmaf(w, v45.y, acc[5]);
            acc[6] = fmaf(w, v67.x, acc[6]);
            acc[7] = fmaf(w, v67.y, acc[7]);
        }
        float rr[8];
#pragma unroll
        for (int j = 0; j < 8; ++j) {
            rr[j] = __log10f(fmaxf(acc[j], 1e-10f));
            lmax = fmaxf(lmax, rr[j]);
        }
        float4* op = reinterpret_cast<float4*>(out + ((size_t)b * NMELS + m) * NFRAMES + t0);
        op[0] = make_float4(rr[0], rr[1], rr[2], rr[3]);
        op[1] = make_float4(rr[4], rr[5], rr[6], rr[7]);
    }
    __shared__ float wmax[8];
#pragma unroll
    for (int o = 16; o; o >>= 1)
        lmax = fmaxf(lmax, __shfl_xor_sync(0xffffffffu, lmax, o));
    if ((threadIdx.x & 31) == 0) wmax[threadIdx.x >> 5] = lmax;
    __syncthreads();
    if (threadIdx.x < 8) {
        float v = wmax[threadIdx.x];
#pragma unroll
        for (int o = 4; o; o >>= 1)
            v = fmaxf(v, __shfl_xor_sync(0xffu, v, o));
        if (threadIdx.x == 0) atomicMax(&g_max[b], f2ord(v));
    }
}

// ---------------- finalize: floor at max-8, normalize (2 float4 / thread) -------
__global__ void __launch_bounds__(256) fin_kernel(float* __restrict__ out) {
    const int b = blockIdx.y;
    const float floorv = ord2f(g_max[b]) - 8.0f;
    const size_t base = 2 * ((size_t)blockIdx.x * blockDim.x + threadIdx.x);
    const size_t per = (size_t)NMELS * NFRAMES / 4;
    float4* pb = reinterpret_cast<float4*>(out + (size_t)b * NMELS * NFRAMES);
#pragma unroll
    for (int j = 0; j < 2; ++j) {
        const size_t idx = base + j;
        if (idx < per) {
            float4 v = pb[idx];
            v.x = (fmaxf(v.x, floorv) + 4.0f) * 0.25f;
            v.y = (fmaxf(v.y, floorv) + 4.0f) * 0.25f;
            v.z = (fmaxf(v.z, floorv) + 4.0f) * 0.25f;
            v.w = (fmaxf(v.w, floorv) + 4.0f) * 0.25f;
            pb[idx] = v;
        }
    }
}

// ---------------- launch --------------------------------------------------------
extern "C" void kernel_launch(void* const* d_in, const int* in_sizes, int n_in,
                              void* d_out, int out_size) {
    const float* audio = (const float*)d_in[0];
    const float* cosk  = (const float*)d_in[1];
    const float* fb    = (const float*)d_in[3];
    float* out = (float*)d_out;

    cudaFuncSetAttribute(stft_mma_kernel, cudaFuncAttributeMaxDynamicSharedMemorySize, SMEMSZ);

    prep_kernel<<<1024, 256>>>(fb);
    prep_uv<<<dim3(NNT, BATCH), 224>>>(audio, cosk);

    stft_mma_kernel<<<dim3(NSMB, 2), STH, SMEMSZ>>>();

    dim3 gm((NFRAMES / 8 + 255) / 256, NMELS, BATCH);         // (2, 128, 32)
    mel_kernel<<<gm, 256>>>(fb, out);

    dim3 gf((NMELS * NFRAMES / 8 + 255) / 256, BATCH);
    fin_kernel<<<gf, 256>>>(out);
}